// round 3
// baseline (speedup 1.0000x reference)
#include <cuda_runtime.h>
#include <math.h>

#define K_NODES 4096
#define SEQ_L   32
#define D_MODEL 128
#define D_FF    512
#define N_EDGES 65536
#define N_TOT_EDGES (N_EDGES + K_NODES)

// ---------------- scratch (static device memory; no runtime allocation) ----
__device__ float g_xt[K_NODES * SEQ_L * D_MODEL];   // temporal output
__device__ float g_h [K_NODES * SEQ_L * D_MODEL];   // GAT-transformed features
__device__ float g_as[K_NODES * SEQ_L];
__device__ float g_ad[K_NODES * SEQ_L];
__device__ int   g_cnt[K_NODES];
__device__ int   g_cur[K_NODES];
__device__ int   g_off[K_NODES + 1];
__device__ int   g_csr_src[N_TOT_EDGES];
__device__ int   g_is32;   // 1 if edge_index is int32-packed, 0 if int64

// ---------------- f32x2 packed-FMA helpers (sm_103a) -------------------------
__device__ __forceinline__ unsigned long long pack2(float lo, float hi) {
    unsigned long long r;
    asm("mov.b64 %0, {%1, %2};" : "=l"(r) : "f"(lo), "f"(hi));
    return r;
}
__device__ __forceinline__ void unpack2(unsigned long long v, float& lo, float& hi) {
    asm("mov.b64 {%0, %1}, %2;" : "=f"(lo), "=f"(hi) : "l"(v));
}
__device__ __forceinline__ void ffma2(unsigned long long& acc,
                                      unsigned long long a, unsigned long long b) {
    asm("fma.rn.f32x2 %0, %1, %2, %0;" : "+l"(acc) : "l"(a), "l"(b));
}

// Swizzled transposed-A layout: A^T stored as [K][32] with row permutation
// phys_row = ((r & ~3) ^ ((d & 7) << 2)) + (r & 3). Keeps 4-row groups
// contiguous (16B-aligned float4/u64x2) while spreading banks on writes.
__device__ __forceinline__ int swz(int r, int d) {
    return d * 32 + (((r & ~3) ^ ((d & 7) << 2)) | (r & 3));
}

__device__ __forceinline__ float gelu_exact(float v) {
    return 0.5f * v * (1.0f + erff(v * 0.70710678118654752f));
}

// ---------------- LayerNorm 32x128: row-major in -> swizzled-transposed out --
__device__ __forceinline__ void layernorm_T(const float* __restrict__ sin,
                                            float* __restrict__ soutT,
                                            const float* __restrict__ g,
                                            const float* __restrict__ b) {
    int warp = threadIdx.x >> 5, lane = threadIdx.x & 31;
    float4 gg = *(const float4*)(g + lane * 4);
    float4 bb = *(const float4*)(b + lane * 4);
    for (int r = warp; r < 32; r += 8) {
        float4 v = *(const float4*)(sin + r * 128 + lane * 4);
        float s  = v.x + v.y + v.z + v.w;
        float ss = v.x * v.x + v.y * v.y + v.z * v.z + v.w * v.w;
        #pragma unroll
        for (int o = 16; o; o >>= 1) {
            s  += __shfl_xor_sync(0xffffffffu, s, o);
            ss += __shfl_xor_sync(0xffffffffu, ss, o);
        }
        float m   = s * (1.0f / 128.0f);
        float var = ss * (1.0f / 128.0f) - m * m;
        float rs  = rsqrtf(var + 1e-5f);
        int d0 = lane * 4;
        soutT[swz(r, d0 + 0)] = (v.x - m) * rs * gg.x + bb.x;
        soutT[swz(r, d0 + 1)] = (v.y - m) * rs * gg.y + bb.y;
        soutT[swz(r, d0 + 2)] = (v.z - m) * rs * gg.z + bb.z;
        soutT[swz(r, d0 + 3)] = (v.w - m) * rs * gg.w + bb.w;
    }
}

// ---------------- FFMA2 GEMM: D[32, 128 cols@colOff] = A[32,K] @ W[N,K]^T ---
// A supplied transposed+swizzled as sAT[K][32]. 256 threads:
// 64 col-threads (j0 = colOff + t&63, j1 = j0+64) x 4 row-groups of 8 rows.
// a-reads are warp-broadcast LDS.128 (conflict-free).
// MODE: 0 = store row-major, 1 = gelu + store transposed-swizzled,
//       2 = accumulate into row-major sD.
template <int K, int MODE>
__device__ __forceinline__ void gemm2(const float* __restrict__ sAT,
                                      const float* __restrict__ W,
                                      const float* __restrict__ bias,
                                      float* __restrict__ sD, int ldd,
                                      int colOff) {
    int t  = threadIdx.x;
    int j0 = colOff + (t & 63);
    int j1 = j0 + 64;
    int r0 = (t >> 6) * 8;
    unsigned long long acc[4][2];
    #pragma unroll
    for (int p = 0; p < 4; p++) { acc[p][0] = 0ull; acc[p][1] = 0ull; }
    const float* w0p = W + (size_t)j0 * K;
    const float* w1p = W + (size_t)j1 * K;
    #pragma unroll 2
    for (int d = 0; d < K; d += 4) {
        float4 w0 = *(const float4*)(w0p + d);
        float4 w1 = *(const float4*)(w1p + d);
        float w0a[4] = {w0.x, w0.y, w0.z, w0.w};
        float w1a[4] = {w1.x, w1.y, w1.z, w1.w};
        #pragma unroll
        for (int kk = 0; kk < 4; kk++) {
            int dd = d + kk;
            ulonglong2 aA = *(const ulonglong2*)(sAT + swz(r0, dd));
            ulonglong2 aB = *(const ulonglong2*)(sAT + swz(r0 + 4, dd));
            unsigned long long wd0 = pack2(w0a[kk], w0a[kk]);
            unsigned long long wd1 = pack2(w1a[kk], w1a[kk]);
            ffma2(acc[0][0], aA.x, wd0); ffma2(acc[0][1], aA.x, wd1);
            ffma2(acc[1][0], aA.y, wd0); ffma2(acc[1][1], aA.y, wd1);
            ffma2(acc[2][0], aB.x, wd0); ffma2(acc[2][1], aB.x, wd1);
            ffma2(acc[3][0], aB.y, wd0); ffma2(acc[3][1], aB.y, wd1);
        }
    }
    float b0 = bias ? bias[j0] : 0.f;
    float b1 = bias ? bias[j1] : 0.f;
    #pragma unroll
    for (int p = 0; p < 4; p++) {
        float v0lo, v0hi, v1lo, v1hi;
        unpack2(acc[p][0], v0lo, v0hi);
        unpack2(acc[p][1], v1lo, v1hi);
        int rr = r0 + 2 * p;
        v0lo += b0; v0hi += b0; v1lo += b1; v1hi += b1;
        if (MODE == 1) {
            sD[swz(rr,     j0)] = gelu_exact(v0lo);
            sD[swz(rr + 1, j0)] = gelu_exact(v0hi);
            sD[swz(rr,     j1)] = gelu_exact(v1lo);
            sD[swz(rr + 1, j1)] = gelu_exact(v1hi);
        } else if (MODE == 2) {
            sD[rr * ldd + j0]       += v0lo;
            sD[(rr + 1) * ldd + j0] += v0hi;
            sD[rr * ldd + j1]       += v1lo;
            sD[(rr + 1) * ldd + j1] += v1hi;
        } else {
            sD[rr * ldd + j0]       = v0lo;
            sD[(rr + 1) * ldd + j0] = v0hi;
            sD[rr * ldd + j1]       = v1lo;
            sD[(rr + 1) * ldd + j1] = v1hi;
        }
    }
}

// ---------------- temporal transformer: one block per node ------------------
// dyn smem: sx[32*128] shT[128*32] sbuf[16384] ssc[32*32] = 25600 floats.
__global__ void __launch_bounds__(256, 2)
temporal_kernel(const float* __restrict__ x,
                const float* __restrict__ ln1_g, const float* __restrict__ ln1_b,
                const float* __restrict__ qkv_w, const float* __restrict__ qkv_b,
                const float* __restrict__ out_w, const float* __restrict__ out_b,
                const float* __restrict__ ln2_g, const float* __restrict__ ln2_b,
                const float* __restrict__ ff1_w, const float* __restrict__ ff1_b,
                const float* __restrict__ ff2_w, const float* __restrict__ ff2_b) {
    extern __shared__ float sm[];
    float* sx   = sm;                    // 4096: residual (row-major [32][128])
    float* shT  = sx + 32 * 128;         // 4096: transposed-swizzled A [128][32]
    float* sbuf = shT + 32 * 128;        // 16384: qkv rows (stride 512) / ffT [512][32]
    float* ssc  = sbuf + 16384;          // 1024: attention scores

    int node = blockIdx.x;
    int t    = threadIdx.x;
    const float* xg = x + (size_t)node * (32 * 128);

    for (int i = t; i < 32 * 128 / 4; i += 256)
        ((float4*)sx)[i] = ((const float4*)xg)[i];
    __syncthreads();

    // ---- LN1 -> shT
    layernorm_T(sx, shT, ln1_g, ln1_b);
    __syncthreads();

    // ---- qkv = LN1 @ qkv_w^T + b  -> sbuf rows stride 512 (q|k|v at 0|128|256)
    for (int c = 0; c < 384; c += 128)
        gemm2<128, 0>(shT, qkv_w, qkv_b, sbuf, 512, c);
    __syncthreads();

    // ---- scores[i][j] = q_i . k_j / sqrt(128)
    {
        int i = t >> 3, j0 = (t & 7) * 4;
        float acc[4] = {0.f, 0.f, 0.f, 0.f};
        const float* qrow = sbuf + i * 512;
        #pragma unroll 4
        for (int d = 0; d < 128; d += 4) {
            float4 q = *(const float4*)(qrow + d);
            #pragma unroll
            for (int jj = 0; jj < 4; jj++) {
                float4 k4 = *(const float4*)(sbuf + (j0 + jj) * 512 + 128 + d);
                acc[jj] += q.x * k4.x + q.y * k4.y + q.z * k4.z + q.w * k4.w;
            }
        }
        const float scale = 0.08838834764831845f;  // 1/sqrt(128)
        #pragma unroll
        for (int jj = 0; jj < 4; jj++) ssc[i * 32 + j0 + jj] = acc[jj] * scale;
    }
    __syncthreads();

    // ---- softmax rows of ssc
    {
        int warp = t >> 5, lane = t & 31;
        for (int r = warp; r < 32; r += 8) {
            float v = ssc[r * 32 + lane];
            float mx = v;
            #pragma unroll
            for (int o = 16; o; o >>= 1) mx = fmaxf(mx, __shfl_xor_sync(0xffffffffu, mx, o));
            float e = expf(v - mx);
            float s = e;
            #pragma unroll
            for (int o = 16; o; o >>= 1) s += __shfl_xor_sync(0xffffffffu, s, o);
            ssc[r * 32 + lane] = e / s;
        }
    }
    __syncthreads();

    // ---- attn = a @ v  -> shT (transposed-swizzled, feeds out-proj GEMM)
    {
        int i = t >> 3, d0 = (t & 7) * 16;
        float acc[16];
        #pragma unroll
        for (int q = 0; q < 16; q++) acc[q] = 0.f;
        for (int j = 0; j < 32; j++) {
            float a = ssc[i * 32 + j];
            const float* vr = sbuf + j * 512 + 256 + d0;
            #pragma unroll
            for (int q = 0; q < 16; q += 4) {
                float4 v4 = *(const float4*)(vr + q);
                acc[q] += a * v4.x; acc[q + 1] += a * v4.y;
                acc[q + 2] += a * v4.z; acc[q + 3] += a * v4.w;
            }
        }
        #pragma unroll
        for (int q = 0; q < 16; q++) shT[swz(i, d0 + q)] = acc[q];
    }
    __syncthreads();

    // ---- x += attn @ out_w^T + out_b
    gemm2<128, 2>(shT, out_w, out_b, sx, 128, 0);
    __syncthreads();

    // ---- LN2 -> shT
    layernorm_T(sx, shT, ln2_g, ln2_b);
    __syncthreads();

    // ---- ff1 + gelu -> sbuf as transposed-swizzled ffT [512][32]
    for (int c = 0; c < 512; c += 128)
        gemm2<128, 1>(shT, ff1_w, ff1_b, sbuf, 0, c);
    __syncthreads();

    // ---- x += gelu(ff1) @ ff2_w^T + ff2_b
    gemm2<512, 2>(sbuf, ff2_w, ff2_b, sx, 128, 0);
    __syncthreads();

    float* xtg = g_xt + (size_t)node * (32 * 128);
    for (int i = t; i < 32 * 128 / 4; i += 256)
        ((float4*)xtg)[i] = ((const float4*)sx)[i];
}

// ---------------- GAT transform: h = xt @ gat_w^T, plus a_src/a_dst --------
__global__ void __launch_bounds__(256)
gat_transform_kernel(const float* __restrict__ gat_w,
                     const float* __restrict__ att_src,
                     const float* __restrict__ att_dst) {
    __shared__ float sAT[32 * 128];
    __shared__ float sD[32 * 128];
    int node = blockIdx.x, t = threadIdx.x;
    const float* xg = g_xt + (size_t)node * 4096;
    for (int idx = t; idx < 1024; idx += 256) {
        int row = idx >> 5, d0 = (idx & 31) * 4;
        float4 v = ((const float4*)xg)[idx];
        sAT[swz(row, d0 + 0)] = v.x;
        sAT[swz(row, d0 + 1)] = v.y;
        sAT[swz(row, d0 + 2)] = v.z;
        sAT[swz(row, d0 + 3)] = v.w;
    }
    __syncthreads();

    gemm2<128, 0>(sAT, gat_w, (const float*)nullptr, sD, 128, 0);
    __syncthreads();

    float* hg = g_h + (size_t)node * 4096;
    for (int i = t; i < 1024; i += 256)
        ((float4*)hg)[i] = ((const float4*)sD)[i];

    int warp = t >> 5, lane = t & 31;
    float4 as4 = *(const float4*)(att_src + lane * 4);
    float4 ad4 = *(const float4*)(att_dst + lane * 4);
    for (int r = warp; r < 32; r += 8) {
        float4 h4 = *(const float4*)(sD + r * 128 + lane * 4);
        float s = h4.x * as4.x + h4.y * as4.y + h4.z * as4.z + h4.w * as4.w;
        float d = h4.x * ad4.x + h4.y * ad4.y + h4.z * ad4.z + h4.w * ad4.w;
        #pragma unroll
        for (int o = 16; o; o >>= 1) {
            s += __shfl_xor_sync(0xffffffffu, s, o);
            d += __shfl_xor_sync(0xffffffffu, d, o);
        }
        if (lane == 0) {
            g_as[node * 32 + r] = s;
            g_ad[node * 32 + r] = d;
        }
    }
}

// ---------------- edge dtype detection + CSR build ---------------------------
__global__ void zero_counts_kernel() {
    int i = blockIdx.x * blockDim.x + threadIdx.x;
    if (i < K_NODES) { g_cnt[i] = 0; g_cur[i] = 0; }
    if (i == 0) g_is32 = 0;
}

__global__ void detect_dtype_kernel(const int* __restrict__ ei32) {
    int i = blockIdx.x * blockDim.x + threadIdx.x;
    if (i < N_EDGES) {
        if (ei32[2 * i + 1] != 0) atomicExch(&g_is32, 1);
    }
}

__device__ __forceinline__ int load_idx(const int* __restrict__ ei32, int elem) {
    return g_is32 ? ei32[elem] : ei32[2 * elem];
}

__global__ void count_edges_kernel(const int* __restrict__ ei32) {
    int e = blockIdx.x * blockDim.x + threadIdx.x;
    if (e >= N_TOT_EDGES) return;
    int dst = (e < N_EDGES) ? load_idx(ei32, N_EDGES + e) : (e - N_EDGES);
    if ((unsigned)dst >= K_NODES) return;
    atomicAdd(&g_cnt[dst], 1);
}

__global__ void scan_kernel() {  // 1 block, 1024 threads; 4096 counts
    __shared__ int ts[1024];
    int t = threadIdx.x;
    int c[4], s = 0;
    #pragma unroll
    for (int i = 0; i < 4; i++) { c[i] = s; s += g_cnt[t * 4 + i]; }
    ts[t] = s;
    __syncthreads();
    for (int o = 1; o < 1024; o <<= 1) {
        int v = (t >= o) ? ts[t - o] : 0;
        __syncthreads();
        ts[t] += v;
        __syncthreads();
    }
    int base = (t == 0) ? 0 : ts[t - 1];
    #pragma unroll
    for (int i = 0; i < 4; i++) g_off[t * 4 + i] = base + c[i];
    if (t == 1023) g_off[4096] = ts[1023];
}

__global__ void fill_edges_kernel(const int* __restrict__ ei32) {
    int e = blockIdx.x * blockDim.x + threadIdx.x;
    if (e >= N_TOT_EDGES) return;
    int src, dst;
    if (e < N_EDGES) {
        src = load_idx(ei32, e);
        dst = load_idx(ei32, N_EDGES + e);
    } else {
        src = dst = e - N_EDGES;
    }
    if ((unsigned)dst >= K_NODES || (unsigned)src >= K_NODES) return;
    int pos = atomicAdd(&g_cur[dst], 1);
    g_csr_src[g_off[dst] + pos] = src;
}

// ---------------- GAT aggregation: one block per dst node -------------------
__global__ void __launch_bounds__(256)
gat_aggregate_kernel(const float* __restrict__ gat_b, float* __restrict__ out) {
    __shared__ float sm_m[32], sm_d[32];
    __shared__ float part[8][32];
    int dst = blockIdx.x, t = threadIdx.x;
    int off0 = g_off[dst], ne = g_cur[dst];

    // phase A: per-l max of leaky_relu(a_s[src]+a_d[dst])
    {
        int l = t & 31, grp = t >> 5;
        float adl = g_ad[dst * 32 + l];
        float lm = -3.4e38f;
        for (int e = grp; e < ne; e += 8) {
            int src = g_csr_src[off0 + e];
            float v = g_as[src * 32 + l] + adl;
            v = v > 0.f ? v : 0.2f * v;
            lm = fmaxf(lm, v);
        }
        part[grp][l] = lm;
        __syncthreads();
        if (t < 32) {
            float m = part[0][t];
            #pragma unroll
            for (int g2 = 1; g2 < 8; g2++) m = fmaxf(m, part[g2][t]);
            sm_m[t] = m;
        }
        __syncthreads();
    }
    // phase B: denom
    {
        int l = t & 31, grp = t >> 5;
        float adl = g_ad[dst * 32 + l];
        float m = sm_m[l], sden = 0.f;
        for (int e = grp; e < ne; e += 8) {
            int src = g_csr_src[off0 + e];
            float v = g_as[src * 32 + l] + adl;
            v = v > 0.f ? v : 0.2f * v;
            sden += expf(v - m);
        }
        __syncthreads();
        part[grp][l] = sden;
        __syncthreads();
        if (t < 32) {
            float s2 = 0.f;
            #pragma unroll
            for (int g2 = 0; g2 < 8; g2++) s2 += part[g2][t];
            sm_d[t] = s2;
        }
        __syncthreads();
    }
    // phase C: out[dst,l,d] = sum_e (ex/denom) * h[src,l,d] + gat_b[d]
    {
        int l = t >> 3, d0 = (t & 7) * 16;
        float m = sm_m[l];
        float adl = g_ad[dst * 32 + l];
        float acc[16];
        #pragma unroll
        for (int i = 0; i < 16; i++) acc[i] = 0.f;
        for (int e = 0; e < ne; e++) {
            int src = g_csr_src[off0 + e];
            float v = g_as[src * 32 + l] + adl;
            v = v > 0.f ? v : 0.2f * v;
            float ex = expf(v - m);
            const float4* hp = (const float4*)(g_h + ((size_t)src * 32 + l) * 128 + d0);
            #pragma unroll
            for (int q = 0; q < 4; q++) {
                float4 h4 = hp[q];
                acc[q * 4 + 0] += ex * h4.x;
                acc[q * 4 + 1] += ex * h4.y;
                acc[q * 4 + 2] += ex * h4.z;
                acc[q * 4 + 3] += ex * h4.w;
            }
        }
        float inv = 1.f / (sm_d[l] + 1e-16f);
        float* op = out + ((size_t)dst * 32 + l) * 128 + d0;
        #pragma unroll
        for (int q = 0; q < 4; q++) {
            float4 o4;
            o4.x = acc[q * 4 + 0] * inv + gat_b[d0 + q * 4 + 0];
            o4.y = acc[q * 4 + 1] * inv + gat_b[d0 + q * 4 + 1];
            o4.z = acc[q * 4 + 2] * inv + gat_b[d0 + q * 4 + 2];
            o4.w = acc[q * 4 + 3] * inv + gat_b[d0 + q * 4 + 3];
            ((float4*)op)[q] = o4;
        }
    }
}

// ---------------- launch -----------------------------------------------------
extern "C" void kernel_launch(void* const* d_in, const int* in_sizes, int n_in,
                              void* d_out, int out_size) {
    const float* x     = (const float*)d_in[0];
    const int*   ei32  = (const int*)d_in[1];   // int32 or int64 words; auto-detected
    const float* ln1_g = (const float*)d_in[2];
    const float* ln1_b = (const float*)d_in[3];
    const float* qkv_w = (const float*)d_in[4];
    const float* qkv_b = (const float*)d_in[5];
    const float* out_w = (const float*)d_in[6];
    const float* out_b = (const float*)d_in[7];
    const float* ln2_g = (const float*)d_in[8];
    const float* ln2_b = (const float*)d_in[9];
    const float* ff1_w = (const float*)d_in[10];
    const float* ff1_b = (const float*)d_in[11];
    const float* ff2_w = (const float*)d_in[12];
    const float* ff2_b = (const float*)d_in[13];
    const float* gat_w = (const float*)d_in[14];
    const float* att_s = (const float*)d_in[15];
    const float* att_d = (const float*)d_in[16];
    const float* gat_b = (const float*)d_in[17];
    float* out = (float*)d_out;

    // CSR build first (independent of temporal); puts temporal_kernel at
    // launch #6 where the ncu capture (-s 5 -c 1) lands.
    zero_counts_kernel<<<(K_NODES + 255) / 256, 256>>>();
    detect_dtype_kernel<<<(N_EDGES + 255) / 256, 256>>>(ei32);
    count_edges_kernel<<<(N_TOT_EDGES + 255) / 256, 256>>>(ei32);
    scan_kernel<<<1, 1024>>>();
    fill_edges_kernel<<<(N_TOT_EDGES + 255) / 256, 256>>>(ei32);

    const int TEMP_SMEM = 25600 * sizeof(float);  // 100 KB
    cudaFuncSetAttribute(temporal_kernel,
                         cudaFuncAttributeMaxDynamicSharedMemorySize, TEMP_SMEM);

    temporal_kernel<<<K_NODES, 256, TEMP_SMEM>>>(
        x, ln1_g, ln1_b, qkv_w, qkv_b, out_w, out_b,
        ln2_g, ln2_b, ff1_w, ff1_b, ff2_w, ff2_b);

    gat_transform_kernel<<<K_NODES, 256>>>(gat_w, att_s, att_d);

    gat_aggregate_kernel<<<K_NODES, 256>>>(gat_b, out);
}

// round 4
// speedup vs baseline: 1.6877x; 1.6877x over previous
#include <cuda_runtime.h>
#include <math.h>

#define K_NODES 4096
#define SEQ_L   32
#define D_MODEL 128
#define D_FF    512
#define N_EDGES 65536
#define N_TOT_EDGES (N_EDGES + K_NODES)

#define WT_LD  20   // 16 k-floats + 4 pad, 80B row (16B aligned)
#define CHUNK  16

// ---------------- scratch (static device memory; no runtime allocation) ----
__device__ float g_xt[K_NODES * SEQ_L * D_MODEL];
__device__ float g_h [K_NODES * SEQ_L * D_MODEL];
__device__ float g_as[K_NODES * SEQ_L];
__device__ float g_ad[K_NODES * SEQ_L];
__device__ int   g_cnt[K_NODES];
__device__ int   g_cur[K_NODES];
__device__ int   g_off[K_NODES + 1];
__device__ int   g_csr_src[N_TOT_EDGES];
__device__ int   g_is32;

// ---------------- f32x2 packed-FMA helpers (sm_103a) -------------------------
__device__ __forceinline__ unsigned long long pack2(float lo, float hi) {
    unsigned long long r;
    asm("mov.b64 %0, {%1, %2};" : "=l"(r) : "f"(lo), "f"(hi));
    return r;
}
__device__ __forceinline__ void unpack2(unsigned long long v, float& lo, float& hi) {
    asm("mov.b64 {%0, %1}, %2;" : "=f"(lo), "=f"(hi) : "l"(v));
}
__device__ __forceinline__ void ffma2(unsigned long long& acc,
                                      unsigned long long a, unsigned long long b) {
    asm("fma.rn.f32x2 %0, %1, %2, %0;" : "+l"(acc) : "l"(a), "l"(b));
}

// Swizzled transposed-A layout: A^T as [K][32], 4-row groups kept contiguous.
__device__ __forceinline__ int swz(int r, int d) {
    return d * 32 + (((r & ~3) ^ ((d & 7) << 2)) | (r & 3));
}

__device__ __forceinline__ float gelu_exact(float v) {
    return 0.5f * v * (1.0f + erff(v * 0.70710678118654752f));
}

// ---------------- LayerNorm 32x128: row-major in -> swizzled-transposed out --
__device__ __forceinline__ void layernorm_T(const float* __restrict__ sin,
                                            float* __restrict__ soutT,
                                            const float* __restrict__ g,
                                            const float* __restrict__ b) {
    int warp = threadIdx.x >> 5, lane = threadIdx.x & 31;
    float4 gg = *(const float4*)(g + lane * 4);
    float4 bb = *(const float4*)(b + lane * 4);
    for (int r = warp; r < 32; r += 8) {
        float4 v = *(const float4*)(sin + r * 128 + lane * 4);
        float s  = v.x + v.y + v.z + v.w;
        float ss = v.x * v.x + v.y * v.y + v.z * v.z + v.w * v.w;
        #pragma unroll
        for (int o = 16; o; o >>= 1) {
            s  += __shfl_xor_sync(0xffffffffu, s, o);
            ss += __shfl_xor_sync(0xffffffffu, ss, o);
        }
        float m   = s * (1.0f / 128.0f);
        float var = ss * (1.0f / 128.0f) - m * m;
        float rs  = rsqrtf(var + 1e-5f);
        int d0 = lane * 4;
        soutT[swz(r, d0 + 0)] = (v.x - m) * rs * gg.x + bb.x;
        soutT[swz(r, d0 + 1)] = (v.y - m) * rs * gg.y + bb.y;
        soutT[swz(r, d0 + 2)] = (v.z - m) * rs * gg.z + bb.z;
        soutT[swz(r, d0 + 3)] = (v.w - m) * rs * gg.w + bb.w;
    }
}

// ---------------- smem-staged FFMA2 GEMM -------------------------------------
// D[32 rows, 128 cols@colOff] = A[32,K] @ W[N,K]^T (+bias).
// A transposed+swizzled in sAT[K][32]; W streamed through smem tile wt
// (128 cols x CHUNK k, coalesced loads, conflict-free reads).
// MODE: 0 = store row-major (ldd), 1 = gelu + store transposed-swizzled,
//       2 = accumulate into row-major sD.
template <int K, int MODE>
__device__ __forceinline__ void gemm_sw(const float* __restrict__ sAT,
                                        const float* __restrict__ W,
                                        const float* __restrict__ bias,
                                        float* __restrict__ wt,
                                        float* __restrict__ sD, int ldd,
                                        int colOff) {
    int t   = threadIdx.x;
    int jl0 = t & 63;
    int jl1 = jl0 + 64;
    int r0  = (t >> 6) * 8;
    unsigned long long acc[4][2];
    #pragma unroll
    for (int p = 0; p < 4; p++) { acc[p][0] = 0ull; acc[p][1] = 0ull; }

    for (int kc = 0; kc < K; kc += CHUNK) {
        __syncthreads();   // previous chunk reads (or prior call) done
        #pragma unroll
        for (int i = 0; i < 2; i++) {
            int f  = t + 256 * i;          // 0..511 float4s
            int j  = f >> 2;               // 0..127
            int kk = (f & 3) * 4;          // 0,4,8,12
            float4 w4 = *(const float4*)(W + (size_t)(colOff + j) * K + kc + kk);
            *(float4*)(wt + j * WT_LD + kk) = w4;
        }
        __syncthreads();
        #pragma unroll
        for (int dl = 0; dl < CHUNK; dl += 4) {
            int d = kc + dl;
            float4 w0 = *(const float4*)(wt + jl0 * WT_LD + dl);
            float4 w1 = *(const float4*)(wt + jl1 * WT_LD + dl);
            float w0a[4] = {w0.x, w0.y, w0.z, w0.w};
            float w1a[4] = {w1.x, w1.y, w1.z, w1.w};
            #pragma unroll
            for (int kk = 0; kk < 4; kk++) {
                int dd = d + kk;
                ulonglong2 aA = *(const ulonglong2*)(sAT + swz(r0, dd));
                ulonglong2 aB = *(const ulonglong2*)(sAT + swz(r0 + 4, dd));
                unsigned long long wd0 = pack2(w0a[kk], w0a[kk]);
                unsigned long long wd1 = pack2(w1a[kk], w1a[kk]);
                ffma2(acc[0][0], aA.x, wd0); ffma2(acc[0][1], aA.x, wd1);
                ffma2(acc[1][0], aA.y, wd0); ffma2(acc[1][1], aA.y, wd1);
                ffma2(acc[2][0], aB.x, wd0); ffma2(acc[2][1], aB.x, wd1);
                ffma2(acc[3][0], aB.y, wd0); ffma2(acc[3][1], aB.y, wd1);
            }
        }
    }

    int j0 = colOff + jl0, j1 = colOff + jl1;
    float b0 = bias ? bias[j0] : 0.f;
    float b1 = bias ? bias[j1] : 0.f;
    #pragma unroll
    for (int p = 0; p < 4; p++) {
        float v0lo, v0hi, v1lo, v1hi;
        unpack2(acc[p][0], v0lo, v0hi);
        unpack2(acc[p][1], v1lo, v1hi);
        int rr = r0 + 2 * p;
        v0lo += b0; v0hi += b0; v1lo += b1; v1hi += b1;
        if (MODE == 1) {
            sD[swz(rr,     j0)] = gelu_exact(v0lo);
            sD[swz(rr + 1, j0)] = gelu_exact(v0hi);
            sD[swz(rr,     j1)] = gelu_exact(v1lo);
            sD[swz(rr + 1, j1)] = gelu_exact(v1hi);
        } else if (MODE == 2) {
            sD[rr * ldd + j0]       += v0lo;
            sD[(rr + 1) * ldd + j0] += v0hi;
            sD[rr * ldd + j1]       += v1lo;
            sD[(rr + 1) * ldd + j1] += v1hi;
        } else {
            sD[rr * ldd + j0]       = v0lo;
            sD[(rr + 1) * ldd + j0] = v0hi;
            sD[rr * ldd + j1]       = v1lo;
            sD[(rr + 1) * ldd + j1] = v1hi;
        }
    }
}

// ---------------- temporal transformer: one block per node ------------------
// dyn smem: sx[4096] shT[4096] sbuf[16384] wt[2560] = 27136 floats (106 KB).
// qkv lives in sbuf rows stride 384 (48 KB); ssc at sbuf+12288;
// ffT[512][32] uses full sbuf.
__global__ void __launch_bounds__(256, 2)
temporal_kernel(const float* __restrict__ x,
                const float* __restrict__ ln1_g, const float* __restrict__ ln1_b,
                const float* __restrict__ qkv_w, const float* __restrict__ qkv_b,
                const float* __restrict__ out_w, const float* __restrict__ out_b,
                const float* __restrict__ ln2_g, const float* __restrict__ ln2_b,
                const float* __restrict__ ff1_w, const float* __restrict__ ff1_b,
                const float* __restrict__ ff2_w, const float* __restrict__ ff2_b) {
    extern __shared__ float sm[];
    float* sx   = sm;                    // residual [32][128]
    float* shT  = sx + 4096;             // transposed-swizzled A [128][32]
    float* sbuf = shT + 4096;            // 16384 floats
    float* wt   = sbuf + 16384;          // 2560 floats weight tile
    float* ssc  = sbuf + 12288;          // scores [32][32] (qkv phase only)

    int node = blockIdx.x;
    int t    = threadIdx.x;
    const float* xg = x + (size_t)node * 4096;

    for (int i = t; i < 1024; i += 256)
        ((float4*)sx)[i] = ((const float4*)xg)[i];
    __syncthreads();

    // ---- LN1 -> shT
    layernorm_T(sx, shT, ln1_g, ln1_b);

    // ---- qkv = LN1 @ qkv_w^T + b -> sbuf rows stride 384 (q|k|v at 0|128|256)
    for (int c = 0; c < 384; c += 128)
        gemm_sw<128, 0>(shT, qkv_w, qkv_b, wt, sbuf, 384, c);
    __syncthreads();

    // ---- scores[i][j] = q_i . k_j / sqrt(128)
    {
        int i = t >> 3, j0 = (t & 7) * 4;
        float acc[4] = {0.f, 0.f, 0.f, 0.f};
        const float* qrow = sbuf + i * 384;
        #pragma unroll 4
        for (int d = 0; d < 128; d += 4) {
            float4 q = *(const float4*)(qrow + d);
            #pragma unroll
            for (int jj = 0; jj < 4; jj++) {
                float4 k4 = *(const float4*)(sbuf + (j0 + jj) * 384 + 128 + d);
                acc[jj] += q.x * k4.x + q.y * k4.y + q.z * k4.z + q.w * k4.w;
            }
        }
        const float scale = 0.08838834764831845f;
        #pragma unroll
        for (int jj = 0; jj < 4; jj++) ssc[i * 32 + j0 + jj] = acc[jj] * scale;
    }
    __syncthreads();

    // ---- softmax rows of ssc
    {
        int warp = t >> 5, lane = t & 31;
        for (int r = warp; r < 32; r += 8) {
            float v = ssc[r * 32 + lane];
            float mx = v;
            #pragma unroll
            for (int o = 16; o; o >>= 1) mx = fmaxf(mx, __shfl_xor_sync(0xffffffffu, mx, o));
            float e = expf(v - mx);
            float s = e;
            #pragma unroll
            for (int o = 16; o; o >>= 1) s += __shfl_xor_sync(0xffffffffu, s, o);
            ssc[r * 32 + lane] = e / s;
        }
    }
    __syncthreads();

    // ---- attn = a @ v -> shT (transposed-swizzled)
    {
        int i = t >> 3, d0 = (t & 7) * 16;
        float acc[16];
        #pragma unroll
        for (int q = 0; q < 16; q++) acc[q] = 0.f;
        for (int j = 0; j < 32; j++) {
            float a = ssc[i * 32 + j];
            const float* vr = sbuf + j * 384 + 256 + d0;
            #pragma unroll
            for (int q = 0; q < 16; q += 4) {
                float4 v4 = *(const float4*)(vr + q);
                acc[q] += a * v4.x; acc[q + 1] += a * v4.y;
                acc[q + 2] += a * v4.z; acc[q + 3] += a * v4.w;
            }
        }
        #pragma unroll
        for (int q = 0; q < 16; q++) shT[swz(i, d0 + q)] = acc[q];
    }
    __syncthreads();

    // ---- x += attn @ out_w^T + out_b
    gemm_sw<128, 2>(shT, out_w, out_b, wt, sx, 128, 0);
    __syncthreads();

    // ---- LN2 -> shT
    layernorm_T(sx, shT, ln2_g, ln2_b);

    // ---- ff1 + gelu -> sbuf as transposed-swizzled ffT [512][32]
    for (int c = 0; c < 512; c += 128)
        gemm_sw<128, 1>(shT, ff1_w, ff1_b, wt, sbuf, 0, c);
    __syncthreads();

    // ---- x += gelu(ff1) @ ff2_w^T + ff2_b
    gemm_sw<512, 2>(sbuf, ff2_w, ff2_b, wt, sx, 128, 0);
    __syncthreads();

    float* xtg = g_xt + (size_t)node * 4096;
    for (int i = t; i < 1024; i += 256)
        ((float4*)xtg)[i] = ((const float4*)sx)[i];
}

// ---------------- GAT transform ----------------------------------------------
__global__ void __launch_bounds__(256)
gat_transform_kernel(const float* __restrict__ gat_w,
                     const float* __restrict__ att_src,
                     const float* __restrict__ att_dst) {
    __shared__ float sAT[4096];
    __shared__ float sD[4096];
    __shared__ float wt[128 * WT_LD];
    int node = blockIdx.x, t = threadIdx.x;
    const float* xg = g_xt + (size_t)node * 4096;
    for (int idx = t; idx < 1024; idx += 256) {
        int row = idx >> 5, d0 = (idx & 31) * 4;
        float4 v = ((const float4*)xg)[idx];
        sAT[swz(row, d0 + 0)] = v.x;
        sAT[swz(row, d0 + 1)] = v.y;
        sAT[swz(row, d0 + 2)] = v.z;
        sAT[swz(row, d0 + 3)] = v.w;
    }

    gemm_sw<128, 0>(sAT, gat_w, (const float*)nullptr, wt, sD, 128, 0);
    __syncthreads();

    float* hg = g_h + (size_t)node * 4096;
    for (int i = t; i < 1024; i += 256)
        ((float4*)hg)[i] = ((const float4*)sD)[i];

    int warp = t >> 5, lane = t & 31;
    float4 as4 = *(const float4*)(att_src + lane * 4);
    float4 ad4 = *(const float4*)(att_dst + lane * 4);
    for (int r = warp; r < 32; r += 8) {
        float4 h4 = *(const float4*)(sD + r * 128 + lane * 4);
        float s = h4.x * as4.x + h4.y * as4.y + h4.z * as4.z + h4.w * as4.w;
        float d = h4.x * ad4.x + h4.y * ad4.y + h4.z * ad4.z + h4.w * ad4.w;
        #pragma unroll
        for (int o = 16; o; o >>= 1) {
            s += __shfl_xor_sync(0xffffffffu, s, o);
            d += __shfl_xor_sync(0xffffffffu, d, o);
        }
        if (lane == 0) {
            g_as[node * 32 + r] = s;
            g_ad[node * 32 + r] = d;
        }
    }
}

// ---------------- edge dtype detection + CSR build ---------------------------
__global__ void zero_counts_kernel() {
    int i = blockIdx.x * blockDim.x + threadIdx.x;
    if (i < K_NODES) { g_cnt[i] = 0; g_cur[i] = 0; }
    if (i == 0) g_is32 = 0;
}

__global__ void detect_dtype_kernel(const int* __restrict__ ei32) {
    int i = blockIdx.x * blockDim.x + threadIdx.x;
    if (i < N_EDGES) {
        if (ei32[2 * i + 1] != 0) atomicExch(&g_is32, 1);
    }
}

__device__ __forceinline__ int load_idx(const int* __restrict__ ei32, int elem) {
    return g_is32 ? ei32[elem] : ei32[2 * elem];
}

__global__ void count_edges_kernel(const int* __restrict__ ei32) {
    int e = blockIdx.x * blockDim.x + threadIdx.x;
    if (e >= N_TOT_EDGES) return;
    int dst = (e < N_EDGES) ? load_idx(ei32, N_EDGES + e) : (e - N_EDGES);
    if ((unsigned)dst >= K_NODES) return;
    atomicAdd(&g_cnt[dst], 1);
}

__global__ void scan_kernel() {
    __shared__ int ts[1024];
    int t = threadIdx.x;
    int c[4], s = 0;
    #pragma unroll
    for (int i = 0; i < 4; i++) { c[i] = s; s += g_cnt[t * 4 + i]; }
    ts[t] = s;
    __syncthreads();
    for (int o = 1; o < 1024; o <<= 1) {
        int v = (t >= o) ? ts[t - o] : 0;
        __syncthreads();
        ts[t] += v;
        __syncthreads();
    }
    int base = (t == 0) ? 0 : ts[t - 1];
    #pragma unroll
    for (int i = 0; i < 4; i++) g_off[t * 4 + i] = base + c[i];
    if (t == 1023) g_off[4096] = ts[1023];
}

__global__ void fill_edges_kernel(const int* __restrict__ ei32) {
    int e = blockIdx.x * blockDim.x + threadIdx.x;
    if (e >= N_TOT_EDGES) return;
    int src, dst;
    if (e < N_EDGES) {
        src = load_idx(ei32, e);
        dst = load_idx(ei32, N_EDGES + e);
    } else {
        src = dst = e - N_EDGES;
    }
    if ((unsigned)dst >= K_NODES || (unsigned)src >= K_NODES) return;
    int pos = atomicAdd(&g_cur[dst], 1);
    g_csr_src[g_off[dst] + pos] = src;
}

// ---------------- GAT aggregation: one block per dst node -------------------
__global__ void __launch_bounds__(256)
gat_aggregate_kernel(const float* __restrict__ gat_b, float* __restrict__ out) {
    __shared__ float sm_m[32], sm_d[32];
    __shared__ float part[8][32];
    int dst = blockIdx.x, t = threadIdx.x;
    int off0 = g_off[dst], ne = g_cur[dst];

    {   // phase A: per-l max of leaky_relu(a_s[src]+a_d[dst])
        int l = t & 31, grp = t >> 5;
        float adl = g_ad[dst * 32 + l];
        float lm = -3.4e38f;
        for (int e = grp; e < ne; e += 8) {
            int src = g_csr_src[off0 + e];
            float v = g_as[src * 32 + l] + adl;
            v = v > 0.f ? v : 0.2f * v;
            lm = fmaxf(lm, v);
        }
        part[grp][l] = lm;
        __syncthreads();
        if (t < 32) {
            float m = part[0][t];
            #pragma unroll
            for (int g2 = 1; g2 < 8; g2++) m = fmaxf(m, part[g2][t]);
            sm_m[t] = m;
        }
        __syncthreads();
    }
    {   // phase B: denom
        int l = t & 31, grp = t >> 5;
        float adl = g_ad[dst * 32 + l];
        float m = sm_m[l], sden = 0.f;
        for (int e = grp; e < ne; e += 8) {
            int src = g_csr_src[off0 + e];
            float v = g_as[src * 32 + l] + adl;
            v = v > 0.f ? v : 0.2f * v;
            sden += expf(v - m);
        }
        __syncthreads();
        part[grp][l] = sden;
        __syncthreads();
        if (t < 32) {
            float s2 = 0.f;
            #pragma unroll
            for (int g2 = 0; g2 < 8; g2++) s2 += part[g2][t];
            sm_d[t] = s2;
        }
        __syncthreads();
    }
    {   // phase C: weighted aggregation
        int l = t >> 3, d0 = (t & 7) * 16;
        float m = sm_m[l];
        float adl = g_ad[dst * 32 + l];
        float acc[16];
        #pragma unroll
        for (int i = 0; i < 16; i++) acc[i] = 0.f;
        for (int e = 0; e < ne; e++) {
            int src = g_csr_src[off0 + e];
            float v = g_as[src * 32 + l] + adl;
            v = v > 0.f ? v : 0.2f * v;
            float ex = expf(v - m);
            const float4* hp = (const float4*)(g_h + ((size_t)src * 32 + l) * 128 + d0);
            #pragma unroll
            for (int q = 0; q < 4; q++) {
                float4 h4 = hp[q];
                acc[q * 4 + 0] += ex * h4.x;
                acc[q * 4 + 1] += ex * h4.y;
                acc[q * 4 + 2] += ex * h4.z;
                acc[q * 4 + 3] += ex * h4.w;
            }
        }
        float inv = 1.f / (sm_d[l] + 1e-16f);
        float* op = out + ((size_t)dst * 32 + l) * 128 + d0;
        #pragma unroll
        for (int q = 0; q < 4; q++) {
            float4 o4;
            o4.x = acc[q * 4 + 0] * inv + gat_b[d0 + q * 4 + 0];
            o4.y = acc[q * 4 + 1] * inv + gat_b[d0 + q * 4 + 1];
            o4.z = acc[q * 4 + 2] * inv + gat_b[d0 + q * 4 + 2];
            o4.w = acc[q * 4 + 3] * inv + gat_b[d0 + q * 4 + 3];
            ((float4*)op)[q] = o4;
        }
    }
}

// ---------------- launch -----------------------------------------------------
extern "C" void kernel_launch(void* const* d_in, const int* in_sizes, int n_in,
                              void* d_out, int out_size) {
    const float* x     = (const float*)d_in[0];
    const int*   ei32  = (const int*)d_in[1];
    const float* ln1_g = (const float*)d_in[2];
    const float* ln1_b = (const float*)d_in[3];
    const float* qkv_w = (const float*)d_in[4];
    const float* qkv_b = (const float*)d_in[5];
    const float* out_w = (const float*)d_in[6];
    const float* out_b = (const float*)d_in[7];
    const float* ln2_g = (const float*)d_in[8];
    const float* ln2_b = (const float*)d_in[9];
    const float* ff1_w = (const float*)d_in[10];
    const float* ff1_b = (const float*)d_in[11];
    const float* ff2_w = (const float*)d_in[12];
    const float* ff2_b = (const float*)d_in[13];
    const float* gat_w = (const float*)d_in[14];
    const float* att_s = (const float*)d_in[15];
    const float* att_d = (const float*)d_in[16];
    const float* gat_b = (const float*)d_in[17];
    float* out = (float*)d_out;

    // temporal_kernel placed 4th in-call: both prior rounds showed ncu
    // (-s 5 -c 1, with 2 harness pre-launches) profiling in-call launch #4.
    zero_counts_kernel<<<(K_NODES + 255) / 256, 256>>>();
    detect_dtype_kernel<<<(N_EDGES + 255) / 256, 256>>>(ei32);
    count_edges_kernel<<<(N_TOT_EDGES + 255) / 256, 256>>>(ei32);

    const int TEMP_SMEM = 27136 * sizeof(float);  // 106 KB
    cudaFuncSetAttribute(temporal_kernel,
                         cudaFuncAttributeMaxDynamicSharedMemorySize, TEMP_SMEM);
    temporal_kernel<<<K_NODES, 256, TEMP_SMEM>>>(
        x, ln1_g, ln1_b, qkv_w, qkv_b, out_w, out_b,
        ln2_g, ln2_b, ff1_w, ff1_b, ff2_w, ff2_b);

    scan_kernel<<<1, 1024>>>();
    fill_edges_kernel<<<(N_TOT_EDGES + 255) / 256, 256>>>(ei32);

    gat_transform_kernel<<<K_NODES, 256>>>(gat_w, att_s, att_d);
    gat_aggregate_kernel<<<K_NODES, 256>>>(gat_b, out);
}

// round 7
// speedup vs baseline: 2.3722x; 1.4056x over previous
#include <cuda_runtime.h>
#include <cuda_bf16.h>
#include <cstdint>
#include <math.h>

#define K_NODES 4096
#define SEQ_L   32
#define D_MODEL 128
#define D_FF    512
#define N_EDGES 65536
#define N_TOT_EDGES (N_EDGES + K_NODES)
#define MM (K_NODES * SEQ_L)           // 131072 rows

#define SLD 136                         // smem bf16 row stride (128 + 8 pad)

// ---------------- big scratch buffers (static; no runtime alloc) ------------
__device__ float g_ln  [MM * 128];
__device__ float g_qkv [MM * 384];
__device__ float g_attn[MM * 128];
__device__ float g_x2  [MM * 128];
__device__ float g_ff  [MM * 512];
__device__ float g_xt  [MM * 128];
__device__ float g_h   [MM * 128];
__device__ float g_as[K_NODES * SEQ_L];
__device__ float g_ad[K_NODES * SEQ_L];
__device__ int   g_cnt[K_NODES];
__device__ int   g_cur[K_NODES];
__device__ int   g_off[K_NODES + 1];
__device__ int   g_csr_src[N_TOT_EDGES];
__device__ int   g_is32;

__device__ __forceinline__ float gelu_exact(float v) {
    return 0.5f * v * (1.0f + erff(v * 0.70710678118654752f));
}

// mma.sync m16n8k16 row.col f32.bf16.bf16.f32 (portable PTX, sm_80+)
__device__ __forceinline__ void mma16816(float* d,
                                         const uint32_t* a, const uint32_t* b) {
    asm volatile(
        "mma.sync.aligned.m16n8k16.row.col.f32.bf16.bf16.f32 "
        "{%0,%1,%2,%3}, {%4,%5,%6,%7}, {%8,%9}, {%0,%1,%2,%3};"
        : "+f"(d[0]), "+f"(d[1]), "+f"(d[2]), "+f"(d[3])
        : "r"(a[0]), "r"(a[1]), "r"(a[2]), "r"(a[3]), "r"(b[0]), "r"(b[1]));
}

__device__ __forceinline__ uint32_t pack_bf2(float x, float y) {
    __nv_bfloat162 p;
    p.x = __float2bfloat16(x);
    p.y = __float2bfloat16(y);
    return *(uint32_t*)&p;
}

// ---------------- tensor-core GEMM: C tile = A[M,K] @ W[N,K]^T ---------------
// Block = 256 threads (8 warps). Tile: 128 M-rows (bx) x 128 N-cols (by).
// Warp w computes rows [w*16, w*16+16). bf16 split: Ahi*Bhi + Ahi*Blo + Alo*Bhi.
// epi: 0=+bias; 1=+bias,gelu; 2=+bias,+res; 3=none.
__global__ void __launch_bounds__(256, 1)
gemm_mma_kernel(const float* __restrict__ A, int lda, int K,
                const float* __restrict__ W,
                const float* __restrict__ bias,
                float* __restrict__ C, int ldc,
                const float* __restrict__ res, int epi) {
    extern __shared__ __nv_bfloat16 sm[];
    __nv_bfloat16* sAhi = sm;                 // [128][SLD]
    __nv_bfloat16* sAlo = sAhi + 128 * SLD;
    __nv_bfloat16* sBhi = sAlo + 128 * SLD;
    __nv_bfloat16* sBlo = sBhi + 128 * SLD;

    int t    = threadIdx.x;
    int wid  = t >> 5, lane = t & 31;
    int g    = lane >> 2;                // group id 0..7
    int c    = lane & 3;                 // thread-in-group 0..3
    int M0   = blockIdx.x * 128;
    int col0 = blockIdx.y * 128;
    int m0   = wid * 16;

    float acc[16][4];
    #pragma unroll
    for (int n = 0; n < 16; n++)
        #pragma unroll
        for (int q = 0; q < 4; q++) acc[n][q] = 0.f;

    for (int kc = 0; kc < K; kc += 128) {
        __syncthreads();
        // cooperative load + bf16 split: A rows and W rows (both k-contiguous)
        #pragma unroll 4
        for (int i = 0; i < 16; i++) {
            int f   = i * 256 + t;           // 0..4095
            int row = f >> 5;
            int c4  = (f & 31) * 4;
            float4 a4 = *(const float4*)(A + (size_t)(M0 + row) * lda + kc + c4);
            float4 w4 = *(const float4*)(W + (size_t)(col0 + row) * K + kc + c4);
            uint32_t ah01 = pack_bf2(a4.x, a4.y);
            uint32_t ah23 = pack_bf2(a4.z, a4.w);
            __nv_bfloat162 h01 = *(__nv_bfloat162*)&ah01;
            __nv_bfloat162 h23 = *(__nv_bfloat162*)&ah23;
            uint32_t al01 = pack_bf2(a4.x - __bfloat162float(h01.x),
                                     a4.y - __bfloat162float(h01.y));
            uint32_t al23 = pack_bf2(a4.z - __bfloat162float(h23.x),
                                     a4.w - __bfloat162float(h23.y));
            uint32_t wh01 = pack_bf2(w4.x, w4.y);
            uint32_t wh23 = pack_bf2(w4.z, w4.w);
            __nv_bfloat162 W01 = *(__nv_bfloat162*)&wh01;
            __nv_bfloat162 W23 = *(__nv_bfloat162*)&wh23;
            uint32_t wl01 = pack_bf2(w4.x - __bfloat162float(W01.x),
                                     w4.y - __bfloat162float(W01.y));
            uint32_t wl23 = pack_bf2(w4.z - __bfloat162float(W23.x),
                                     w4.w - __bfloat162float(W23.y));
            int off = row * SLD + c4;
            *(uint32_t*)(sAhi + off)     = ah01;
            *(uint32_t*)(sAhi + off + 2) = ah23;
            *(uint32_t*)(sAlo + off)     = al01;
            *(uint32_t*)(sAlo + off + 2) = al23;
            *(uint32_t*)(sBhi + off)     = wh01;
            *(uint32_t*)(sBhi + off + 2) = wh23;
            *(uint32_t*)(sBlo + off)     = wl01;
            *(uint32_t*)(sBlo + off + 2) = wl23;
        }
        __syncthreads();

        // three split passes: (Ahi,Bhi), (Ahi,Blo), (Alo,Bhi)
        #pragma unroll
        for (int s = 0; s < 3; s++) {
            const __nv_bfloat16* pA = (s == 2) ? sAlo : sAhi;
            const __nv_bfloat16* pB = (s == 1) ? sBlo : sBhi;
            #pragma unroll
            for (int kk = 0; kk < 128; kk += 16) {
                uint32_t a[4];
                int ar = (m0 + g) * SLD + kk + 2 * c;
                a[0] = *(const uint32_t*)(pA + ar);
                a[1] = *(const uint32_t*)(pA + ar + 8 * SLD);
                a[2] = *(const uint32_t*)(pA + ar + 8);
                a[3] = *(const uint32_t*)(pA + ar + 8 * SLD + 8);
                #pragma unroll
                for (int n = 0; n < 16; n++) {
                    uint32_t b[2];
                    int br = (n * 8 + g) * SLD + kk + 2 * c;
                    b[0] = *(const uint32_t*)(pB + br);
                    b[1] = *(const uint32_t*)(pB + br + 8);
                    mma16816(acc[n], a, b);
                }
            }
        }
    }

    // epilogue: thread owns rows (M0+m0+g, +8), cols col0 + n*8 + 2c, 2c+1
    int row0 = M0 + m0 + g;
    #pragma unroll
    for (int n = 0; n < 16; n++) {
        int col = col0 + n * 8 + 2 * c;
        float b0 = 0.f, b1 = 0.f;
        if (epi != 3) { b0 = bias[col]; b1 = bias[col + 1]; }
        float v00 = acc[n][0] + b0, v01 = acc[n][1] + b1;
        float v10 = acc[n][2] + b0, v11 = acc[n][3] + b1;
        if (epi == 1) {
            v00 = gelu_exact(v00); v01 = gelu_exact(v01);
            v10 = gelu_exact(v10); v11 = gelu_exact(v11);
        } else if (epi == 2) {
            const float* r0 = res + (size_t)row0 * 128 + (col - col0) + col0 - col0;
            // res has 128 cols; col-col0 is the in-tile column
            float2 ra = *(const float2*)(res + (size_t)row0 * 128 + (col0 ? (col - col0) : col) + (col0 ? col0 * 0 : 0) + (col - col0) * 0 + (col - col0));
            (void)r0; (void)ra;
            // (simplified below — res col == global col since res width==ldc only when ldc==128)
        }
        if (epi == 2) {
            float2 ra = *(const float2*)(res + (size_t)row0 * 128 + col);
            float2 rb = *(const float2*)(res + (size_t)(row0 + 8) * 128 + col);
            v00 += ra.x; v01 += ra.y; v10 += rb.x; v11 += rb.y;
        }
        float2 o0 = {v00, v01}, o1 = {v10, v11};
        *(float2*)(C + (size_t)row0 * ldc + col)       = o0;
        *(float2*)(C + (size_t)(row0 + 8) * ldc + col) = o1;
    }
}

// ---------------- LayerNorm over rows of [MM,128] ----------------------------
__global__ void __launch_bounds__(256)
ln_kernel(const float* __restrict__ in, float* __restrict__ out,
          const float* __restrict__ g, const float* __restrict__ b) {
    int warp = threadIdx.x >> 5, lane = threadIdx.x & 31;
    size_t row = (size_t)blockIdx.x * 8 + warp;
    float4 v = *(const float4*)(in + row * 128 + lane * 4);
    float s  = v.x + v.y + v.z + v.w;
    float ss = v.x * v.x + v.y * v.y + v.z * v.z + v.w * v.w;
    #pragma unroll
    for (int o = 16; o; o >>= 1) {
        s  += __shfl_xor_sync(0xffffffffu, s, o);
        ss += __shfl_xor_sync(0xffffffffu, ss, o);
    }
    float m   = s * (1.0f / 128.0f);
    float var = ss * (1.0f / 128.0f) - m * m;
    float rs  = rsqrtf(var + 1e-5f);
    float4 gg = *(const float4*)(g + lane * 4);
    float4 bb = *(const float4*)(b + lane * 4);
    float4 o4;
    o4.x = (v.x - m) * rs * gg.x + bb.x;
    o4.y = (v.y - m) * rs * gg.y + bb.y;
    o4.z = (v.z - m) * rs * gg.z + bb.z;
    o4.w = (v.w - m) * rs * gg.w + bb.w;
    *(float4*)(out + row * 128 + lane * 4) = o4;
}

// ---------------- attention (per node, fp32) ---------------------------------
__global__ void __launch_bounds__(256)
attn_kernel() {
    extern __shared__ float s[];
    float* sq  = s;
    float* sk  = s + 4096;
    float* sv  = s + 8192;
    float* ssc = s + 12288;
    int node = blockIdx.x, t = threadIdx.x;
    const float* qg = g_qkv + (size_t)node * 32 * 384;

    for (int i = t; i < 1024; i += 256) {
        int l = i >> 5, c4 = (i & 31) * 4;
        *(float4*)(sq + l * 128 + c4) = *(const float4*)(qg + l * 384 + c4);
        *(float4*)(sk + l * 128 + c4) = *(const float4*)(qg + l * 384 + 128 + c4);
        *(float4*)(sv + l * 128 + c4) = *(const float4*)(qg + l * 384 + 256 + c4);
    }
    __syncthreads();

    {   // scores
        int i = t >> 3, j0 = (t & 7) * 4;
        float acc[4] = {0.f, 0.f, 0.f, 0.f};
        #pragma unroll 4
        for (int d = 0; d < 128; d += 4) {
            float4 q = *(const float4*)(sq + i * 128 + d);
            #pragma unroll
            for (int jj = 0; jj < 4; jj++) {
                float4 k4 = *(const float4*)(sk + (j0 + jj) * 128 + d);
                acc[jj] += q.x * k4.x + q.y * k4.y + q.z * k4.z + q.w * k4.w;
            }
        }
        const float scale = 0.08838834764831845f;
        #pragma unroll
        for (int jj = 0; jj < 4; jj++) ssc[i * 32 + j0 + jj] = acc[jj] * scale;
    }
    __syncthreads();
    {   // softmax
        int warp = t >> 5, lane = t & 31;
        for (int r = warp; r < 32; r += 8) {
            float v = ssc[r * 32 + lane];
            float mx = v;
            #pragma unroll
            for (int o = 16; o; o >>= 1) mx = fmaxf(mx, __shfl_xor_sync(0xffffffffu, mx, o));
            float e = expf(v - mx);
            float sm2 = e;
            #pragma unroll
            for (int o = 16; o; o >>= 1) sm2 += __shfl_xor_sync(0xffffffffu, sm2, o);
            ssc[r * 32 + lane] = e / sm2;
        }
    }
    __syncthreads();
    {   // attn = a @ v
        int i = t >> 3, d0 = (t & 7) * 16;
        float acc[16];
        #pragma unroll
        for (int q = 0; q < 16; q++) acc[q] = 0.f;
        for (int j = 0; j < 32; j++) {
            float a = ssc[i * 32 + j];
            const float* vr = sv + j * 128 + d0;
            #pragma unroll
            for (int q = 0; q < 16; q += 4) {
                float4 v4 = *(const float4*)(vr + q);
                acc[q] += a * v4.x; acc[q + 1] += a * v4.y;
                acc[q + 2] += a * v4.z; acc[q + 3] += a * v4.w;
            }
        }
        float* og = g_attn + ((size_t)node * 32 + i) * 128 + d0;
        #pragma unroll
        for (int q = 0; q < 16; q += 4) {
            float4 o4 = {acc[q], acc[q + 1], acc[q + 2], acc[q + 3]};
            *(float4*)(og + q) = o4;
        }
    }
}

// ---------------- a_src/a_dst projections ------------------------------------
__global__ void __launch_bounds__(256)
asad_kernel(const float* __restrict__ att_src, const float* __restrict__ att_dst) {
    int node = blockIdx.x, t = threadIdx.x;
    int warp = t >> 5, lane = t & 31;
    float4 as4 = *(const float4*)(att_src + lane * 4);
    float4 ad4 = *(const float4*)(att_dst + lane * 4);
    for (int r = warp; r < 32; r += 8) {
        float4 h4 = *(const float4*)(g_h + ((size_t)node * 32 + r) * 128 + lane * 4);
        float s = h4.x * as4.x + h4.y * as4.y + h4.z * as4.z + h4.w * as4.w;
        float d = h4.x * ad4.x + h4.y * ad4.y + h4.z * ad4.z + h4.w * ad4.w;
        #pragma unroll
        for (int o = 16; o; o >>= 1) {
            s += __shfl_xor_sync(0xffffffffu, s, o);
            d += __shfl_xor_sync(0xffffffffu, d, o);
        }
        if (lane == 0) {
            g_as[node * 32 + r] = s;
            g_ad[node * 32 + r] = d;
        }
    }
}

// ---------------- edge dtype detection + CSR build ---------------------------
__global__ void zero_counts_kernel() {
    int i = blockIdx.x * blockDim.x + threadIdx.x;
    if (i < K_NODES) { g_cnt[i] = 0; g_cur[i] = 0; }
    if (i == 0) g_is32 = 0;
}
__global__ void detect_dtype_kernel(const int* __restrict__ ei32) {
    int i = blockIdx.x * blockDim.x + threadIdx.x;
    if (i < N_EDGES && ei32[2 * i + 1] != 0) atomicExch(&g_is32, 1);
}
__device__ __forceinline__ int load_idx(const int* __restrict__ ei32, int elem) {
    return g_is32 ? ei32[elem] : ei32[2 * elem];
}
__global__ void count_edges_kernel(const int* __restrict__ ei32) {
    int e = blockIdx.x * blockDim.x + threadIdx.x;
    if (e >= N_TOT_EDGES) return;
    int dst = (e < N_EDGES) ? load_idx(ei32, N_EDGES + e) : (e - N_EDGES);
    if ((unsigned)dst >= K_NODES) return;
    atomicAdd(&g_cnt[dst], 1);
}
__global__ void scan_kernel() {
    __shared__ int ts[1024];
    int t = threadIdx.x;
    int c[4], s = 0;
    #pragma unroll
    for (int i = 0; i < 4; i++) { c[i] = s; s += g_cnt[t * 4 + i]; }
    ts[t] = s;
    __syncthreads();
    for (int o = 1; o < 1024; o <<= 1) {
        int v = (t >= o) ? ts[t - o] : 0;
        __syncthreads();
        ts[t] += v;
        __syncthreads();
    }
    int base = (t == 0) ? 0 : ts[t - 1];
    #pragma unroll
    for (int i = 0; i < 4; i++) g_off[t * 4 + i] = base + c[i];
    if (t == 1023) g_off[4096] = ts[1023];
}
__global__ void fill_edges_kernel(const int* __restrict__ ei32) {
    int e = blockIdx.x * blockDim.x + threadIdx.x;
    if (e >= N_TOT_EDGES) return;
    int src, dst;
    if (e < N_EDGES) {
        src = load_idx(ei32, e);
        dst = load_idx(ei32, N_EDGES + e);
    } else {
        src = dst = e - N_EDGES;
    }
    if ((unsigned)dst >= K_NODES || (unsigned)src >= K_NODES) return;
    int pos = atomicAdd(&g_cur[dst], 1);
    g_csr_src[g_off[dst] + pos] = src;
}

// ---------------- GAT aggregation: one block per dst node --------------------
__global__ void __launch_bounds__(256)
gat_aggregate_kernel(const float* __restrict__ gat_b, float* __restrict__ out) {
    __shared__ float sm_m[32], sm_d[32];
    __shared__ float part[8][32];
    int dst = blockIdx.x, t = threadIdx.x;
    int off0 = g_off[dst], ne = g_cur[dst];

    {   // phase A: per-l max
        int l = t & 31, grp = t >> 5;
        float adl = g_ad[dst * 32 + l];
        float lm = -3.4e38f;
        for (int e = grp; e < ne; e += 8) {
            int src = g_csr_src[off0 + e];
            float v = g_as[src * 32 + l] + adl;
            v = v > 0.f ? v : 0.2f * v;
            lm = fmaxf(lm, v);
        }
        part[grp][l] = lm;
        __syncthreads();
        if (t < 32) {
            float m = part[0][t];
            #pragma unroll
            for (int g2 = 1; g2 < 8; g2++) m = fmaxf(m, part[g2][t]);
            sm_m[t] = m;
        }
        __syncthreads();
    }
    {   // phase B: denom
        int l = t & 31, grp = t >> 5;
        float adl = g_ad[dst * 32 + l];
        float m = sm_m[l], sden = 0.f;
        for (int e = grp; e < ne; e += 8) {
            int src = g_csr_src[off0 + e];
            float v = g_as[src * 32 + l] + adl;
            v = v > 0.f ? v : 0.2f * v;
            sden += expf(v - m);
        }
        __syncthreads();
        part[grp][l] = sden;
        __syncthreads();
        if (t < 32) {
            float s2 = 0.f;
            #pragma unroll
            for (int g2 = 0; g2 < 8; g2++) s2 += part[g2][t];
            sm_d[t] = s2;
        }
        __syncthreads();
    }
    {   // phase C: weighted aggregation
        int l = t >> 3, d0 = (t & 7) * 16;
        float m = sm_m[l];
        float adl = g_ad[dst * 32 + l];
        float acc[16];
        #pragma unroll
        for (int i = 0; i < 16; i++) acc[i] = 0.f;
        for (int e = 0; e < ne; e++) {
            int src = g_csr_src[off0 + e];
            float v = g_as[src * 32 + l] + adl;
            v = v > 0.f ? v : 0.2f * v;
            float ex = expf(v - m);
            const float4* hp = (const float4*)(g_h + ((size_t)src * 32 + l) * 128 + d0);
            #pragma unroll
            for (int q = 0; q < 4; q++) {
                float4 h4 = hp[q];
                acc[q * 4 + 0] += ex * h4.x;
                acc[q * 4 + 1] += ex * h4.y;
                acc[q * 4 + 2] += ex * h4.z;
                acc[q * 4 + 3] += ex * h4.w;
            }
        }
        float inv = 1.f / (sm_d[l] + 1e-16f);
        float* op = out + ((size_t)dst * 32 + l) * 128 + d0;
        #pragma unroll
        for (int q = 0; q < 4; q++) {
            float4 o4;
            o4.x = acc[q * 4 + 0] * inv + gat_b[d0 + q * 4 + 0];
            o4.y = acc[q * 4 + 1] * inv + gat_b[d0 + q * 4 + 1];
            o4.z = acc[q * 4 + 2] * inv + gat_b[d0 + q * 4 + 2];
            o4.w = acc[q * 4 + 3] * inv + gat_b[d0 + q * 4 + 3];
            ((float4*)op)[q] = o4;
        }
    }
}

// ---------------- launch ------------------------------------------------------
extern "C" void kernel_launch(void* const* d_in, const int* in_sizes, int n_in,
                              void* d_out, int out_size) {
    const float* x     = (const float*)d_in[0];
    const int*   ei32  = (const int*)d_in[1];
    const float* ln1_g = (const float*)d_in[2];
    const float* ln1_b = (const float*)d_in[3];
    const float* qkv_w = (const float*)d_in[4];
    const float* qkv_b = (const float*)d_in[5];
    const float* out_w = (const float*)d_in[6];
    const float* out_b = (const float*)d_in[7];
    const float* ln2_g = (const float*)d_in[8];
    const float* ln2_b = (const float*)d_in[9];
    const float* ff1_w = (const float*)d_in[10];
    const float* ff1_b = (const float*)d_in[11];
    const float* ff2_w = (const float*)d_in[12];
    const float* ff2_b = (const float*)d_in[13];
    const float* gat_w = (const float*)d_in[14];
    const float* att_s = (const float*)d_in[15];
    const float* att_d = (const float*)d_in[16];
    const float* gat_b = (const float*)d_in[17];
    float* out = (float*)d_out;

    float *p_ln, *p_qkv, *p_attn, *p_x2, *p_ff, *p_xt, *p_h;
    cudaGetSymbolAddress((void**)&p_ln,   g_ln);
    cudaGetSymbolAddress((void**)&p_qkv,  g_qkv);
    cudaGetSymbolAddress((void**)&p_attn, g_attn);
    cudaGetSymbolAddress((void**)&p_x2,   g_x2);
    cudaGetSymbolAddress((void**)&p_ff,   g_ff);
    cudaGetSymbolAddress((void**)&p_xt,   g_xt);
    cudaGetSymbolAddress((void**)&p_h,    g_h);

    const int GEMM_SMEM = 4 * 128 * SLD * 2;   // 139264 B
    cudaFuncSetAttribute(gemm_mma_kernel,
                         cudaFuncAttributeMaxDynamicSharedMemorySize, GEMM_SMEM);
    cudaFuncSetAttribute(attn_kernel,
                         cudaFuncAttributeMaxDynamicSharedMemorySize, 53248);

    // 1. LN1
    ln_kernel<<<MM / 8, 256>>>(x, p_ln, ln1_g, ln1_b);
    // 2-3. CSR prep (independent)
    zero_counts_kernel<<<(K_NODES + 255) / 256, 256>>>();
    detect_dtype_kernel<<<(N_EDGES + 255) / 256, 256>>>(ei32);
    // 4. qkv GEMM  (ncu target slot)
    gemm_mma_kernel<<<dim3(MM / 128, 3), 256, GEMM_SMEM>>>(
        p_ln, 128, 128, qkv_w, qkv_b, p_qkv, 384, nullptr, 0);
    // 5. CSR count
    count_edges_kernel<<<(N_TOT_EDGES + 255) / 256, 256>>>(ei32);
    // 6. attention
    attn_kernel<<<K_NODES, 256, 53248>>>();
    // 7. out-proj + residual -> x2
    gemm_mma_kernel<<<dim3(MM / 128, 1), 256, GEMM_SMEM>>>(
        p_attn, 128, 128, out_w, out_b, p_x2, 128, x, 2);
    // 8. CSR scan
    scan_kernel<<<1, 1024>>>();
    // 9. LN2
    ln_kernel<<<MM / 8, 256>>>(p_x2, p_ln, ln2_g, ln2_b);
    // 10. ff1 + gelu
    gemm_mma_kernel<<<dim3(MM / 128, 4), 256, GEMM_SMEM>>>(
        p_ln, 128, 128, ff1_w, ff1_b, p_ff, 512, nullptr, 1);
    // 11. ff2 + residual -> xt
    gemm_mma_kernel<<<dim3(MM / 128, 1), 256, GEMM_SMEM>>>(
        p_ff, 512, 512, ff2_w, ff2_b, p_xt, 128, p_x2, 2);
    // 12. GAT transform
    gemm_mma_kernel<<<dim3(MM / 128, 1), 256, GEMM_SMEM>>>(
        p_xt, 128, 128, gat_w, nullptr, p_h, 128, nullptr, 3);
    // 13. CSR fill
    fill_edges_kernel<<<(N_TOT_EDGES + 255) / 256, 256>>>(ei32);
    // 14. attention coefficients
    asad_kernel<<<K_NODES, 256>>>(att_s, att_d);
    // 15. aggregate
    gat_aggregate_kernel<<<K_NODES, 256>>>(gat_b, out);
}

// round 8
// speedup vs baseline: 2.6927x; 1.1351x over previous
#include <cuda_runtime.h>
#include <cuda_bf16.h>
#include <cstdint>
#include <math.h>

#define K_NODES 4096
#define SEQ_L   32
#define D_MODEL 128
#define D_FF    512
#define N_EDGES 65536
#define N_TOT_EDGES (N_EDGES + K_NODES)
#define MM (K_NODES * SEQ_L)           // 131072 rows

#define SLD 72                          // smem bf16 row stride for 64-k chunk

// weight segment offsets in the packed split buffer
#define WOFF_QKV 0
#define WOFF_OUT 49152
#define WOFF_FF1 65536
#define WOFF_FF2 131072
#define WOFF_GAT 196608
#define W_TOTAL  212992

// ---------------- scratch (static; no runtime alloc) -------------------------
__device__ __nv_bfloat16 g_b1hi[MM * 128], g_b1lo[MM * 128];  // A-side splits (reused)
__device__ __nv_bfloat16 g_b2hi[MM * 512], g_b2lo[MM * 512];  // ff split
__device__ __nv_bfloat16 g_whi[W_TOTAL],  g_wlo[W_TOTAL];     // weight splits
__device__ float g_qkv[MM * 384];
__device__ float g_x2 [MM * 128];
__device__ float g_h  [MM * 128];
__device__ float g_as[K_NODES * SEQ_L];
__device__ float g_ad[K_NODES * SEQ_L];
__device__ int   g_cnt[K_NODES];
__device__ int   g_cur[K_NODES];
__device__ int   g_off[K_NODES + 1];
__device__ int   g_csr_src[N_TOT_EDGES];
__device__ int   g_is32;

__device__ __forceinline__ float gelu_exact(float v) {
    return 0.5f * v * (1.0f + erff(v * 0.70710678118654752f));
}

// mma.sync m16n8k16 row.col f32.bf16.bf16.f32 (portable PTX, sm_80+)
__device__ __forceinline__ void mma16816(float* d,
                                         const uint32_t* a, const uint32_t* b) {
    asm volatile(
        "mma.sync.aligned.m16n8k16.row.col.f32.bf16.bf16.f32 "
        "{%0,%1,%2,%3}, {%4,%5,%6,%7}, {%8,%9}, {%0,%1,%2,%3};"
        : "+f"(d[0]), "+f"(d[1]), "+f"(d[2]), "+f"(d[3])
        : "r"(a[0]), "r"(a[1]), "r"(a[2]), "r"(a[3]), "r"(b[0]), "r"(b[1]));
}

__device__ __forceinline__ void split1(float v, __nv_bfloat16& h, __nv_bfloat16& l) {
    h = __float2bfloat16(v);
    l = __float2bfloat16(v - __bfloat162float(h));
}

// ---------------- weight split (all 5 weights, one launch) -------------------
__global__ void split_w_kernel(const float* __restrict__ w0, const float* __restrict__ w1,
                               const float* __restrict__ w2, const float* __restrict__ w3,
                               const float* __restrict__ w4) {
    int i = blockIdx.x * 256 + threadIdx.x;
    if (i >= W_TOTAL) return;
    const float* src; int off;
    if      (i < WOFF_OUT) { src = w0; off = WOFF_QKV; }
    else if (i < WOFF_FF1) { src = w1; off = WOFF_OUT; }
    else if (i < WOFF_FF2) { src = w2; off = WOFF_FF1; }
    else if (i < WOFF_GAT) { src = w3; off = WOFF_FF2; }
    else                   { src = w4; off = WOFF_GAT; }
    float v = src[i - off];
    __nv_bfloat16 h, l;
    split1(v, h, l);
    g_whi[i] = h; g_wlo[i] = l;
}

// ---------------- tensor-core GEMM on pre-split bf16 -------------------------
// C tile 128x128 (bx = M-tile, by = N-tile). A [M,K] bf16 hi/lo, W [N,K] bf16
// hi/lo. 3-term split: AhiBhi + AhiBlo + AloBhi, fp32 accum.
// epi: 0=+bias fp32 C; 1=+bias,gelu -> split; 2=+bias,+res fp32 C;
//      3=none fp32 C; 4=+bias,+res -> split.
__global__ void __launch_bounds__(256, 2)
gemm_mma_kernel(const __nv_bfloat16* __restrict__ Ahi,
                const __nv_bfloat16* __restrict__ Alo, int lda, int K,
                const __nv_bfloat16* __restrict__ Whi,
                const __nv_bfloat16* __restrict__ Wlo,
                const float* __restrict__ bias,
                float* __restrict__ C,
                __nv_bfloat16* __restrict__ Chi, __nv_bfloat16* __restrict__ Clo,
                int ldc, const float* __restrict__ res, int epi) {
    extern __shared__ __nv_bfloat16 sm[];
    __nv_bfloat16* sAhi = sm;                  // [128][SLD]
    __nv_bfloat16* sAlo = sAhi + 128 * SLD;
    __nv_bfloat16* sBhi = sAlo + 128 * SLD;
    __nv_bfloat16* sBlo = sBhi + 128 * SLD;

    int t    = threadIdx.x;
    int wid  = t >> 5, lane = t & 31;
    int g    = lane >> 2;
    int c    = lane & 3;
    int M0   = blockIdx.x * 128;
    int col0 = blockIdx.y * 128;
    int m0   = wid * 16;

    float acc[16][4];
    #pragma unroll
    for (int n = 0; n < 16; n++)
        #pragma unroll
        for (int q = 0; q < 4; q++) acc[n][q] = 0.f;

    for (int kc = 0; kc < K; kc += 64) {
        __syncthreads();
        // copy 64-wide k chunks (8 bf16 = 16B per thread-iteration)
        #pragma unroll
        for (int i = 0; i < 4; i++) {
            int f   = i * 256 + t;            // 0..1023
            int row = f >> 3;
            int c8  = (f & 7) * 8;
            *(uint4*)(sAhi + row * SLD + c8) =
                *(const uint4*)(Ahi + (size_t)(M0 + row) * lda + kc + c8);
            *(uint4*)(sAlo + row * SLD + c8) =
                *(const uint4*)(Alo + (size_t)(M0 + row) * lda + kc + c8);
            *(uint4*)(sBhi + row * SLD + c8) =
                *(const uint4*)(Whi + (size_t)(col0 + row) * K + kc + c8);
            *(uint4*)(sBlo + row * SLD + c8) =
                *(const uint4*)(Wlo + (size_t)(col0 + row) * K + kc + c8);
        }
        __syncthreads();

        #pragma unroll
        for (int s = 0; s < 3; s++) {
            const __nv_bfloat16* pA = (s == 2) ? sAlo : sAhi;
            const __nv_bfloat16* pB = (s == 1) ? sBlo : sBhi;
            #pragma unroll
            for (int kk = 0; kk < 64; kk += 16) {
                uint32_t a[4];
                int ar = (m0 + g) * SLD + kk + 2 * c;
                a[0] = *(const uint32_t*)(pA + ar);
                a[1] = *(const uint32_t*)(pA + ar + 8 * SLD);
                a[2] = *(const uint32_t*)(pA + ar + 8);
                a[3] = *(const uint32_t*)(pA + ar + 8 * SLD + 8);
                #pragma unroll
                for (int n = 0; n < 16; n++) {
                    uint32_t b[2];
                    int br = (n * 8 + g) * SLD + kk + 2 * c;
                    b[0] = *(const uint32_t*)(pB + br);
                    b[1] = *(const uint32_t*)(pB + br + 8);
                    mma16816(acc[n], a, b);
                }
            }
        }
    }

    // epilogue: thread owns rows (M0+m0+g, +8), cols col0 + n*8 + 2c..+1
    int row0 = M0 + m0 + g;
    #pragma unroll
    for (int n = 0; n < 16; n++) {
        int col = col0 + n * 8 + 2 * c;
        float b0 = 0.f, b1 = 0.f;
        if (epi != 3) { b0 = bias[col]; b1 = bias[col + 1]; }
        float v00 = acc[n][0] + b0, v01 = acc[n][1] + b1;
        float v10 = acc[n][2] + b0, v11 = acc[n][3] + b1;
        if (epi == 1) {
            v00 = gelu_exact(v00); v01 = gelu_exact(v01);
            v10 = gelu_exact(v10); v11 = gelu_exact(v11);
        } else if (epi == 2 || epi == 4) {
            float2 ra = *(const float2*)(res + (size_t)row0 * 128 + col);
            float2 rb = *(const float2*)(res + (size_t)(row0 + 8) * 128 + col);
            v00 += ra.x; v01 += ra.y; v10 += rb.x; v11 += rb.y;
        }
        if (epi == 1 || epi == 4) {
            __nv_bfloat162 h0, l0, h1, l1;
            split1(v00, h0.x, l0.x); split1(v01, h0.y, l0.y);
            split1(v10, h1.x, l1.x); split1(v11, h1.y, l1.y);
            *(__nv_bfloat162*)(Chi + (size_t)row0 * ldc + col)       = h0;
            *(__nv_bfloat162*)(Clo + (size_t)row0 * ldc + col)       = l0;
            *(__nv_bfloat162*)(Chi + (size_t)(row0 + 8) * ldc + col) = h1;
            *(__nv_bfloat162*)(Clo + (size_t)(row0 + 8) * ldc + col) = l1;
        } else {
            float2 o0 = {v00, v01}, o1 = {v10, v11};
            *(float2*)(C + (size_t)row0 * ldc + col)       = o0;
            *(float2*)(C + (size_t)(row0 + 8) * ldc + col) = o1;
        }
    }
}

// ---------------- LayerNorm: fp32 in -> bf16 split out -----------------------
__global__ void __launch_bounds__(256)
ln_kernel(const float* __restrict__ in,
          __nv_bfloat16* __restrict__ ohi, __nv_bfloat16* __restrict__ olo,
          const float* __restrict__ g, const float* __restrict__ b) {
    int warp = threadIdx.x >> 5, lane = threadIdx.x & 31;
    size_t row = (size_t)blockIdx.x * 8 + warp;
    float4 v = *(const float4*)(in + row * 128 + lane * 4);
    float s  = v.x + v.y + v.z + v.w;
    float ss = v.x * v.x + v.y * v.y + v.z * v.z + v.w * v.w;
    #pragma unroll
    for (int o = 16; o; o >>= 1) {
        s  += __shfl_xor_sync(0xffffffffu, s, o);
        ss += __shfl_xor_sync(0xffffffffu, ss, o);
    }
    float m   = s * (1.0f / 128.0f);
    float var = ss * (1.0f / 128.0f) - m * m;
    float rs  = rsqrtf(var + 1e-5f);
    float4 gg = *(const float4*)(g + lane * 4);
    float4 bb = *(const float4*)(b + lane * 4);
    float o0 = (v.x - m) * rs * gg.x + bb.x;
    float o1 = (v.y - m) * rs * gg.y + bb.y;
    float o2 = (v.z - m) * rs * gg.z + bb.z;
    float o3 = (v.w - m) * rs * gg.w + bb.w;
    __nv_bfloat162 h01, l01, h23, l23;
    split1(o0, h01.x, l01.x); split1(o1, h01.y, l01.y);
    split1(o2, h23.x, l23.x); split1(o3, h23.y, l23.y);
    *(__nv_bfloat162*)(ohi + row * 128 + lane * 4)     = h01;
    *(__nv_bfloat162*)(ohi + row * 128 + lane * 4 + 2) = h23;
    *(__nv_bfloat162*)(olo + row * 128 + lane * 4)     = l01;
    *(__nv_bfloat162*)(olo + row * 128 + lane * 4 + 2) = l23;
}

// ---------------- attention (per node, fp32 in, bf16 split out) -------------
__global__ void __launch_bounds__(256)
attn_kernel() {
    extern __shared__ float s[];
    float* sq  = s;
    float* sk  = s + 4096;
    float* sv  = s + 8192;
    float* ssc = s + 12288;
    int node = blockIdx.x, t = threadIdx.x;
    const float* qg = g_qkv + (size_t)node * 32 * 384;

    for (int i = t; i < 1024; i += 256) {
        int l = i >> 5, c4 = (i & 31) * 4;
        *(float4*)(sq + l * 128 + c4) = *(const float4*)(qg + l * 384 + c4);
        *(float4*)(sk + l * 128 + c4) = *(const float4*)(qg + l * 384 + 128 + c4);
        *(float4*)(sv + l * 128 + c4) = *(const float4*)(qg + l * 384 + 256 + c4);
    }
    __syncthreads();

    {   // scores
        int i = t >> 3, j0 = (t & 7) * 4;
        float acc[4] = {0.f, 0.f, 0.f, 0.f};
        #pragma unroll 4
        for (int d = 0; d < 128; d += 4) {
            float4 q = *(const float4*)(sq + i * 128 + d);
            #pragma unroll
            for (int jj = 0; jj < 4; jj++) {
                float4 k4 = *(const float4*)(sk + (j0 + jj) * 128 + d);
                acc[jj] += q.x * k4.x + q.y * k4.y + q.z * k4.z + q.w * k4.w;
            }
        }
        const float scale = 0.08838834764831845f;
        #pragma unroll
        for (int jj = 0; jj < 4; jj++) ssc[i * 32 + j0 + jj] = acc[jj] * scale;
    }
    __syncthreads();
    {   // softmax
        int warp = t >> 5, lane = t & 31;
        for (int r = warp; r < 32; r += 8) {
            float v = ssc[r * 32 + lane];
            float mx = v;
            #pragma unroll
            for (int o = 16; o; o >>= 1) mx = fmaxf(mx, __shfl_xor_sync(0xffffffffu, mx, o));
            float e = expf(v - mx);
            float sm2 = e;
            #pragma unroll
            for (int o = 16; o; o >>= 1) sm2 += __shfl_xor_sync(0xffffffffu, sm2, o);
            ssc[r * 32 + lane] = e / sm2;
        }
    }
    __syncthreads();
    {   // attn = a @ v -> split bf16
        int i = t >> 3, d0 = (t & 7) * 16;
        float acc[16];
        #pragma unroll
        for (int q = 0; q < 16; q++) acc[q] = 0.f;
        for (int j = 0; j < 32; j++) {
            float a = ssc[i * 32 + j];
            const float* vr = sv + j * 128 + d0;
            #pragma unroll
            for (int q = 0; q < 16; q += 4) {
                float4 v4 = *(const float4*)(vr + q);
                acc[q] += a * v4.x; acc[q + 1] += a * v4.y;
                acc[q + 2] += a * v4.z; acc[q + 3] += a * v4.w;
            }
        }
        size_t base = ((size_t)node * 32 + i) * 128 + d0;
        #pragma unroll
        for (int q = 0; q < 16; q += 2) {
            __nv_bfloat162 h, l;
            split1(acc[q],     h.x, l.x);
            split1(acc[q + 1], h.y, l.y);
            *(__nv_bfloat162*)(g_b1hi + base + q) = h;
            *(__nv_bfloat162*)(g_b1lo + base + q) = l;
        }
    }
}

// ---------------- a_src/a_dst projections ------------------------------------
__global__ void __launch_bounds__(256)
asad_kernel(const float* __restrict__ att_src, const float* __restrict__ att_dst) {
    int node = blockIdx.x, t = threadIdx.x;
    int warp = t >> 5, lane = t & 31;
    float4 as4 = *(const float4*)(att_src + lane * 4);
    float4 ad4 = *(const float4*)(att_dst + lane * 4);
    for (int r = warp; r < 32; r += 8) {
        float4 h4 = *(const float4*)(g_h + ((size_t)node * 32 + r) * 128 + lane * 4);
        float s = h4.x * as4.x + h4.y * as4.y + h4.z * as4.z + h4.w * as4.w;
        float d = h4.x * ad4.x + h4.y * ad4.y + h4.z * ad4.z + h4.w * ad4.w;
        #pragma unroll
        for (int o = 16; o; o >>= 1) {
            s += __shfl_xor_sync(0xffffffffu, s, o);
            d += __shfl_xor_sync(0xffffffffu, d, o);
        }
        if (lane == 0) {
            g_as[node * 32 + r] = s;
            g_ad[node * 32 + r] = d;
        }
    }
}

// ---------------- edge dtype detection + CSR build ---------------------------
__global__ void zero_counts_kernel() {
    int i = blockIdx.x * blockDim.x + threadIdx.x;
    if (i < K_NODES) { g_cnt[i] = 0; g_cur[i] = 0; }
    if (i == 0) g_is32 = 0;
}
__global__ void detect_dtype_kernel(const int* __restrict__ ei32) {
    int i = blockIdx.x * blockDim.x + threadIdx.x;
    if (i < N_EDGES && ei32[2 * i + 1] != 0) atomicExch(&g_is32, 1);
}
__device__ __forceinline__ int load_idx(const int* __restrict__ ei32, int elem) {
    return g_is32 ? ei32[elem] : ei32[2 * elem];
}
__global__ void count_edges_kernel(const int* __restrict__ ei32) {
    int e = blockIdx.x * blockDim.x + threadIdx.x;
    if (e >= N_TOT_EDGES) return;
    int dst = (e < N_EDGES) ? load_idx(ei32, N_EDGES + e) : (e - N_EDGES);
    if ((unsigned)dst >= K_NODES) return;
    atomicAdd(&g_cnt[dst], 1);
}
__global__ void scan_kernel() {
    __shared__ int ts[1024];
    int t = threadIdx.x;
    int c[4], s = 0;
    #pragma unroll
    for (int i = 0; i < 4; i++) { c[i] = s; s += g_cnt[t * 4 + i]; }
    ts[t] = s;
    __syncthreads();
    for (int o = 1; o < 1024; o <<= 1) {
        int v = (t >= o) ? ts[t - o] : 0;
        __syncthreads();
        ts[t] += v;
        __syncthreads();
    }
    int base = (t == 0) ? 0 : ts[t - 1];
    #pragma unroll
    for (int i = 0; i < 4; i++) g_off[t * 4 + i] = base + c[i];
    if (t == 1023) g_off[4096] = ts[1023];
}
__global__ void fill_edges_kernel(const int* __restrict__ ei32) {
    int e = blockIdx.x * blockDim.x + threadIdx.x;
    if (e >= N_TOT_EDGES) return;
    int src, dst;
    if (e < N_EDGES) {
        src = load_idx(ei32, e);
        dst = load_idx(ei32, N_EDGES + e);
    } else {
        src = dst = e - N_EDGES;
    }
    if ((unsigned)dst >= K_NODES || (unsigned)src >= K_NODES) return;
    int pos = atomicAdd(&g_cur[dst], 1);
    g_csr_src[g_off[dst] + pos] = src;
}

// ---------------- GAT aggregation: one block per dst node --------------------
__global__ void __launch_bounds__(256)
gat_aggregate_kernel(const float* __restrict__ gat_b, float* __restrict__ out) {
    __shared__ float sm_m[32], sm_d[32];
    __shared__ float part[8][32];
    int dst = blockIdx.x, t = threadIdx.x;
    int off0 = g_off[dst], ne = g_cur[dst];

    {   // phase A: per-l max
        int l = t & 31, grp = t >> 5;
        float adl = g_ad[dst * 32 + l];
        float lm = -3.4e38f;
        for (int e = grp; e < ne; e += 8) {
            int src = g_csr_src[off0 + e];
            float v = g_as[src * 32 + l] + adl;
            v = v > 0.f ? v : 0.2f * v;
            lm = fmaxf(lm, v);
        }
        part[grp][l] = lm;
        __syncthreads();
        if (t < 32) {
            float m = part[0][t];
            #pragma unroll
            for (int g2 = 1; g2 < 8; g2++) m = fmaxf(m, part[g2][t]);
            sm_m[t] = m;
        }
        __syncthreads();
    }
    {   // phase B: denom
        int l = t & 31, grp = t >> 5;
        float adl = g_ad[dst * 32 + l];
        float m = sm_m[l], sden = 0.f;
        for (int e = grp; e < ne; e += 8) {
            int src = g_csr_src[off0 + e];
            float v = g_as[src * 32 + l] + adl;
            v = v > 0.f ? v : 0.2f * v;
            sden += expf(v - m);
        }
        __syncthreads();
        part[grp][l] = sden;
        __syncthreads();
        if (t < 32) {
            float s2 = 0.f;
            #pragma unroll
            for (int g2 = 0; g2 < 8; g2++) s2 += part[g2][t];
            sm_d[t] = s2;
        }
        __syncthreads();
    }
    {   // phase C: weighted aggregation
        int l = t >> 3, d0 = (t & 7) * 16;
        float m = sm_m[l];
        float adl = g_ad[dst * 32 + l];
        float acc[16];
        #pragma unroll
        for (int i = 0; i < 16; i++) acc[i] = 0.f;
        for (int e = 0; e < ne; e++) {
            int src = g_csr_src[off0 + e];
            float v = g_as[src * 32 + l] + adl;
            v = v > 0.f ? v : 0.2f * v;
            float ex = expf(v - m);
            const float4* hp = (const float4*)(g_h + ((size_t)src * 32 + l) * 128 + d0);
            #pragma unroll
            for (int q = 0; q < 4; q++) {
                float4 h4 = hp[q];
                acc[q * 4 + 0] += ex * h4.x;
                acc[q * 4 + 1] += ex * h4.y;
                acc[q * 4 + 2] += ex * h4.z;
                acc[q * 4 + 3] += ex * h4.w;
            }
        }
        float inv = 1.f / (sm_d[l] + 1e-16f);
        float* op = out + ((size_t)dst * 32 + l) * 128 + d0;
        #pragma unroll
        for (int q = 0; q < 4; q++) {
            float4 o4;
            o4.x = acc[q * 4 + 0] * inv + gat_b[d0 + q * 4 + 0];
            o4.y = acc[q * 4 + 1] * inv + gat_b[d0 + q * 4 + 1];
            o4.z = acc[q * 4 + 2] * inv + gat_b[d0 + q * 4 + 2];
            o4.w = acc[q * 4 + 3] * inv + gat_b[d0 + q * 4 + 3];
            ((float4*)op)[q] = o4;
        }
    }
}

// ---------------- launch ------------------------------------------------------
extern "C" void kernel_launch(void* const* d_in, const int* in_sizes, int n_in,
                              void* d_out, int out_size) {
    const float* x     = (const float*)d_in[0];
    const int*   ei32  = (const int*)d_in[1];
    const float* ln1_g = (const float*)d_in[2];
    const float* ln1_b = (const float*)d_in[3];
    const float* qkv_w = (const float*)d_in[4];
    const float* qkv_b = (const float*)d_in[5];
    const float* out_w = (const float*)d_in[6];
    const float* out_b = (const float*)d_in[7];
    const float* ln2_g = (const float*)d_in[8];
    const float* ln2_b = (const float*)d_in[9];
    const float* ff1_w = (const float*)d_in[10];
    const float* ff1_b = (const float*)d_in[11];
    const float* ff2_w = (const float*)d_in[12];
    const float* ff2_b = (const float*)d_in[13];
    const float* gat_w = (const float*)d_in[14];
    const float* att_s = (const float*)d_in[15];
    const float* att_d = (const float*)d_in[16];
    const float* gat_b = (const float*)d_in[17];
    float* out = (float*)d_out;

    float *p_qkv, *p_x2, *p_h;
    __nv_bfloat16 *p_b1hi, *p_b1lo, *p_b2hi, *p_b2lo, *p_whi, *p_wlo;
    cudaGetSymbolAddress((void**)&p_qkv,  g_qkv);
    cudaGetSymbolAddress((void**)&p_x2,   g_x2);
    cudaGetSymbolAddress((void**)&p_h,    g_h);
    cudaGetSymbolAddress((void**)&p_b1hi, g_b1hi);
    cudaGetSymbolAddress((void**)&p_b1lo, g_b1lo);
    cudaGetSymbolAddress((void**)&p_b2hi, g_b2hi);
    cudaGetSymbolAddress((void**)&p_b2lo, g_b2lo);
    cudaGetSymbolAddress((void**)&p_whi,  g_whi);
    cudaGetSymbolAddress((void**)&p_wlo,  g_wlo);

    const int GEMM_SMEM = 4 * 128 * SLD * 2;   // 73728 B
    cudaFuncSetAttribute(gemm_mma_kernel,
                         cudaFuncAttributeMaxDynamicSharedMemorySize, GEMM_SMEM);
    cudaFuncSetAttribute(attn_kernel,
                         cudaFuncAttributeMaxDynamicSharedMemorySize, 53248);

    // 1. weight splits
    split_w_kernel<<<(W_TOTAL + 255) / 256, 256>>>(qkv_w, out_w, ff1_w, ff2_w, gat_w);
    // 2. LN1 -> b1 split
    ln_kernel<<<MM / 8, 256>>>(x, p_b1hi, p_b1lo, ln1_g, ln1_b);
    // 3. CSR zero
    zero_counts_kernel<<<(K_NODES + 255) / 256, 256>>>();
    // 4. qkv GEMM  (ncu slot)
    gemm_mma_kernel<<<dim3(MM / 128, 3), 256, GEMM_SMEM>>>(
        p_b1hi, p_b1lo, 128, 128, p_whi + WOFF_QKV, p_wlo + WOFF_QKV,
        qkv_b, p_qkv, nullptr, nullptr, 384, nullptr, 0);
    // 5-6. CSR detect/count
    detect_dtype_kernel<<<(N_EDGES + 255) / 256, 256>>>(ei32);
    count_edges_kernel<<<(N_TOT_EDGES + 255) / 256, 256>>>(ei32);
    // 7. attention -> b1 split
    attn_kernel<<<K_NODES, 256, 53248>>>();
    // 8. out-proj + residual -> x2 (fp32)
    gemm_mma_kernel<<<dim3(MM / 128, 1), 256, GEMM_SMEM>>>(
        p_b1hi, p_b1lo, 128, 128, p_whi + WOFF_OUT, p_wlo + WOFF_OUT,
        out_b, p_x2, nullptr, nullptr, 128, x, 2);
    // 9. CSR scan
    scan_kernel<<<1, 1024>>>();
    // 10. LN2 -> b1 split
    ln_kernel<<<MM / 8, 256>>>(p_x2, p_b1hi, p_b1lo, ln2_g, ln2_b);
    // 11. ff1 + gelu -> b2 split
    gemm_mma_kernel<<<dim3(MM / 128, 4), 256, GEMM_SMEM>>>(
        p_b1hi, p_b1lo, 128, 128, p_whi + WOFF_FF1, p_wlo + WOFF_FF1,
        ff1_b, nullptr, p_b2hi, p_b2lo, 512, nullptr, 1);
    // 12. ff2 + residual -> xt (b1 split)
    gemm_mma_kernel<<<dim3(MM / 128, 1), 256, GEMM_SMEM>>>(
        p_b2hi, p_b2lo, 512, 512, p_whi + WOFF_FF2, p_wlo + WOFF_FF2,
        ff2_b, nullptr, p_b1hi, p_b1lo, 128, p_x2, 4);
    // 13. GAT transform -> h (fp32)
    gemm_mma_kernel<<<dim3(MM / 128, 1), 256, GEMM_SMEM>>>(
        p_b1hi, p_b1lo, 128, 128, p_whi + WOFF_GAT, p_wlo + WOFF_GAT,
        nullptr, p_h, nullptr, nullptr, 128, nullptr, 3);
    // 14. CSR fill
    fill_edges_kernel<<<(N_TOT_EDGES + 255) / 256, 256>>>(ei32);
    // 15. attention coefficients
    asad_kernel<<<K_NODES, 256>>>(att_s, att_d);
    // 16. aggregate
    gat_aggregate_kernel<<<K_NODES, 256>>>(gat_b, out);
}

// round 9
// speedup vs baseline: 2.8201x; 1.0473x over previous
#include <cuda_runtime.h>
#include <cuda_bf16.h>
#include <cstdint>
#include <math.h>

#define K_NODES 4096
#define SEQ_L   32
#define D_MODEL 128
#define D_FF    512
#define N_EDGES 65536
#define N_TOT_EDGES (N_EDGES + K_NODES)
#define MM (K_NODES * SEQ_L)           // 131072 rows

#define SLD 72                          // smem bf16 row stride for 64-k chunk

// weight segment offsets in the packed split buffer
#define WOFF_QKV 0
#define WOFF_OUT 49152
#define WOFF_FF1 65536
#define WOFF_FF2 131072
#define WOFF_GAT 196608
#define W_TOTAL  212992

// ---------------- scratch (static; no runtime alloc) -------------------------
__device__ __nv_bfloat16 g_b1hi[MM * 128], g_b1lo[MM * 128];
__device__ __nv_bfloat16 g_b2hi[MM * 512], g_b2lo[MM * 512];
__device__ __nv_bfloat16 g_whi[W_TOTAL],  g_wlo[W_TOTAL];
__device__ float g_qkv[MM * 384];
__device__ float g_x2 [MM * 128];
__device__ float g_h  [MM * 128];
__device__ float g_as[K_NODES * SEQ_L];
__device__ float g_ad[K_NODES * SEQ_L];
__device__ int   g_cnt[K_NODES];
__device__ int   g_cur[K_NODES];
__device__ int   g_off[K_NODES + 1];
__device__ int   g_csr_src[N_TOT_EDGES];
__device__ int   g_is32;

__device__ __forceinline__ float gelu_exact(float v) {
    return 0.5f * v * (1.0f + erff(v * 0.70710678118654752f));
}

__device__ __forceinline__ uint32_t smem_u32(const void* p) {
    uint32_t a;
    asm("{ .reg .u64 t; cvta.to.shared.u64 t, %1; cvt.u32.u64 %0, t; }"
        : "=r"(a) : "l"(p));
    return a;
}

// mma.sync m16n8k16 row.col f32.bf16.bf16.f32 (portable PTX, sm_80+)
__device__ __forceinline__ void mma16816(float* d,
                                         const uint32_t* a, const uint32_t* b) {
    asm volatile(
        "mma.sync.aligned.m16n8k16.row.col.f32.bf16.bf16.f32 "
        "{%0,%1,%2,%3}, {%4,%5,%6,%7}, {%8,%9}, {%0,%1,%2,%3};"
        : "+f"(d[0]), "+f"(d[1]), "+f"(d[2]), "+f"(d[3])
        : "r"(a[0]), "r"(a[1]), "r"(a[2]), "r"(a[3]), "r"(b[0]), "r"(b[1]));
}

__device__ __forceinline__ void ldsm4(uint32_t* r, uint32_t addr) {
    asm volatile("ldmatrix.sync.aligned.m8n8.x4.shared.b16 {%0,%1,%2,%3}, [%4];"
        : "=r"(r[0]), "=r"(r[1]), "=r"(r[2]), "=r"(r[3]) : "r"(addr));
}

__device__ __forceinline__ void split1(float v, __nv_bfloat16& h, __nv_bfloat16& l) {
    h = __float2bfloat16(v);
    l = __float2bfloat16(v - __bfloat162float(h));
}

// ---------------- weight split ------------------------------------------------
__global__ void split_w_kernel(const float* __restrict__ w0, const float* __restrict__ w1,
                               const float* __restrict__ w2, const float* __restrict__ w3,
                               const float* __restrict__ w4) {
    int i = blockIdx.x * 256 + threadIdx.x;
    if (i >= W_TOTAL) return;
    const float* src; int off;
    if      (i < WOFF_OUT) { src = w0; off = WOFF_QKV; }
    else if (i < WOFF_FF1) { src = w1; off = WOFF_OUT; }
    else if (i < WOFF_FF2) { src = w2; off = WOFF_FF1; }
    else if (i < WOFF_GAT) { src = w3; off = WOFF_FF2; }
    else                   { src = w4; off = WOFF_GAT; }
    float v = src[i - off];
    __nv_bfloat16 h, l;
    split1(v, h, l);
    g_whi[i] = h; g_wlo[i] = l;
}

// ---------------- tensor-core GEMM on pre-split bf16 -------------------------
// Tile 128x128. Warp grid 4(M)x2(N): warp owns 32 rows x 64 cols.
// ldmatrix fragment loads; 3-term split AhiBhi+AhiBlo+AloBhi, fp32 accum.
// epi: 0=+bias fp32; 1=+bias,gelu->split; 2=+bias,+res fp32; 3=none fp32;
//      4=+bias,+res->split.
__global__ void __launch_bounds__(256, 2)
gemm_mma_kernel(const __nv_bfloat16* __restrict__ Ahi,
                const __nv_bfloat16* __restrict__ Alo, int lda, int K,
                const __nv_bfloat16* __restrict__ Whi,
                const __nv_bfloat16* __restrict__ Wlo,
                const float* __restrict__ bias,
                float* __restrict__ C,
                __nv_bfloat16* __restrict__ Chi, __nv_bfloat16* __restrict__ Clo,
                int ldc, const float* __restrict__ res, int epi) {
    extern __shared__ __nv_bfloat16 sm[];
    __nv_bfloat16* sAhi = sm;
    __nv_bfloat16* sAlo = sAhi + 128 * SLD;
    __nv_bfloat16* sBhi = sAlo + 128 * SLD;
    __nv_bfloat16* sBlo = sBhi + 128 * SLD;
    uint32_t uAhi = smem_u32(sAhi), uAlo = smem_u32(sAlo);
    uint32_t uBhi = smem_u32(sBhi), uBlo = smem_u32(sBlo);

    int t    = threadIdx.x;
    int wid  = t >> 5, lane = t & 31;
    int g    = lane >> 2;
    int c    = lane & 3;
    int M0   = blockIdx.x * 128;
    int col0 = blockIdx.y * 128;
    int wm   = wid >> 1, wn = wid & 1;
    int m_base = wm * 32, n_base = wn * 64;

    // ldmatrix lane-address components
    int la = lane & 15;                       // A row within 16
    int ka = (lane >> 4) * 8;                 // A k-half
    int lb = (lane & 7) + ((lane >> 4) * 8);  // B row within 16
    int kb = ((lane >> 3) & 1) * 8;           // B k-half

    float acc[2][8][4];
    #pragma unroll
    for (int mt = 0; mt < 2; mt++)
        #pragma unroll
        for (int nt = 0; nt < 8; nt++)
            #pragma unroll
            for (int q = 0; q < 4; q++) acc[mt][nt][q] = 0.f;

    for (int kc = 0; kc < K; kc += 64) {
        __syncthreads();
        #pragma unroll
        for (int i = 0; i < 4; i++) {
            int f   = i * 256 + t;            // 0..1023
            int row = f >> 3;
            int c8  = (f & 7) * 8;
            *(uint4*)(sAhi + row * SLD + c8) =
                *(const uint4*)(Ahi + (size_t)(M0 + row) * lda + kc + c8);
            *(uint4*)(sAlo + row * SLD + c8) =
                *(const uint4*)(Alo + (size_t)(M0 + row) * lda + kc + c8);
            *(uint4*)(sBhi + row * SLD + c8) =
                *(const uint4*)(Whi + (size_t)(col0 + row) * K + kc + c8);
            *(uint4*)(sBlo + row * SLD + c8) =
                *(const uint4*)(Wlo + (size_t)(col0 + row) * K + kc + c8);
        }
        __syncthreads();

        #pragma unroll
        for (int kk = 0; kk < 64; kk += 16) {
            uint32_t ah0[4], ah1[4], al0[4], al1[4];
            uint32_t aoff0 = ((m_base + la) * SLD + ka + kk) * 2;
            uint32_t aoff1 = ((m_base + 16 + la) * SLD + ka + kk) * 2;
            ldsm4(ah0, uAhi + aoff0);
            ldsm4(ah1, uAhi + aoff1);
            ldsm4(al0, uAlo + aoff0);
            ldsm4(al1, uAlo + aoff1);
            #pragma unroll
            for (int np = 0; np < 4; np++) {
                uint32_t bh[4], bl[4];
                uint32_t boff = ((n_base + np * 16 + lb) * SLD + kb + kk) * 2;
                ldsm4(bh, uBhi + boff);
                ldsm4(bl, uBlo + boff);
                int nt0 = 2 * np, nt1 = 2 * np + 1;
                mma16816(acc[0][nt0], ah0, bh);
                mma16816(acc[0][nt0], ah0, bl);
                mma16816(acc[0][nt0], al0, bh);
                mma16816(acc[0][nt1], ah0, bh + 2);
                mma16816(acc[0][nt1], ah0, bl + 2);
                mma16816(acc[0][nt1], al0, bh + 2);
                mma16816(acc[1][nt0], ah1, bh);
                mma16816(acc[1][nt0], ah1, bl);
                mma16816(acc[1][nt0], al1, bh);
                mma16816(acc[1][nt1], ah1, bh + 2);
                mma16816(acc[1][nt1], ah1, bl + 2);
                mma16816(acc[1][nt1], al1, bh + 2);
            }
        }
    }

    // epilogue: warp rows M0+m_base+mt*16+g (+8), cols col0+n_base+nt*8+2c
    #pragma unroll
    for (int mt = 0; mt < 2; mt++) {
        int row0 = M0 + m_base + mt * 16 + g;
        #pragma unroll
        for (int nt = 0; nt < 8; nt++) {
            int col = col0 + n_base + nt * 8 + 2 * c;
            float b0 = 0.f, b1 = 0.f;
            if (epi != 3) { b0 = bias[col]; b1 = bias[col + 1]; }
            float v00 = acc[mt][nt][0] + b0, v01 = acc[mt][nt][1] + b1;
            float v10 = acc[mt][nt][2] + b0, v11 = acc[mt][nt][3] + b1;
            if (epi == 1) {
                v00 = gelu_exact(v00); v01 = gelu_exact(v01);
                v10 = gelu_exact(v10); v11 = gelu_exact(v11);
            } else if (epi == 2 || epi == 4) {
                float2 ra = *(const float2*)(res + (size_t)row0 * 128 + col);
                float2 rb = *(const float2*)(res + (size_t)(row0 + 8) * 128 + col);
                v00 += ra.x; v01 += ra.y; v10 += rb.x; v11 += rb.y;
            }
            if (epi == 1 || epi == 4) {
                __nv_bfloat162 h0, l0, h1, l1;
                split1(v00, h0.x, l0.x); split1(v01, h0.y, l0.y);
                split1(v10, h1.x, l1.x); split1(v11, h1.y, l1.y);
                *(__nv_bfloat162*)(Chi + (size_t)row0 * ldc + col)       = h0;
                *(__nv_bfloat162*)(Clo + (size_t)row0 * ldc + col)       = l0;
                *(__nv_bfloat162*)(Chi + (size_t)(row0 + 8) * ldc + col) = h1;
                *(__nv_bfloat162*)(Clo + (size_t)(row0 + 8) * ldc + col) = l1;
            } else {
                float2 o0 = {v00, v01}, o1 = {v10, v11};
                *(float2*)(C + (size_t)row0 * ldc + col)       = o0;
                *(float2*)(C + (size_t)(row0 + 8) * ldc + col) = o1;
            }
        }
    }
}

// ---------------- LayerNorm: fp32 in -> bf16 split out -----------------------
__global__ void __launch_bounds__(256)
ln_kernel(const float* __restrict__ in,
          __nv_bfloat16* __restrict__ ohi, __nv_bfloat16* __restrict__ olo,
          const float* __restrict__ g, const float* __restrict__ b) {
    int warp = threadIdx.x >> 5, lane = threadIdx.x & 31;
    size_t row = (size_t)blockIdx.x * 8 + warp;
    float4 v = *(const float4*)(in + row * 128 + lane * 4);
    float s  = v.x + v.y + v.z + v.w;
    float ss = v.x * v.x + v.y * v.y + v.z * v.z + v.w * v.w;
    #pragma unroll
    for (int o = 16; o; o >>= 1) {
        s  += __shfl_xor_sync(0xffffffffu, s, o);
        ss += __shfl_xor_sync(0xffffffffu, ss, o);
    }
    float m   = s * (1.0f / 128.0f);
    float var = ss * (1.0f / 128.0f) - m * m;
    float rs  = rsqrtf(var + 1e-5f);
    float4 gg = *(const float4*)(g + lane * 4);
    float4 bb = *(const float4*)(b + lane * 4);
    float o0 = (v.x - m) * rs * gg.x + bb.x;
    float o1 = (v.y - m) * rs * gg.y + bb.y;
    float o2 = (v.z - m) * rs * gg.z + bb.z;
    float o3 = (v.w - m) * rs * gg.w + bb.w;
    __nv_bfloat162 h01, l01, h23, l23;
    split1(o0, h01.x, l01.x); split1(o1, h01.y, l01.y);
    split1(o2, h23.x, l23.x); split1(o3, h23.y, l23.y);
    *(__nv_bfloat162*)(ohi + row * 128 + lane * 4)     = h01;
    *(__nv_bfloat162*)(ohi + row * 128 + lane * 4 + 2) = h23;
    *(__nv_bfloat162*)(olo + row * 128 + lane * 4)     = l01;
    *(__nv_bfloat162*)(olo + row * 128 + lane * 4 + 2) = l23;
}

// ---------------- attention (per node, fp32 in, bf16 split out) -------------
__global__ void __launch_bounds__(256)
attn_kernel() {
    extern __shared__ float s[];
    float* sq  = s;
    float* sk  = s + 4096;
    float* sv  = s + 8192;
    float* ssc = s + 12288;
    int node = blockIdx.x, t = threadIdx.x;
    const float* qg = g_qkv + (size_t)node * 32 * 384;

    for (int i = t; i < 1024; i += 256) {
        int l = i >> 5, c4 = (i & 31) * 4;
        *(float4*)(sq + l * 128 + c4) = *(const float4*)(qg + l * 384 + c4);
        *(float4*)(sk + l * 128 + c4) = *(const float4*)(qg + l * 384 + 128 + c4);
        *(float4*)(sv + l * 128 + c4) = *(const float4*)(qg + l * 384 + 256 + c4);
    }
    __syncthreads();

    {   // scores
        int i = t >> 3, j0 = (t & 7) * 4;
        float acc[4] = {0.f, 0.f, 0.f, 0.f};
        #pragma unroll 4
        for (int d = 0; d < 128; d += 4) {
            float4 q = *(const float4*)(sq + i * 128 + d);
            #pragma unroll
            for (int jj = 0; jj < 4; jj++) {
                float4 k4 = *(const float4*)(sk + (j0 + jj) * 128 + d);
                acc[jj] += q.x * k4.x + q.y * k4.y + q.z * k4.z + q.w * k4.w;
            }
        }
        const float scale = 0.08838834764831845f;
        #pragma unroll
        for (int jj = 0; jj < 4; jj++) ssc[i * 32 + j0 + jj] = acc[jj] * scale;
    }
    __syncthreads();
    {   // softmax
        int warp = t >> 5, lane = t & 31;
        for (int r = warp; r < 32; r += 8) {
            float v = ssc[r * 32 + lane];
            float mx = v;
            #pragma unroll
            for (int o = 16; o; o >>= 1) mx = fmaxf(mx, __shfl_xor_sync(0xffffffffu, mx, o));
            float e = expf(v - mx);
            float sm2 = e;
            #pragma unroll
            for (int o = 16; o; o >>= 1) sm2 += __shfl_xor_sync(0xffffffffu, sm2, o);
            ssc[r * 32 + lane] = e / sm2;
        }
    }
    __syncthreads();
    {   // attn = a @ v -> split bf16
        int i = t >> 3, d0 = (t & 7) * 16;
        float acc[16];
        #pragma unroll
        for (int q = 0; q < 16; q++) acc[q] = 0.f;
        for (int j = 0; j < 32; j++) {
            float a = ssc[i * 32 + j];
            const float* vr = sv + j * 128 + d0;
            #pragma unroll
            for (int q = 0; q < 16; q += 4) {
                float4 v4 = *(const float4*)(vr + q);
                acc[q] += a * v4.x; acc[q + 1] += a * v4.y;
                acc[q + 2] += a * v4.z; acc[q + 3] += a * v4.w;
            }
        }
        size_t base = ((size_t)node * 32 + i) * 128 + d0;
        #pragma unroll
        for (int q = 0; q < 16; q += 2) {
            __nv_bfloat162 h, l;
            split1(acc[q],     h.x, l.x);
            split1(acc[q + 1], h.y, l.y);
            *(__nv_bfloat162*)(g_b1hi + base + q) = h;
            *(__nv_bfloat162*)(g_b1lo + base + q) = l;
        }
    }
}

// ---------------- a_src/a_dst projections ------------------------------------
__global__ void __launch_bounds__(256)
asad_kernel(const float* __restrict__ att_src, const float* __restrict__ att_dst) {
    int node = blockIdx.x, t = threadIdx.x;
    int warp = t >> 5, lane = t & 31;
    float4 as4 = *(const float4*)(att_src + lane * 4);
    float4 ad4 = *(const float4*)(att_dst + lane * 4);
    for (int r = warp; r < 32; r += 8) {
        float4 h4 = *(const float4*)(g_h + ((size_t)node * 32 + r) * 128 + lane * 4);
        float s = h4.x * as4.x + h4.y * as4.y + h4.z * as4.z + h4.w * as4.w;
        float d = h4.x * ad4.x + h4.y * ad4.y + h4.z * ad4.z + h4.w * ad4.w;
        #pragma unroll
        for (int o = 16; o; o >>= 1) {
            s += __shfl_xor_sync(0xffffffffu, s, o);
            d += __shfl_xor_sync(0xffffffffu, d, o);
        }
        if (lane == 0) {
            g_as[node * 32 + r] = s;
            g_ad[node * 32 + r] = d;
        }
    }
}

// ---------------- edge dtype detection + CSR build ---------------------------
__global__ void zero_counts_kernel() {
    int i = blockIdx.x * blockDim.x + threadIdx.x;
    if (i < K_NODES) { g_cnt[i] = 0; g_cur[i] = 0; }
    if (i == 0) g_is32 = 0;
}
__global__ void detect_dtype_kernel(const int* __restrict__ ei32) {
    int i = blockIdx.x * blockDim.x + threadIdx.x;
    if (i < N_EDGES && ei32[2 * i + 1] != 0) atomicExch(&g_is32, 1);
}
__device__ __forceinline__ int load_idx(const int* __restrict__ ei32, int elem) {
    return g_is32 ? ei32[elem] : ei32[2 * elem];
}
__global__ void count_edges_kernel(const int* __restrict__ ei32) {
    int e = blockIdx.x * blockDim.x + threadIdx.x;
    if (e >= N_TOT_EDGES) return;
    int dst = (e < N_EDGES) ? load_idx(ei32, N_EDGES + e) : (e - N_EDGES);
    if ((unsigned)dst >= K_NODES) return;
    atomicAdd(&g_cnt[dst], 1);
}
__global__ void scan_kernel() {
    __shared__ int ts[1024];
    int t = threadIdx.x;
    int c[4], s = 0;
    #pragma unroll
    for (int i = 0; i < 4; i++) { c[i] = s; s += g_cnt[t * 4 + i]; }
    ts[t] = s;
    __syncthreads();
    for (int o = 1; o < 1024; o <<= 1) {
        int v = (t >= o) ? ts[t - o] : 0;
        __syncthreads();
        ts[t] += v;
        __syncthreads();
    }
    int base = (t == 0) ? 0 : ts[t - 1];
    #pragma unroll
    for (int i = 0; i < 4; i++) g_off[t * 4 + i] = base + c[i];
    if (t == 1023) g_off[4096] = ts[1023];
}
__global__ void fill_edges_kernel(const int* __restrict__ ei32) {
    int e = blockIdx.x * blockDim.x + threadIdx.x;
    if (e >= N_TOT_EDGES) return;
    int src, dst;
    if (e < N_EDGES) {
        src = load_idx(ei32, e);
        dst = load_idx(ei32, N_EDGES + e);
    } else {
        src = dst = e - N_EDGES;
    }
    if ((unsigned)dst >= K_NODES || (unsigned)src >= K_NODES) return;
    int pos = atomicAdd(&g_cur[dst], 1);
    g_csr_src[g_off[dst] + pos] = src;
}

// ---------------- GAT aggregation: one block per dst node --------------------
__global__ void __launch_bounds__(256)
gat_aggregate_kernel(const float* __restrict__ gat_b, float* __restrict__ out) {
    __shared__ float sm_m[32], sm_d[32];
    __shared__ float part[8][32];
    int dst = blockIdx.x, t = threadIdx.x;
    int off0 = g_off[dst], ne = g_cur[dst];

    {   // phase A: per-l max
        int l = t & 31, grp = t >> 5;
        float adl = g_ad[dst * 32 + l];
        float lm = -3.4e38f;
        for (int e = grp; e < ne; e += 8) {
            int src = g_csr_src[off0 + e];
            float v = g_as[src * 32 + l] + adl;
            v = v > 0.f ? v : 0.2f * v;
            lm = fmaxf(lm, v);
        }
        part[grp][l] = lm;
        __syncthreads();
        if (t < 32) {
            float m = part[0][t];
            #pragma unroll
            for (int g2 = 1; g2 < 8; g2++) m = fmaxf(m, part[g2][t]);
            sm_m[t] = m;
        }
        __syncthreads();
    }
    {   // phase B: denom
        int l = t & 31, grp = t >> 5;
        float adl = g_ad[dst * 32 + l];
        float m = sm_m[l], sden = 0.f;
        for (int e = grp; e < ne; e += 8) {
            int src = g_csr_src[off0 + e];
            float v = g_as[src * 32 + l] + adl;
            v = v > 0.f ? v : 0.2f * v;
            sden += expf(v - m);
        }
        __syncthreads();
        part[grp][l] = sden;
        __syncthreads();
        if (t < 32) {
            float s2 = 0.f;
            #pragma unroll
            for (int g2 = 0; g2 < 8; g2++) s2 += part[g2][t];
            sm_d[t] = s2;
        }
        __syncthreads();
    }
    {   // phase C: weighted aggregation
        int l = t >> 3, d0 = (t & 7) * 16;
        float m = sm_m[l];
        float adl = g_ad[dst * 32 + l];
        float acc[16];
        #pragma unroll
        for (int i = 0; i < 16; i++) acc[i] = 0.f;
        for (int e = 0; e < ne; e++) {
            int src = g_csr_src[off0 + e];
            float v = g_as[src * 32 + l] + adl;
            v = v > 0.f ? v : 0.2f * v;
            float ex = expf(v - m);
            const float4* hp = (const float4*)(g_h + ((size_t)src * 32 + l) * 128 + d0);
            #pragma unroll
            for (int q = 0; q < 4; q++) {
                float4 h4 = hp[q];
                acc[q * 4 + 0] += ex * h4.x;
                acc[q * 4 + 1] += ex * h4.y;
                acc[q * 4 + 2] += ex * h4.z;
                acc[q * 4 + 3] += ex * h4.w;
            }
        }
        float inv = 1.f / (sm_d[l] + 1e-16f);
        float* op = out + ((size_t)dst * 32 + l) * 128 + d0;
        #pragma unroll
        for (int q = 0; q < 4; q++) {
            float4 o4;
            o4.x = acc[q * 4 + 0] * inv + gat_b[d0 + q * 4 + 0];
            o4.y = acc[q * 4 + 1] * inv + gat_b[d0 + q * 4 + 1];
            o4.z = acc[q * 4 + 2] * inv + gat_b[d0 + q * 4 + 2];
            o4.w = acc[q * 4 + 3] * inv + gat_b[d0 + q * 4 + 3];
            ((float4*)op)[q] = o4;
        }
    }
}

// ---------------- launch ------------------------------------------------------
extern "C" void kernel_launch(void* const* d_in, const int* in_sizes, int n_in,
                              void* d_out, int out_size) {
    const float* x     = (const float*)d_in[0];
    const int*   ei32  = (const int*)d_in[1];
    const float* ln1_g = (const float*)d_in[2];
    const float* ln1_b = (const float*)d_in[3];
    const float* qkv_w = (const float*)d_in[4];
    const float* qkv_b = (const float*)d_in[5];
    const float* out_w = (const float*)d_in[6];
    const float* out_b = (const float*)d_in[7];
    const float* ln2_g = (const float*)d_in[8];
    const float* ln2_b = (const float*)d_in[9];
    const float* ff1_w = (const float*)d_in[10];
    const float* ff1_b = (const float*)d_in[11];
    const float* ff2_w = (const float*)d_in[12];
    const float* ff2_b = (const float*)d_in[13];
    const float* gat_w = (const float*)d_in[14];
    const float* att_s = (const float*)d_in[15];
    const float* att_d = (const float*)d_in[16];
    const float* gat_b = (const float*)d_in[17];
    float* out = (float*)d_out;

    float *p_qkv, *p_x2, *p_h;
    __nv_bfloat16 *p_b1hi, *p_b1lo, *p_b2hi, *p_b2lo, *p_whi, *p_wlo;
    cudaGetSymbolAddress((void**)&p_qkv,  g_qkv);
    cudaGetSymbolAddress((void**)&p_x2,   g_x2);
    cudaGetSymbolAddress((void**)&p_h,    g_h);
    cudaGetSymbolAddress((void**)&p_b1hi, g_b1hi);
    cudaGetSymbolAddress((void**)&p_b1lo, g_b1lo);
    cudaGetSymbolAddress((void**)&p_b2hi, g_b2hi);
    cudaGetSymbolAddress((void**)&p_b2lo, g_b2lo);
    cudaGetSymbolAddress((void**)&p_whi,  g_whi);
    cudaGetSymbolAddress((void**)&p_wlo,  g_wlo);

    const int GEMM_SMEM = 4 * 128 * SLD * 2;   // 73728 B
    cudaFuncSetAttribute(gemm_mma_kernel,
                         cudaFuncAttributeMaxDynamicSharedMemorySize, GEMM_SMEM);
    cudaFuncSetAttribute(attn_kernel,
                         cudaFuncAttributeMaxDynamicSharedMemorySize, 53248);

    // 1. weight splits
    split_w_kernel<<<(W_TOTAL + 255) / 256, 256>>>(qkv_w, out_w, ff1_w, ff2_w, gat_w);
    // 2. LN1 -> b1 split
    ln_kernel<<<MM / 8, 256>>>(x, p_b1hi, p_b1lo, ln1_g, ln1_b);
    // 3. CSR zero
    zero_counts_kernel<<<(K_NODES + 255) / 256, 256>>>();
    // 4. qkv GEMM  (ncu slot)
    gemm_mma_kernel<<<dim3(MM / 128, 3), 256, GEMM_SMEM>>>(
        p_b1hi, p_b1lo, 128, 128, p_whi + WOFF_QKV, p_wlo + WOFF_QKV,
        qkv_b, p_qkv, nullptr, nullptr, 384, nullptr, 0);
    // 5-6. CSR detect/count
    detect_dtype_kernel<<<(N_EDGES + 255) / 256, 256>>>(ei32);
    count_edges_kernel<<<(N_TOT_EDGES + 255) / 256, 256>>>(ei32);
    // 7. attention -> b1 split
    attn_kernel<<<K_NODES, 256, 53248>>>();
    // 8. out-proj + residual -> x2 (fp32)
    gemm_mma_kernel<<<dim3(MM / 128, 1), 256, GEMM_SMEM>>>(
        p_b1hi, p_b1lo, 128, 128, p_whi + WOFF_OUT, p_wlo + WOFF_OUT,
        out_b, p_x2, nullptr, nullptr, 128, x, 2);
    // 9. CSR scan
    scan_kernel<<<1, 1024>>>();
    // 10. LN2 -> b1 split
    ln_kernel<<<MM / 8, 256>>>(p_x2, p_b1hi, p_b1lo, ln2_g, ln2_b);
    // 11. ff1 + gelu -> b2 split
    gemm_mma_kernel<<<dim3(MM / 128, 4), 256, GEMM_SMEM>>>(
        p_b1hi, p_b1lo, 128, 128, p_whi + WOFF_FF1, p_wlo + WOFF_FF1,
        ff1_b, nullptr, p_b2hi, p_b2lo, 512, nullptr, 1);
    // 12. ff2 + residual -> xt (b1 split)
    gemm_mma_kernel<<<dim3(MM / 128, 1), 256, GEMM_SMEM>>>(
        p_b2hi, p_b2lo, 512, 512, p_whi + WOFF_FF2, p_wlo + WOFF_FF2,
        ff2_b, nullptr, p_b1hi, p_b1lo, 128, p_x2, 4);
    // 13. GAT transform -> h (fp32)
    gemm_mma_kernel<<<dim3(MM / 128, 1), 256, GEMM_SMEM>>>(
        p_b1hi, p_b1lo, 128, 128, p_whi + WOFF_GAT, p_wlo + WOFF_GAT,
        nullptr, p_h, nullptr, nullptr, 128, nullptr, 3);
    // 14. CSR fill
    fill_edges_kernel<<<(N_TOT_EDGES + 255) / 256, 256>>>(ei32);
    // 15. attention coefficients
    asad_kernel<<<K_NODES, 256>>>(att_s, att_d);
    // 16. aggregate
    gat_aggregate_kernel<<<K_NODES, 256>>>(gat_b, out);
}

// round 10
// speedup vs baseline: 2.8495x; 1.0104x over previous
#include <cuda_runtime.h>
#include <cuda_bf16.h>
#include <cstdint>
#include <math.h>

#define K_NODES 4096
#define SEQ_L   32
#define D_MODEL 128
#define D_FF    512
#define N_EDGES 65536
#define N_TOT_EDGES (N_EDGES + K_NODES)
#define MM (K_NODES * SEQ_L)           // 131072 rows

#define KCH  32                         // k-chunk per pipeline stage
#define SLD  40                         // smem bf16 row stride (32 + 8 pad)
#define STAGE_B (4 * 128 * SLD * 2)     // 40960 B per stage

// weight segment offsets in the packed split buffer
#define WOFF_QKV 0
#define WOFF_OUT 49152
#define WOFF_FF1 65536
#define WOFF_FF2 131072
#define WOFF_GAT 196608
#define W_TOTAL  212992

// ---------------- scratch (static; no runtime alloc) -------------------------
__device__ __nv_bfloat16 g_b1hi[MM * 128], g_b1lo[MM * 128];
__device__ __nv_bfloat16 g_b2hi[MM * 512], g_b2lo[MM * 512];
__device__ __nv_bfloat16 g_whi[W_TOTAL],  g_wlo[W_TOTAL];
__device__ float g_qkv[MM * 384];
__device__ float g_x2 [MM * 128];
__device__ float g_h  [MM * 128];
__device__ float g_as[K_NODES * SEQ_L];
__device__ float g_ad[K_NODES * SEQ_L];
__device__ int   g_cnt[K_NODES];
__device__ int   g_cur[K_NODES];
__device__ int   g_off[K_NODES + 1];
__device__ int   g_csr_src[N_TOT_EDGES];
__device__ int   g_is32;

__device__ __forceinline__ float gelu_exact(float v) {
    return 0.5f * v * (1.0f + erff(v * 0.70710678118654752f));
}

__device__ __forceinline__ uint32_t smem_u32(const void* p) {
    uint32_t a;
    asm("{ .reg .u64 t; cvta.to.shared.u64 t, %1; cvt.u32.u64 %0, t; }"
        : "=r"(a) : "l"(p));
    return a;
}

__device__ __forceinline__ void cp16(uint32_t dst, const void* src) {
    asm volatile("cp.async.cg.shared.global [%0], [%1], 16;"
                 :: "r"(dst), "l"(src));
}
#define CP_COMMIT() asm volatile("cp.async.commit_group;" ::: "memory")

// mma.sync m16n8k16 row.col f32.bf16.bf16.f32 (portable PTX, sm_80+)
__device__ __forceinline__ void mma16816(float* d,
                                         const uint32_t* a, const uint32_t* b) {
    asm volatile(
        "mma.sync.aligned.m16n8k16.row.col.f32.bf16.bf16.f32 "
        "{%0,%1,%2,%3}, {%4,%5,%6,%7}, {%8,%9}, {%0,%1,%2,%3};"
        : "+f"(d[0]), "+f"(d[1]), "+f"(d[2]), "+f"(d[3])
        : "r"(a[0]), "r"(a[1]), "r"(a[2]), "r"(a[3]), "r"(b[0]), "r"(b[1]));
}

__device__ __forceinline__ void ldsm4(uint32_t* r, uint32_t addr) {
    asm volatile("ldmatrix.sync.aligned.m8n8.x4.shared.b16 {%0,%1,%2,%3}, [%4];"
        : "=r"(r[0]), "=r"(r[1]), "=r"(r[2]), "=r"(r[3]) : "r"(addr));
}

__device__ __forceinline__ void split1(float v, __nv_bfloat16& h, __nv_bfloat16& l) {
    h = __float2bfloat16(v);
    l = __float2bfloat16(v - __bfloat162float(h));
}

// ---------------- weight split ------------------------------------------------
__global__ void split_w_kernel(const float* __restrict__ w0, const float* __restrict__ w1,
                               const float* __restrict__ w2, const float* __restrict__ w3,
                               const float* __restrict__ w4) {
    int i = blockIdx.x * 256 + threadIdx.x;
    if (i >= W_TOTAL) return;
    const float* src; int off;
    if      (i < WOFF_OUT) { src = w0; off = WOFF_QKV; }
    else if (i < WOFF_FF1) { src = w1; off = WOFF_OUT; }
    else if (i < WOFF_FF2) { src = w2; off = WOFF_FF1; }
    else if (i < WOFF_GAT) { src = w3; off = WOFF_FF2; }
    else                   { src = w4; off = WOFF_GAT; }
    float v = src[i - off];
    __nv_bfloat16 h, l;
    split1(v, h, l);
    g_whi[i] = h; g_wlo[i] = l;
}

// ---------------- tensor-core GEMM, cp.async double-buffered ------------------
// Tile 128x128, warp grid 4(M)x2(N). 3-term bf16 split, fp32 accum.
// epi: 0=+bias fp32; 1=+bias,gelu->split; 2=+bias,+res fp32; 3=none fp32;
//      4=+bias,+res->split.
__global__ void __launch_bounds__(256, 2)
gemm_mma_kernel(const __nv_bfloat16* __restrict__ Ahi,
                const __nv_bfloat16* __restrict__ Alo, int lda, int K,
                const __nv_bfloat16* __restrict__ Whi,
                const __nv_bfloat16* __restrict__ Wlo,
                const float* __restrict__ bias,
                float* __restrict__ C,
                __nv_bfloat16* __restrict__ Chi, __nv_bfloat16* __restrict__ Clo,
                int ldc, const float* __restrict__ res, int epi) {
    extern __shared__ __nv_bfloat16 sm[];
    uint32_t u0 = smem_u32(sm);

    int t    = threadIdx.x;
    int wid  = t >> 5, lane = t & 31;
    int g    = lane >> 2;
    int c    = lane & 3;
    int M0   = blockIdx.x * 128;
    int col0 = blockIdx.y * 128;
    int wm   = wid >> 1, wn = wid & 1;
    int m_base = wm * 32, n_base = wn * 64;

    int la = lane & 15;
    int ka = (lane >> 4) * 8;
    int lb = (lane & 7) + ((lane >> 4) * 8);
    int kb = ((lane >> 3) & 1) * 8;

    // copy-index precompute: idx in [0, 2048) 16B segments per chunk
    // arr = idx>>9 (0..3), row = (idx>>2)&127, seg8 = (idx&3)*8 (bf16 elems)
    float acc[2][8][4];
    #pragma unroll
    for (int mt = 0; mt < 2; mt++)
        #pragma unroll
        for (int nt = 0; nt < 8; nt++)
            #pragma unroll
            for (int q = 0; q < 4; q++) acc[mt][nt][q] = 0.f;

    int nch = K / KCH;

    // stage-copy lambda (8 cp.async per thread)
    auto copy_chunk = [&](int kc, int stg) {
        uint32_t sbase = u0 + stg * STAGE_B;
        #pragma unroll
        for (int it = 0; it < 8; it++) {
            int idx  = it * 256 + t;
            int arr  = idx >> 9;
            int row  = (idx >> 2) & 127;
            int seg8 = (idx & 3) * 8;
            const __nv_bfloat16* src;
            if      (arr == 0) src = Ahi + (size_t)(M0 + row) * lda + kc + seg8;
            else if (arr == 1) src = Alo + (size_t)(M0 + row) * lda + kc + seg8;
            else if (arr == 2) src = Whi + (size_t)(col0 + row) * K + kc + seg8;
            else               src = Wlo + (size_t)(col0 + row) * K + kc + seg8;
            cp16(sbase + ((arr * 128 + row) * SLD + seg8) * 2, src);
        }
        CP_COMMIT();
    };

    copy_chunk(0, 0);

    for (int ch = 0; ch < nch; ch++) {
        int cur = ch & 1;
        if (ch + 1 < nch) copy_chunk((ch + 1) * KCH, cur ^ 1);
        if (ch + 1 < nch) { asm volatile("cp.async.wait_group 1;" ::: "memory"); }
        else              { asm volatile("cp.async.wait_group 0;" ::: "memory"); }
        __syncthreads();

        uint32_t base = u0 + cur * STAGE_B;
        uint32_t bAhi = base;
        uint32_t bAlo = base + 128 * SLD * 2;
        uint32_t bBhi = base + 2 * 128 * SLD * 2;
        uint32_t bBlo = base + 3 * 128 * SLD * 2;

        #pragma unroll
        for (int kk = 0; kk < KCH; kk += 16) {
            uint32_t ah0[4], ah1[4], al0[4], al1[4];
            uint32_t aoff0 = ((m_base + la) * SLD + ka + kk) * 2;
            uint32_t aoff1 = ((m_base + 16 + la) * SLD + ka + kk) * 2;
            ldsm4(ah0, bAhi + aoff0);
            ldsm4(ah1, bAhi + aoff1);
            ldsm4(al0, bAlo + aoff0);
            ldsm4(al1, bAlo + aoff1);
            #pragma unroll
            for (int np = 0; np < 4; np++) {
                uint32_t bh[4], bl[4];
                uint32_t boff = ((n_base + np * 16 + lb) * SLD + kb + kk) * 2;
                ldsm4(bh, bBhi + boff);
                ldsm4(bl, bBlo + boff);
                int nt0 = 2 * np, nt1 = 2 * np + 1;
                mma16816(acc[0][nt0], ah0, bh);
                mma16816(acc[0][nt0], ah0, bl);
                mma16816(acc[0][nt0], al0, bh);
                mma16816(acc[0][nt1], ah0, bh + 2);
                mma16816(acc[0][nt1], ah0, bl + 2);
                mma16816(acc[0][nt1], al0, bh + 2);
                mma16816(acc[1][nt0], ah1, bh);
                mma16816(acc[1][nt0], ah1, bl);
                mma16816(acc[1][nt0], al1, bh);
                mma16816(acc[1][nt1], ah1, bh + 2);
                mma16816(acc[1][nt1], ah1, bl + 2);
                mma16816(acc[1][nt1], al1, bh + 2);
            }
        }
        __syncthreads();
    }

    // epilogue
    #pragma unroll
    for (int mt = 0; mt < 2; mt++) {
        int row0 = M0 + m_base + mt * 16 + g;
        #pragma unroll
        for (int nt = 0; nt < 8; nt++) {
            int col = col0 + n_base + nt * 8 + 2 * c;
            float b0 = 0.f, b1 = 0.f;
            if (epi != 3) { b0 = bias[col]; b1 = bias[col + 1]; }
            float v00 = acc[mt][nt][0] + b0, v01 = acc[mt][nt][1] + b1;
            float v10 = acc[mt][nt][2] + b0, v11 = acc[mt][nt][3] + b1;
            if (epi == 1) {
                v00 = gelu_exact(v00); v01 = gelu_exact(v01);
                v10 = gelu_exact(v10); v11 = gelu_exact(v11);
            } else if (epi == 2 || epi == 4) {
                float2 ra = *(const float2*)(res + (size_t)row0 * 128 + col);
                float2 rb = *(const float2*)(res + (size_t)(row0 + 8) * 128 + col);
                v00 += ra.x; v01 += ra.y; v10 += rb.x; v11 += rb.y;
            }
            if (epi == 1 || epi == 4) {
                __nv_bfloat162 h0, l0, h1, l1;
                split1(v00, h0.x, l0.x); split1(v01, h0.y, l0.y);
                split1(v10, h1.x, l1.x); split1(v11, h1.y, l1.y);
                *(__nv_bfloat162*)(Chi + (size_t)row0 * ldc + col)       = h0;
                *(__nv_bfloat162*)(Clo + (size_t)row0 * ldc + col)       = l0;
                *(__nv_bfloat162*)(Chi + (size_t)(row0 + 8) * ldc + col) = h1;
                *(__nv_bfloat162*)(Clo + (size_t)(row0 + 8) * ldc + col) = l1;
            } else {
                float2 o0 = {v00, v01}, o1 = {v10, v11};
                *(float2*)(C + (size_t)row0 * ldc + col)       = o0;
                *(float2*)(C + (size_t)(row0 + 8) * ldc + col) = o1;
            }
        }
    }
}

// ---------------- LayerNorm: fp32 in -> bf16 split out -----------------------
__global__ void __launch_bounds__(256)
ln_kernel(const float* __restrict__ in,
          __nv_bfloat16* __restrict__ ohi, __nv_bfloat16* __restrict__ olo,
          const float* __restrict__ g, const float* __restrict__ b) {
    int warp = threadIdx.x >> 5, lane = threadIdx.x & 31;
    size_t row = (size_t)blockIdx.x * 8 + warp;
    float4 v = *(const float4*)(in + row * 128 + lane * 4);
    float s  = v.x + v.y + v.z + v.w;
    float ss = v.x * v.x + v.y * v.y + v.z * v.z + v.w * v.w;
    #pragma unroll
    for (int o = 16; o; o >>= 1) {
        s  += __shfl_xor_sync(0xffffffffu, s, o);
        ss += __shfl_xor_sync(0xffffffffu, ss, o);
    }
    float m   = s * (1.0f / 128.0f);
    float var = ss * (1.0f / 128.0f) - m * m;
    float rs  = rsqrtf(var + 1e-5f);
    float4 gg = *(const float4*)(g + lane * 4);
    float4 bb = *(const float4*)(b + lane * 4);
    float o0 = (v.x - m) * rs * gg.x + bb.x;
    float o1 = (v.y - m) * rs * gg.y + bb.y;
    float o2 = (v.z - m) * rs * gg.z + bb.z;
    float o3 = (v.w - m) * rs * gg.w + bb.w;
    __nv_bfloat162 h01, l01, h23, l23;
    split1(o0, h01.x, l01.x); split1(o1, h01.y, l01.y);
    split1(o2, h23.x, l23.x); split1(o3, h23.y, l23.y);
    *(__nv_bfloat162*)(ohi + row * 128 + lane * 4)     = h01;
    *(__nv_bfloat162*)(ohi + row * 128 + lane * 4 + 2) = h23;
    *(__nv_bfloat162*)(olo + row * 128 + lane * 4)     = l01;
    *(__nv_bfloat162*)(olo + row * 128 + lane * 4 + 2) = l23;
}

// ---------------- attention (per node, fp32 in, bf16 split out) -------------
__global__ void __launch_bounds__(256)
attn_kernel() {
    extern __shared__ float s[];
    float* sq  = s;
    float* sk  = s + 4096;
    float* sv  = s + 8192;
    float* ssc = s + 12288;
    int node = blockIdx.x, t = threadIdx.x;
    const float* qg = g_qkv + (size_t)node * 32 * 384;

    for (int i = t; i < 1024; i += 256) {
        int l = i >> 5, c4 = (i & 31) * 4;
        *(float4*)(sq + l * 128 + c4) = *(const float4*)(qg + l * 384 + c4);
        *(float4*)(sk + l * 128 + c4) = *(const float4*)(qg + l * 384 + 128 + c4);
        *(float4*)(sv + l * 128 + c4) = *(const float4*)(qg + l * 384 + 256 + c4);
    }
    __syncthreads();

    {   // scores
        int i = t >> 3, j0 = (t & 7) * 4;
        float acc[4] = {0.f, 0.f, 0.f, 0.f};
        #pragma unroll 4
        for (int d = 0; d < 128; d += 4) {
            float4 q = *(const float4*)(sq + i * 128 + d);
            #pragma unroll
            for (int jj = 0; jj < 4; jj++) {
                float4 k4 = *(const float4*)(sk + (j0 + jj) * 128 + d);
                acc[jj] += q.x * k4.x + q.y * k4.y + q.z * k4.z + q.w * k4.w;
            }
        }
        const float scale = 0.08838834764831845f;
        #pragma unroll
        for (int jj = 0; jj < 4; jj++) ssc[i * 32 + j0 + jj] = acc[jj] * scale;
    }
    __syncthreads();
    {   // softmax
        int warp = t >> 5, lane = t & 31;
        for (int r = warp; r < 32; r += 8) {
            float v = ssc[r * 32 + lane];
            float mx = v;
            #pragma unroll
            for (int o = 16; o; o >>= 1) mx = fmaxf(mx, __shfl_xor_sync(0xffffffffu, mx, o));
            float e = expf(v - mx);
            float sm2 = e;
            #pragma unroll
            for (int o = 16; o; o >>= 1) sm2 += __shfl_xor_sync(0xffffffffu, sm2, o);
            ssc[r * 32 + lane] = e / sm2;
        }
    }
    __syncthreads();
    {   // attn = a @ v -> split bf16
        int i = t >> 3, d0 = (t & 7) * 16;
        float acc[16];
        #pragma unroll
        for (int q = 0; q < 16; q++) acc[q] = 0.f;
        for (int j = 0; j < 32; j++) {
            float a = ssc[i * 32 + j];
            const float* vr = sv + j * 128 + d0;
            #pragma unroll
            for (int q = 0; q < 16; q += 4) {
                float4 v4 = *(const float4*)(vr + q);
                acc[q] += a * v4.x; acc[q + 1] += a * v4.y;
                acc[q + 2] += a * v4.z; acc[q + 3] += a * v4.w;
            }
        }
        size_t base = ((size_t)node * 32 + i) * 128 + d0;
        #pragma unroll
        for (int q = 0; q < 16; q += 2) {
            __nv_bfloat162 h, l;
            split1(acc[q],     h.x, l.x);
            split1(acc[q + 1], h.y, l.y);
            *(__nv_bfloat162*)(g_b1hi + base + q) = h;
            *(__nv_bfloat162*)(g_b1lo + base + q) = l;
        }
    }
}

// ---------------- a_src/a_dst projections ------------------------------------
__global__ void __launch_bounds__(256)
asad_kernel(const float* __restrict__ att_src, const float* __restrict__ att_dst) {
    int node = blockIdx.x, t = threadIdx.x;
    int warp = t >> 5, lane = t & 31;
    float4 as4 = *(const float4*)(att_src + lane * 4);
    float4 ad4 = *(const float4*)(att_dst + lane * 4);
    for (int r = warp; r < 32; r += 8) {
        float4 h4 = *(const float4*)(g_h + ((size_t)node * 32 + r) * 128 + lane * 4);
        float s = h4.x * as4.x + h4.y * as4.y + h4.z * as4.z + h4.w * as4.w;
        float d = h4.x * ad4.x + h4.y * ad4.y + h4.z * ad4.z + h4.w * ad4.w;
        #pragma unroll
        for (int o = 16; o; o >>= 1) {
            s += __shfl_xor_sync(0xffffffffu, s, o);
            d += __shfl_xor_sync(0xffffffffu, d, o);
        }
        if (lane == 0) {
            g_as[node * 32 + r] = s;
            g_ad[node * 32 + r] = d;
        }
    }
}

// ---------------- edge dtype detection + CSR build ---------------------------
__global__ void zero_counts_kernel() {
    int i = blockIdx.x * blockDim.x + threadIdx.x;
    if (i < K_NODES) { g_cnt[i] = 0; g_cur[i] = 0; }
    if (i == 0) g_is32 = 0;
}
__global__ void detect_dtype_kernel(const int* __restrict__ ei32) {
    int i = blockIdx.x * blockDim.x + threadIdx.x;
    if (i < N_EDGES && ei32[2 * i + 1] != 0) atomicExch(&g_is32, 1);
}
__device__ __forceinline__ int load_idx(const int* __restrict__ ei32, int elem) {
    return g_is32 ? ei32[elem] : ei32[2 * elem];
}
__global__ void count_edges_kernel(const int* __restrict__ ei32) {
    int e = blockIdx.x * blockDim.x + threadIdx.x;
    if (e >= N_TOT_EDGES) return;
    int dst = (e < N_EDGES) ? load_idx(ei32, N_EDGES + e) : (e - N_EDGES);
    if ((unsigned)dst >= K_NODES) return;
    atomicAdd(&g_cnt[dst], 1);
}
__global__ void scan_kernel() {
    __shared__ int ts[1024];
    int t = threadIdx.x;
    int c[4], s = 0;
    #pragma unroll
    for (int i = 0; i < 4; i++) { c[i] = s; s += g_cnt[t * 4 + i]; }
    ts[t] = s;
    __syncthreads();
    for (int o = 1; o < 1024; o <<= 1) {
        int v = (t >= o) ? ts[t - o] : 0;
        __syncthreads();
        ts[t] += v;
        __syncthreads();
    }
    int base = (t == 0) ? 0 : ts[t - 1];
    #pragma unroll
    for (int i = 0; i < 4; i++) g_off[t * 4 + i] = base + c[i];
    if (t == 1023) g_off[4096] = ts[1023];
}
__global__ void fill_edges_kernel(const int* __restrict__ ei32) {
    int e = blockIdx.x * blockDim.x + threadIdx.x;
    if (e >= N_TOT_EDGES) return;
    int src, dst;
    if (e < N_EDGES) {
        src = load_idx(ei32, e);
        dst = load_idx(ei32, N_EDGES + e);
    } else {
        src = dst = e - N_EDGES;
    }
    if ((unsigned)dst >= K_NODES || (unsigned)src >= K_NODES) return;
    int pos = atomicAdd(&g_cur[dst], 1);
    g_csr_src[g_off[dst] + pos] = src;
}

// ---------------- GAT aggregation: one block per dst node --------------------
__global__ void __launch_bounds__(256)
gat_aggregate_kernel(const float* __restrict__ gat_b, float* __restrict__ out) {
    __shared__ float sm_m[32], sm_d[32];
    __shared__ float part[8][32];
    __shared__ float s_alpha[64][33];
    __shared__ int   s_src[64];
    int dst = blockIdx.x, t = threadIdx.x;
    int off0 = g_off[dst], ne = g_cur[dst];

    {   // phase A: per-l max
        int l = t & 31, grp = t >> 5;
        float adl = g_ad[dst * 32 + l];
        float lm = -3.4e38f;
        for (int e = grp; e < ne; e += 8) {
            int src = g_csr_src[off0 + e];
            float v = g_as[src * 32 + l] + adl;
            v = v > 0.f ? v : 0.2f * v;
            lm = fmaxf(lm, v);
        }
        part[grp][l] = lm;
        __syncthreads();
        if (t < 32) {
            float m = part[0][t];
            #pragma unroll
            for (int g2 = 1; g2 < 8; g2++) m = fmaxf(m, part[g2][t]);
            sm_m[t] = m;
        }
        __syncthreads();
    }
    {   // phase B: denom
        int l = t & 31, grp = t >> 5;
        float adl = g_ad[dst * 32 + l];
        float m = sm_m[l], sden = 0.f;
        for (int e = grp; e < ne; e += 8) {
            int src = g_csr_src[off0 + e];
            float v = g_as[src * 32 + l] + adl;
            v = v > 0.f ? v : 0.2f * v;
            sden += expf(v - m);
        }
        __syncthreads();
        part[grp][l] = sden;
        __syncthreads();
        if (t < 32) {
            float s2 = 0.f;
            #pragma unroll
            for (int g2 = 0; g2 < 8; g2++) s2 += part[g2][t];
            sm_d[t] = s2;
        }
        __syncthreads();
    }
    {   // phase C: chunked alpha staging + weighted aggregation
        int l = t >> 3, d0 = (t & 7) * 16;
        float acc[16];
        #pragma unroll
        for (int i = 0; i < 16; i++) acc[i] = 0.f;

        for (int e0 = 0; e0 < ne; e0 += 64) {
            int ecnt = min(64, ne - e0);
            __syncthreads();
            if (t < ecnt) s_src[t] = g_csr_src[off0 + e0 + t];
            __syncthreads();
            for (int idx = t; idx < ecnt * 32; idx += 256) {
                int e = idx >> 5, ll = idx & 31;
                float v = g_as[s_src[e] * 32 + ll] + g_ad[dst * 32 + ll];
                v = v > 0.f ? v : 0.2f * v;
                s_alpha[e][ll] = expf(v - sm_m[ll]);
            }
            __syncthreads();
            for (int e = 0; e < ecnt; e++) {
                float ex = s_alpha[e][l];
                const float4* hp =
                    (const float4*)(g_h + ((size_t)s_src[e] * 32 + l) * 128 + d0);
                #pragma unroll
                for (int q = 0; q < 4; q++) {
                    float4 h4 = hp[q];
                    acc[q * 4 + 0] += ex * h4.x;
                    acc[q * 4 + 1] += ex * h4.y;
                    acc[q * 4 + 2] += ex * h4.z;
                    acc[q * 4 + 3] += ex * h4.w;
                }
            }
        }

        float inv = 1.f / (sm_d[l] + 1e-16f);
        float* op = out + ((size_t)dst * 32 + l) * 128 + d0;
        #pragma unroll
        for (int q = 0; q < 4; q++) {
            float4 o4;
            o4.x = acc[q * 4 + 0] * inv + gat_b[d0 + q * 4 + 0];
            o4.y = acc[q * 4 + 1] * inv + gat_b[d0 + q * 4 + 1];
            o4.z = acc[q * 4 + 2] * inv + gat_b[d0 + q * 4 + 2];
            o4.w = acc[q * 4 + 3] * inv + gat_b[d0 + q * 4 + 3];
            ((float4*)op)[q] = o4;
        }
    }
}

// ---------------- launch ------------------------------------------------------
extern "C" void kernel_launch(void* const* d_in, const int* in_sizes, int n_in,
                              void* d_out, int out_size) {
    const float* x     = (const float*)d_in[0];
    const int*   ei32  = (const int*)d_in[1];
    const float* ln1_g = (const float*)d_in[2];
    const float* ln1_b = (const float*)d_in[3];
    const float* qkv_w = (const float*)d_in[4];
    const float* qkv_b = (const float*)d_in[5];
    const float* out_w = (const float*)d_in[6];
    const float* out_b = (const float*)d_in[7];
    const float* ln2_g = (const float*)d_in[8];
    const float* ln2_b = (const float*)d_in[9];
    const float* ff1_w = (const float*)d_in[10];
    const float* ff1_b = (const float*)d_in[11];
    const float* ff2_w = (const float*)d_in[12];
    const float* ff2_b = (const float*)d_in[13];
    const float* gat_w = (const float*)d_in[14];
    const float* att_s = (const float*)d_in[15];
    const float* att_d = (const float*)d_in[16];
    const float* gat_b = (const float*)d_in[17];
    float* out = (float*)d_out;

    float *p_qkv, *p_x2, *p_h;
    __nv_bfloat16 *p_b1hi, *p_b1lo, *p_b2hi, *p_b2lo, *p_whi, *p_wlo;
    cudaGetSymbolAddress((void**)&p_qkv,  g_qkv);
    cudaGetSymbolAddress((void**)&p_x2,   g_x2);
    cudaGetSymbolAddress((void**)&p_h,    g_h);
    cudaGetSymbolAddress((void**)&p_b1hi, g_b1hi);
    cudaGetSymbolAddress((void**)&p_b1lo, g_b1lo);
    cudaGetSymbolAddress((void**)&p_b2hi, g_b2hi);
    cudaGetSymbolAddress((void**)&p_b2lo, g_b2lo);
    cudaGetSymbolAddress((void**)&p_whi,  g_whi);
    cudaGetSymbolAddress((void**)&p_wlo,  g_wlo);

    const int GEMM_SMEM = 2 * STAGE_B;   // 81920 B
    cudaFuncSetAttribute(gemm_mma_kernel,
                         cudaFuncAttributeMaxDynamicSharedMemorySize, GEMM_SMEM);
    cudaFuncSetAttribute(attn_kernel,
                         cudaFuncAttributeMaxDynamicSharedMemorySize, 53248);

    // 1. weight splits
    split_w_kernel<<<(W_TOTAL + 255) / 256, 256>>>(qkv_w, out_w, ff1_w, ff2_w, gat_w);
    // 2. LN1 -> b1 split
    ln_kernel<<<MM / 8, 256>>>(x, p_b1hi, p_b1lo, ln1_g, ln1_b);
    // 3. CSR zero
    zero_counts_kernel<<<(K_NODES + 255) / 256, 256>>>();
    // 4. qkv GEMM  (ncu slot)
    gemm_mma_kernel<<<dim3(MM / 128, 3), 256, GEMM_SMEM>>>(
        p_b1hi, p_b1lo, 128, 128, p_whi + WOFF_QKV, p_wlo + WOFF_QKV,
        qkv_b, p_qkv, nullptr, nullptr, 384, nullptr, 0);
    // 5-6. CSR detect/count
    detect_dtype_kernel<<<(N_EDGES + 255) / 256, 256>>>(ei32);
    count_edges_kernel<<<(N_TOT_EDGES + 255) / 256, 256>>>(ei32);
    // 7. attention -> b1 split
    attn_kernel<<<K_NODES, 256, 53248>>>();
    // 8. out-proj + residual -> x2 (fp32)
    gemm_mma_kernel<<<dim3(MM / 128, 1), 256, GEMM_SMEM>>>(
        p_b1hi, p_b1lo, 128, 128, p_whi + WOFF_OUT, p_wlo + WOFF_OUT,
        out_b, p_x2, nullptr, nullptr, 128, x, 2);
    // 9. CSR scan
    scan_kernel<<<1, 1024>>>();
    // 10. LN2 -> b1 split
    ln_kernel<<<MM / 8, 256>>>(p_x2, p_b1hi, p_b1lo, ln2_g, ln2_b);
    // 11. ff1 + gelu -> b2 split
    gemm_mma_kernel<<<dim3(MM / 128, 4), 256, GEMM_SMEM>>>(
        p_b1hi, p_b1lo, 128, 128, p_whi + WOFF_FF1, p_wlo + WOFF_FF1,
        ff1_b, nullptr, p_b2hi, p_b2lo, 512, nullptr, 1);
    // 12. ff2 + residual -> xt (b1 split)
    gemm_mma_kernel<<<dim3(MM / 128, 1), 256, GEMM_SMEM>>>(
        p_b2hi, p_b2lo, 512, 512, p_whi + WOFF_FF2, p_wlo + WOFF_FF2,
        ff2_b, nullptr, p_b1hi, p_b1lo, 128, p_x2, 4);
    // 13. GAT transform -> h (fp32)
    gemm_mma_kernel<<<dim3(MM / 128, 1), 256, GEMM_SMEM>>>(
        p_b1hi, p_b1lo, 128, 128, p_whi + WOFF_GAT, p_wlo + WOFF_GAT,
        nullptr, p_h, nullptr, nullptr, 128, nullptr, 3);
    // 14. CSR fill
    fill_edges_kernel<<<(N_TOT_EDGES + 255) / 256, 256>>>(ei32);
    // 15. attention coefficients
    asad_kernel<<<K_NODES, 256>>>(att_s, att_d);
    // 16. aggregate
    gat_aggregate_kernel<<<K_NODES, 256>>>(gat_b, out);
}

// round 12
// speedup vs baseline: 3.7298x; 1.3089x over previous
#include <cuda_runtime.h>
#include <cuda_bf16.h>
#include <cstdint>
#include <math.h>

#define K_NODES 4096
#define SEQ_L   32
#define D_MODEL 128
#define D_FF    512
#define N_EDGES 65536
#define N_TOT_EDGES (N_EDGES + K_NODES)
#define MM (K_NODES * SEQ_L)           // 131072 rows

// streaming GEMM (ff2) params
#define KCH  32
#define SLD  40
#define STAGE_B (4 * 128 * SLD * 2)     // 40960 B

// A-resident GEMM params
#define SLDA 136                        // A row stride (128 + 8), conflict-free
#define KCHB 16                         // B chunk k
#define SLDB 24                         // B row stride (16 + 8), conflict-free
#define A_BYTES (2 * 128 * SLDA * 2)    // 69632
#define BSTG_B  (2 * 128 * SLDB * 2)    // 12288 per stage
#define ARES_SMEM (A_BYTES + 2 * BSTG_B)  // 94208

// attn smem stride
#define ATS 132

// weight segment offsets in the packed split buffer
#define WOFF_QKV 0
#define WOFF_OUT 49152
#define WOFF_FF1 65536
#define WOFF_FF2 131072
#define WOFF_GAT 196608
#define W_TOTAL  212992

// ---------------- scratch (static; no runtime alloc) -------------------------
__device__ __nv_bfloat16 g_b1hi[MM * 128], g_b1lo[MM * 128];
__device__ __nv_bfloat16 g_b2hi[MM * 512], g_b2lo[MM * 512];
__device__ __nv_bfloat16 g_whi[W_TOTAL],  g_wlo[W_TOTAL];
__device__ float g_qkv[MM * 384];
__device__ float g_x2 [MM * 128];
__device__ float g_h  [MM * 128];
__device__ float g_as[K_NODES * SEQ_L];
__device__ float g_ad[K_NODES * SEQ_L];
__device__ int   g_cnt[K_NODES];
__device__ int   g_cur[K_NODES];
__device__ int   g_off[K_NODES + 1];
__device__ int   g_csr_src[N_TOT_EDGES];
__device__ int   g_is32;

__device__ __forceinline__ float gelu_exact(float v) {
    return 0.5f * v * (1.0f + erff(v * 0.70710678118654752f));
}

__device__ __forceinline__ uint32_t smem_u32(const void* p) {
    uint32_t a;
    asm("{ .reg .u64 t; cvta.to.shared.u64 t, %1; cvt.u32.u64 %0, t; }"
        : "=r"(a) : "l"(p));
    return a;
}

__device__ __forceinline__ void cp16(uint32_t dst, const void* src) {
    asm volatile("cp.async.cg.shared.global [%0], [%1], 16;"
                 :: "r"(dst), "l"(src));
}
#define CP_COMMIT() asm volatile("cp.async.commit_group;" ::: "memory")
#define CP_WAIT(n)  asm volatile("cp.async.wait_group %0;" :: "n"(n) : "memory")

__device__ __forceinline__ void mma16816(float* d,
                                         const uint32_t* a, const uint32_t* b) {
    asm volatile(
        "mma.sync.aligned.m16n8k16.row.col.f32.bf16.bf16.f32 "
        "{%0,%1,%2,%3}, {%4,%5,%6,%7}, {%8,%9}, {%0,%1,%2,%3};"
        : "+f"(d[0]), "+f"(d[1]), "+f"(d[2]), "+f"(d[3])
        : "r"(a[0]), "r"(a[1]), "r"(a[2]), "r"(a[3]), "r"(b[0]), "r"(b[1]));
}

__device__ __forceinline__ void ldsm4(uint32_t* r, uint32_t addr) {
    asm volatile("ldmatrix.sync.aligned.m8n8.x4.shared.b16 {%0,%1,%2,%3}, [%4];"
        : "=r"(r[0]), "=r"(r[1]), "=r"(r[2]), "=r"(r[3]) : "r"(addr));
}

__device__ __forceinline__ void split1(float v, __nv_bfloat16& h, __nv_bfloat16& l) {
    h = __float2bfloat16(v);
    l = __float2bfloat16(v - __bfloat162float(h));
}

// shared epilogue for one 16x64 thread-slice of accs
__device__ __forceinline__ void epilogue_tile(
    float acc[2][8][4], int M0, int col0, int m_base, int n_base, int g, int c,
    const float* bias, float* C, __nv_bfloat16* Chi, __nv_bfloat16* Clo,
    int ldc, const float* res, int epi) {
    #pragma unroll
    for (int mt = 0; mt < 2; mt++) {
        int row0 = M0 + m_base + mt * 16 + g;
        #pragma unroll
        for (int nt = 0; nt < 8; nt++) {
            int col = col0 + n_base + nt * 8 + 2 * c;
            float b0 = 0.f, b1 = 0.f;
            if (epi != 3) { b0 = bias[col]; b1 = bias[col + 1]; }
            float v00 = acc[mt][nt][0] + b0, v01 = acc[mt][nt][1] + b1;
            float v10 = acc[mt][nt][2] + b0, v11 = acc[mt][nt][3] + b1;
            if (epi == 1) {
                v00 = gelu_exact(v00); v01 = gelu_exact(v01);
                v10 = gelu_exact(v10); v11 = gelu_exact(v11);
            } else if (epi == 2 || epi == 4) {
                float2 ra = *(const float2*)(res + (size_t)row0 * 128 + col);
                float2 rb = *(const float2*)(res + (size_t)(row0 + 8) * 128 + col);
                v00 += ra.x; v01 += ra.y; v10 += rb.x; v11 += rb.y;
            }
            if (epi == 1 || epi == 4) {
                __nv_bfloat162 h0, l0, h1, l1;
                split1(v00, h0.x, l0.x); split1(v01, h0.y, l0.y);
                split1(v10, h1.x, l1.x); split1(v11, h1.y, l1.y);
                *(__nv_bfloat162*)(Chi + (size_t)row0 * ldc + col)       = h0;
                *(__nv_bfloat162*)(Clo + (size_t)row0 * ldc + col)       = l0;
                *(__nv_bfloat162*)(Chi + (size_t)(row0 + 8) * ldc + col) = h1;
                *(__nv_bfloat162*)(Clo + (size_t)(row0 + 8) * ldc + col) = l1;
            } else {
                float2 o0 = {v00, v01}, o1 = {v10, v11};
                *(float2*)(C + (size_t)row0 * ldc + col)       = o0;
                *(float2*)(C + (size_t)(row0 + 8) * ldc + col) = o1;
            }
        }
    }
}

// ---------------- weight split ------------------------------------------------
__global__ void split_w_kernel(const float* __restrict__ w0, const float* __restrict__ w1,
                               const float* __restrict__ w2, const float* __restrict__ w3,
                               const float* __restrict__ w4) {
    int i = blockIdx.x * 256 + threadIdx.x;
    if (i >= W_TOTAL) return;
    const float* src; int off;
    if      (i < WOFF_OUT) { src = w0; off = WOFF_QKV; }
    else if (i < WOFF_FF1) { src = w1; off = WOFF_OUT; }
    else if (i < WOFF_FF2) { src = w2; off = WOFF_FF1; }
    else if (i < WOFF_GAT) { src = w3; off = WOFF_FF2; }
    else                   { src = w4; off = WOFF_GAT; }
    float v = src[i - off];
    __nv_bfloat16 h, l;
    split1(v, h, l);
    g_whi[i] = h; g_wlo[i] = l;
}

// ---------------- A-resident tensor-core GEMM (K = 128) ----------------------
// A (hi+lo) cached fully in smem; loops NT N-tiles of 128 cols, B streamed in
// 16-k double-buffered chunks. Warp grid 4(M)x2(N). 3-term bf16 split.
__global__ void __launch_bounds__(256, 2)
gemm_ares_kernel(const __nv_bfloat16* __restrict__ Ahi,
                 const __nv_bfloat16* __restrict__ Alo,
                 const __nv_bfloat16* __restrict__ Whi,
                 const __nv_bfloat16* __restrict__ Wlo, int Kw,
                 const float* __restrict__ bias,
                 float* __restrict__ C,
                 __nv_bfloat16* __restrict__ Chi, __nv_bfloat16* __restrict__ Clo,
                 int ldc, const float* __restrict__ res, int epi, int NT) {
    extern __shared__ __nv_bfloat16 sm[];
    uint32_t uA = smem_u32(sm);
    uint32_t uB = uA + A_BYTES;

    int t    = threadIdx.x;
    int wid  = t >> 5, lane = t & 31;
    int g    = lane >> 2;
    int c    = lane & 3;
    int M0   = blockIdx.x * 128;
    int wm   = wid >> 1, wn = wid & 1;
    int m_base = wm * 32, n_base = wn * 64;

    int la = lane & 15;
    int ka = (lane >> 4) * 8;
    int lb = (lane & 7) + ((lane >> 4) * 8);
    int kb = ((lane >> 3) & 1) * 8;

    // ---- load A (hi+lo, full 128x128) via cp.async: 4096 16B segments
    #pragma unroll
    for (int it = 0; it < 16; it++) {
        int idx  = it * 256 + t;          // 0..4095
        int arr  = idx >> 11;             // 0 = hi, 1 = lo
        int row  = (idx >> 4) & 127;
        int s8   = (idx & 15) * 8;        // cols 0..120 step 8
        const __nv_bfloat16* src =
            (arr ? Alo : Ahi) + (size_t)(M0 + row) * 128 + s8;
        cp16(uA + arr * 128 * SLDA * 2 + (row * SLDA + s8) * 2, src);
    }
    CP_COMMIT();

    // B chunk copy: 512 segs (2 per thread)
    auto copyB = [&](int col0, int kc, int stg) {
        uint32_t base = uB + stg * BSTG_B;
        #pragma unroll
        for (int it = 0; it < 2; it++) {
            int idx = it * 256 + t;
            int arr = idx >> 8;
            int row = (idx >> 1) & 127;
            int s8  = (idx & 1) * 8;
            const __nv_bfloat16* src =
                (arr ? Wlo : Whi) + (size_t)(col0 + row) * Kw + kc + s8;
            cp16(base + arr * 128 * SLDB * 2 + (row * SLDB + s8) * 2, src);
        }
        CP_COMMIT();
    };

    copyB(0, 0, 0);
    CP_WAIT(0);
    __syncthreads();

    for (int nt = 0; nt < NT; nt++) {
        int col0 = nt * 128;
        float acc[2][8][4];
        #pragma unroll
        for (int mt = 0; mt < 2; mt++)
            #pragma unroll
            for (int n2 = 0; n2 < 8; n2++)
                #pragma unroll
                for (int q = 0; q < 4; q++) acc[mt][n2][q] = 0.f;

        for (int ch = 0; ch < 8; ch++) {
            int stg = ch & 1;
            if (ch + 1 < 8)       copyB(col0, (ch + 1) * KCHB, stg ^ 1);
            else if (nt + 1 < NT) copyB(col0 + 128, 0, stg ^ 1);
            else                  CP_COMMIT();   // keep group parity
            CP_WAIT(1);
            __syncthreads();

            int kk = ch * KCHB;
            uint32_t ah0[4], ah1[4], al0[4], al1[4];
            uint32_t aoff0 = ((m_base + la) * SLDA + ka + kk) * 2;
            uint32_t aoff1 = ((m_base + 16 + la) * SLDA + ka + kk) * 2;
            ldsm4(ah0, uA + aoff0);
            ldsm4(ah1, uA + aoff1);
            ldsm4(al0, uA + 128 * SLDA * 2 + aoff0);
            ldsm4(al1, uA + 128 * SLDA * 2 + aoff1);
            uint32_t bbase = uB + stg * BSTG_B;
            #pragma unroll
            for (int np = 0; np < 4; np++) {
                uint32_t bh[4], bl[4];
                uint32_t boff = ((n_base + np * 16 + lb) * SLDB + kb) * 2;
                ldsm4(bh, bbase + boff);
                ldsm4(bl, bbase + 128 * SLDB * 2 + boff);
                int n0 = 2 * np, n1 = 2 * np + 1;
                mma16816(acc[0][n0], ah0, bh);
                mma16816(acc[0][n0], ah0, bl);
                mma16816(acc[0][n0], al0, bh);
                mma16816(acc[0][n1], ah0, bh + 2);
                mma16816(acc[0][n1], ah0, bl + 2);
                mma16816(acc[0][n1], al0, bh + 2);
                mma16816(acc[1][n0], ah1, bh);
                mma16816(acc[1][n0], ah1, bl);
                mma16816(acc[1][n0], al1, bh);
                mma16816(acc[1][n1], ah1, bh + 2);
                mma16816(acc[1][n1], ah1, bl + 2);
                mma16816(acc[1][n1], al1, bh + 2);
            }
            __syncthreads();
        }
        epilogue_tile(acc, M0, col0, m_base, n_base, g, c,
                      bias, C, Chi, Clo, ldc, res, epi);
    }
}

// ---------------- streaming tensor-core GEMM (ff2, K = 512) -------------------
__global__ void __launch_bounds__(256, 2)
gemm_mma_kernel(const __nv_bfloat16* __restrict__ Ahi,
                const __nv_bfloat16* __restrict__ Alo, int lda, int K,
                const __nv_bfloat16* __restrict__ Whi,
                const __nv_bfloat16* __restrict__ Wlo,
                const float* __restrict__ bias,
                float* __restrict__ C,
                __nv_bfloat16* __restrict__ Chi, __nv_bfloat16* __restrict__ Clo,
                int ldc, const float* __restrict__ res, int epi) {
    extern __shared__ __nv_bfloat16 sm[];
    uint32_t u0 = smem_u32(sm);

    int t    = threadIdx.x;
    int wid  = t >> 5, lane = t & 31;
    int g    = lane >> 2;
    int c    = lane & 3;
    int M0   = blockIdx.x * 128;
    int col0 = blockIdx.y * 128;
    int wm   = wid >> 1, wn = wid & 1;
    int m_base = wm * 32, n_base = wn * 64;

    int la = lane & 15;
    int ka = (lane >> 4) * 8;
    int lb = (lane & 7) + ((lane >> 4) * 8);
    int kb = ((lane >> 3) & 1) * 8;

    float acc[2][8][4];
    #pragma unroll
    for (int mt = 0; mt < 2; mt++)
        #pragma unroll
        for (int nt = 0; nt < 8; nt++)
            #pragma unroll
            for (int q = 0; q < 4; q++) acc[mt][nt][q] = 0.f;

    int nch = K / KCH;
    auto copy_chunk = [&](int kc, int stg) {
        uint32_t sbase = u0 + stg * STAGE_B;
        #pragma unroll
        for (int it = 0; it < 8; it++) {
            int idx  = it * 256 + t;
            int arr  = idx >> 9;
            int row  = (idx >> 2) & 127;
            int seg8 = (idx & 3) * 8;
            const __nv_bfloat16* src;
            if      (arr == 0) src = Ahi + (size_t)(M0 + row) * lda + kc + seg8;
            else if (arr == 1) src = Alo + (size_t)(M0 + row) * lda + kc + seg8;
            else if (arr == 2) src = Whi + (size_t)(col0 + row) * K + kc + seg8;
            else               src = Wlo + (size_t)(col0 + row) * K + kc + seg8;
            cp16(sbase + ((arr * 128 + row) * SLD + seg8) * 2, src);
        }
        CP_COMMIT();
    };

    copy_chunk(0, 0);
    for (int ch = 0; ch < nch; ch++) {
        int cur = ch & 1;
        if (ch + 1 < nch) { copy_chunk((ch + 1) * KCH, cur ^ 1); CP_WAIT(1); }
        else              { CP_WAIT(0); }
        __syncthreads();

        uint32_t base = u0 + cur * STAGE_B;
        #pragma unroll
        for (int kk = 0; kk < KCH; kk += 16) {
            uint32_t ah0[4], ah1[4], al0[4], al1[4];
            uint32_t aoff0 = ((m_base + la) * SLD + ka + kk) * 2;
            uint32_t aoff1 = ((m_base + 16 + la) * SLD + ka + kk) * 2;
            ldsm4(ah0, base + aoff0);
            ldsm4(ah1, base + aoff1);
            ldsm4(al0, base + 128 * SLD * 2 + aoff0);
            ldsm4(al1, base + 128 * SLD * 2 + aoff1);
            #pragma unroll
            for (int np = 0; np < 4; np++) {
                uint32_t bh[4], bl[4];
                uint32_t boff = ((n_base + np * 16 + lb) * SLD + kb + kk) * 2;
                ldsm4(bh, base + 2 * 128 * SLD * 2 + boff);
                ldsm4(bl, base + 3 * 128 * SLD * 2 + boff);
                int n0 = 2 * np, n1 = 2 * np + 1;
                mma16816(acc[0][n0], ah0, bh);
                mma16816(acc[0][n0], ah0, bl);
                mma16816(acc[0][n0], al0, bh);
                mma16816(acc[0][n1], ah0, bh + 2);
                mma16816(acc[0][n1], ah0, bl + 2);
                mma16816(acc[0][n1], al0, bh + 2);
                mma16816(acc[1][n0], ah1, bh);
                mma16816(acc[1][n0], ah1, bl);
                mma16816(acc[1][n0], al1, bh);
                mma16816(acc[1][n1], ah1, bh + 2);
                mma16816(acc[1][n1], ah1, bl + 2);
                mma16816(acc[1][n1], al1, bh + 2);
            }
        }
        __syncthreads();
    }
    epilogue_tile(acc, M0, col0, m_base, n_base, g, c,
                  bias, C, Chi, Clo, ldc, res, epi);
}

// ---------------- LayerNorm: fp32 in -> bf16 split out -----------------------
__global__ void __launch_bounds__(256)
ln_kernel(const float* __restrict__ in,
          __nv_bfloat16* __restrict__ ohi, __nv_bfloat16* __restrict__ olo,
          const float* __restrict__ g, const float* __restrict__ b) {
    int warp = threadIdx.x >> 5, lane = threadIdx.x & 31;
    size_t row = (size_t)blockIdx.x * 8 + warp;
    float4 v = *(const float4*)(in + row * 128 + lane * 4);
    float s  = v.x + v.y + v.z + v.w;
    float ss = v.x * v.x + v.y * v.y + v.z * v.z + v.w * v.w;
    #pragma unroll
    for (int o = 16; o; o >>= 1) {
        s  += __shfl_xor_sync(0xffffffffu, s, o);
        ss += __shfl_xor_sync(0xffffffffu, ss, o);
    }
    float m   = s * (1.0f / 128.0f);
    float var = ss * (1.0f / 128.0f) - m * m;
    float rs  = rsqrtf(var + 1e-5f);
    float4 gg = *(const float4*)(g + lane * 4);
    float4 bb = *(const float4*)(b + lane * 4);
    float o0 = (v.x - m) * rs * gg.x + bb.x;
    float o1 = (v.y - m) * rs * gg.y + bb.y;
    float o2 = (v.z - m) * rs * gg.z + bb.z;
    float o3 = (v.w - m) * rs * gg.w + bb.w;
    __nv_bfloat162 h01, l01, h23, l23;
    split1(o0, h01.x, l01.x); split1(o1, h01.y, l01.y);
    split1(o2, h23.x, l23.x); split1(o3, h23.y, l23.y);
    *(__nv_bfloat162*)(ohi + row * 128 + lane * 4)     = h01;
    *(__nv_bfloat162*)(ohi + row * 128 + lane * 4 + 2) = h23;
    *(__nv_bfloat162*)(olo + row * 128 + lane * 4)     = l01;
    *(__nv_bfloat162*)(olo + row * 128 + lane * 4 + 2) = l23;
}

// ---------------- attention (per node, fp32 in, bf16 split out) -------------
__global__ void __launch_bounds__(256)
attn_kernel() {
    extern __shared__ float s[];
    float* sq  = s;
    float* sk  = s + 32 * ATS;
    float* sv  = s + 64 * ATS;
    float* ssc = s + 96 * ATS;
    int node = blockIdx.x, t = threadIdx.x;
    const float* qg = g_qkv + (size_t)node * 32 * 384;

    for (int i = t; i < 1024; i += 256) {
        int l = i >> 5, c4 = (i & 31) * 4;
        *(float4*)(sq + l * ATS + c4) = *(const float4*)(qg + l * 384 + c4);
        *(float4*)(sk + l * ATS + c4) = *(const float4*)(qg + l * 384 + 128 + c4);
        *(float4*)(sv + l * ATS + c4) = *(const float4*)(qg + l * 384 + 256 + c4);
    }
    __syncthreads();

    {   // scores
        int i = t >> 3, j0 = (t & 7) * 4;
        float acc[4] = {0.f, 0.f, 0.f, 0.f};
        #pragma unroll 4
        for (int d = 0; d < 128; d += 4) {
            float4 q = *(const float4*)(sq + i * ATS + d);
            #pragma unroll
            for (int jj = 0; jj < 4; jj++) {
                float4 k4 = *(const float4*)(sk + (j0 + jj) * ATS + d);
                acc[jj] += q.x * k4.x + q.y * k4.y + q.z * k4.z + q.w * k4.w;
            }
        }
        const float scale = 0.08838834764831845f;
        #pragma unroll
        for (int jj = 0; jj < 4; jj++) ssc[i * 32 + j0 + jj] = acc[jj] * scale;
    }
    __syncthreads();
    {   // softmax
        int warp = t >> 5, lane = t & 31;
        for (int r = warp; r < 32; r += 8) {
            float v = ssc[r * 32 + lane];
            float mx = v;
            #pragma unroll
            for (int o = 16; o; o >>= 1) mx = fmaxf(mx, __shfl_xor_sync(0xffffffffu, mx, o));
            float e = expf(v - mx);
            float sm2 = e;
            #pragma unroll
            for (int o = 16; o; o >>= 1) sm2 += __shfl_xor_sync(0xffffffffu, sm2, o);
            ssc[r * 32 + lane] = e / sm2;
        }
    }
    __syncthreads();
    {   // attn = a @ v -> split bf16; thread owns d = d0 + q*32 + 0..3
        int i = t >> 3, d0 = (t & 7) * 4;
        float acc[4][4];
        #pragma unroll
        for (int q = 0; q < 4; q++)
            #pragma unroll
            for (int e = 0; e < 4; e++) acc[q][e] = 0.f;
        for (int j = 0; j < 32; j++) {
            float a = ssc[i * 32 + j];
            const float* vr = sv + j * ATS + d0;
            #pragma unroll
            for (int q = 0; q < 4; q++) {
                float4 v4 = *(const float4*)(vr + q * 32);
                acc[q][0] += a * v4.x; acc[q][1] += a * v4.y;
                acc[q][2] += a * v4.z; acc[q][3] += a * v4.w;
            }
        }
        size_t base = ((size_t)node * 32 + i) * 128 + d0;
        #pragma unroll
        for (int q = 0; q < 4; q++) {
            __nv_bfloat162 h0, l0, h1, l1;
            split1(acc[q][0], h0.x, l0.x); split1(acc[q][1], h0.y, l0.y);
            split1(acc[q][2], h1.x, l1.x); split1(acc[q][3], h1.y, l1.y);
            *(__nv_bfloat162*)(g_b1hi + base + q * 32)     = h0;
            *(__nv_bfloat162*)(g_b1hi + base + q * 32 + 2) = h1;
            *(__nv_bfloat162*)(g_b1lo + base + q * 32)     = l0;
            *(__nv_bfloat162*)(g_b1lo + base + q * 32 + 2) = l1;
        }
    }
}

// ---------------- a_src/a_dst projections ------------------------------------
__global__ void __launch_bounds__(256)
asad_kernel(const float* __restrict__ att_src, const float* __restrict__ att_dst) {
    int node = blockIdx.x, t = threadIdx.x;
    int warp = t >> 5, lane = t & 31;
    float4 as4 = *(const float4*)(att_src + lane * 4);
    float4 ad4 = *(const float4*)(att_dst + lane * 4);
    for (int r = warp; r < 32; r += 8) {
        float4 h4 = *(const float4*)(g_h + ((size_t)node * 32 + r) * 128 + lane * 4);
        float s = h4.x * as4.x + h4.y * as4.y + h4.z * as4.z + h4.w * as4.w;
        float d = h4.x * ad4.x + h4.y * ad4.y + h4.z * ad4.z + h4.w * ad4.w;
        #pragma unroll
        for (int o = 16; o; o >>= 1) {
            s += __shfl_xor_sync(0xffffffffu, s, o);
            d += __shfl_xor_sync(0xffffffffu, d, o);
        }
        if (lane == 0) {
            g_as[node * 32 + r] = s;
            g_ad[node * 32 + r] = d;
        }
    }
}

// ---------------- edge dtype detection + CSR build ---------------------------
__global__ void zero_counts_kernel() {
    int i = blockIdx.x * blockDim.x + threadIdx.x;
    if (i < K_NODES) { g_cnt[i] = 0; g_cur[i] = 0; }
    if (i == 0) g_is32 = 0;
}
__global__ void detect_dtype_kernel(const int* __restrict__ ei32) {
    int i = blockIdx.x * blockDim.x + threadIdx.x;
    if (i < N_EDGES && ei32[2 * i + 1] != 0) atomicExch(&g_is32, 1);
}
__device__ __forceinline__ int load_idx(const int* __restrict__ ei32, int elem) {
    return g_is32 ? ei32[elem] : ei32[2 * elem];
}
__global__ void count_edges_kernel(const int* __restrict__ ei32) {
    int e = blockIdx.x * blockDim.x + threadIdx.x;
    if (e >= N_TOT_EDGES) return;
    int dst = (e < N_EDGES) ? load_idx(ei32, N_EDGES + e) : (e - N_EDGES);
    if ((unsigned)dst >= K_NODES) return;
    atomicAdd(&g_cnt[dst], 1);
}
__global__ void scan_kernel() {
    __shared__ int ts[1024];
    int t = threadIdx.x;
    int c[4], s = 0;
    #pragma unroll
    for (int i = 0; i < 4; i++) { c[i] = s; s += g_cnt[t * 4 + i]; }
    ts[t] = s;
    __syncthreads();
    for (int o = 1; o < 1024; o <<= 1) {
        int v = (t >= o) ? ts[t - o] : 0;
        __syncthreads();
        ts[t] += v;
        __syncthreads();
    }
    int base = (t == 0) ? 0 : ts[t - 1];
    #pragma unroll
    for (int i = 0; i < 4; i++) g_off[t * 4 + i] = base + c[i];
    if (t == 1023) g_off[4096] = ts[1023];
}
__global__ void fill_edges_kernel(const int* __restrict__ ei32) {
    int e = blockIdx.x * blockDim.x + threadIdx.x;
    if (e >= N_TOT_EDGES) return;
    int src, dst;
    if (e < N_EDGES) {
        src = load_idx(ei32, e);
        dst = load_idx(ei32, N_EDGES + e);
    } else {
        src = dst = e - N_EDGES;
    }
    if ((unsigned)dst >= K_NODES || (unsigned)src >= K_NODES) return;
    int pos = atomicAdd(&g_cur[dst], 1);
    g_csr_src[g_off[dst] + pos] = src;
}

// ---------------- GAT aggregation: one block per dst node --------------------
__global__ void __launch_bounds__(256)
gat_aggregate_kernel(const float* __restrict__ gat_b, float* __restrict__ out) {
    __shared__ float sm_m[32], sm_d[32];
    __shared__ float part[8][32];
    __shared__ float s_alpha[64][33];
    __shared__ int   s_src[64];
    int dst = blockIdx.x, t = threadIdx.x;
    int off0 = g_off[dst], ne = g_cur[dst];

    {   // phase A: per-l max
        int l = t & 31, grp = t >> 5;
        float adl = g_ad[dst * 32 + l];
        float lm = -3.4e38f;
        for (int e = grp; e < ne; e += 8) {
            int src = g_csr_src[off0 + e];
            float v = g_as[src * 32 + l] + adl;
            v = v > 0.f ? v : 0.2f * v;
            lm = fmaxf(lm, v);
        }
        part[grp][l] = lm;
        __syncthreads();
        if (t < 32) {
            float m = part[0][t];
            #pragma unroll
            for (int g2 = 1; g2 < 8; g2++) m = fmaxf(m, part[g2][t]);
            sm_m[t] = m;
        }
        __syncthreads();
    }
    {   // phase B: denom
        int l = t & 31, grp = t >> 5;
        float adl = g_ad[dst * 32 + l];
        float m = sm_m[l], sden = 0.f;
        for (int e = grp; e < ne; e += 8) {
            int src = g_csr_src[off0 + e];
            float v = g_as[src * 32 + l] + adl;
            v = v > 0.f ? v : 0.2f * v;
            sden += expf(v - m);
        }
        __syncthreads();
        part[grp][l] = sden;
        __syncthreads();
        if (t < 32) {
            float s2 = 0.f;
            #pragma unroll
            for (int g2 = 0; g2 < 8; g2++) s2 += part[g2][t];
            sm_d[t] = s2;
        }
        __syncthreads();
    }
    {   // phase C: chunked alpha staging + weighted aggregation
        int l = t >> 3, d0 = (t & 7) * 16;
        float acc[16];
        #pragma unroll
        for (int i = 0; i < 16; i++) acc[i] = 0.f;

        for (int e0 = 0; e0 < ne; e0 += 64) {
            int ecnt = min(64, ne - e0);
            __syncthreads();
            if (t < ecnt) s_src[t] = g_csr_src[off0 + e0 + t];
            __syncthreads();
            for (int idx = t; idx < ecnt * 32; idx += 256) {
                int e = idx >> 5, ll = idx & 31;
                float v = g_as[s_src[e] * 32 + ll] + g_ad[dst * 32 + ll];
                v = v > 0.f ? v : 0.2f * v;
                s_alpha[e][ll] = expf(v - sm_m[ll]);
            }
            __syncthreads();
            for (int e = 0; e < ecnt; e++) {
                float ex = s_alpha[e][l];
                const float4* hp =
                    (const float4*)(g_h + ((size_t)s_src[e] * 32 + l) * 128 + d0);
                #pragma unroll
                for (int q = 0; q < 4; q++) {
                    float4 h4 = hp[q];
                    acc[q * 4 + 0] += ex * h4.x;
                    acc[q * 4 + 1] += ex * h4.y;
                    acc[q * 4 + 2] += ex * h4.z;
                    acc[q * 4 + 3] += ex * h4.w;
                }
            }
        }

        float inv = 1.f / (sm_d[l] + 1e-16f);
        float* op = out + ((size_t)dst * 32 + l) * 128 + d0;
        #pragma unroll
        for (int q = 0; q < 4; q++) {
            float4 o4;
            o4.x = acc[q * 4 + 0] * inv + gat_b[d0 + q * 4 + 0];
            o4.y = acc[q * 4 + 1] * inv + gat_b[d0 + q * 4 + 1];
            o4.z = acc[q * 4 + 2] * inv + gat_b[d0 + q * 4 + 2];
            o4.w = acc[q * 4 + 3] * inv + gat_b[d0 + q * 4 + 3];
            ((float4*)op)[q] = o4;
        }
    }
}

// ---------------- launch ------------------------------------------------------
extern "C" void kernel_launch(void* const* d_in, const int* in_sizes, int n_in,
                              void* d_out, int out_size) {
    const float* x     = (const float*)d_in[0];
    const int*   ei32  = (const int*)d_in[1];
    const float* ln1_g = (const float*)d_in[2];
    const float* ln1_b = (const float*)d_in[3];
    const float* qkv_w = (const float*)d_in[4];
    const float* qkv_b = (const float*)d_in[5];
    const float* out_w = (const float*)d_in[6];
    const float* out_b = (const float*)d_in[7];
    const float* ln2_g = (const float*)d_in[8];
    const float* ln2_b = (const float*)d_in[9];
    const float* ff1_w = (const float*)d_in[10];
    const float* ff1_b = (const float*)d_in[11];
    const float* ff2_w = (const float*)d_in[12];
    const float* ff2_b = (const float*)d_in[13];
    const float* gat_w = (const float*)d_in[14];
    const float* att_s = (const float*)d_in[15];
    const float* att_d = (const float*)d_in[16];
    const float* gat_b = (const float*)d_in[17];
    float* out = (float*)d_out;

    float *p_qkv, *p_x2, *p_h;
    __nv_bfloat16 *p_b1hi, *p_b1lo, *p_b2hi, *p_b2lo, *p_whi, *p_wlo;
    cudaGetSymbolAddress((void**)&p_qkv,  g_qkv);
    cudaGetSymbolAddress((void**)&p_x2,   g_x2);
    cudaGetSymbolAddress((void**)&p_h,    g_h);
    cudaGetSymbolAddress((void**)&p_b1hi, g_b1hi);
    cudaGetSymbolAddress((void**)&p_b1lo, g_b1lo);
    cudaGetSymbolAddress((void**)&p_b2hi, g_b2hi);
    cudaGetSymbolAddress((void**)&p_b2lo, g_b2lo);
    cudaGetSymbolAddress((void**)&p_whi,  g_whi);
    cudaGetSymbolAddress((void**)&p_wlo,  g_wlo);

    const int GEMM_SMEM = 2 * STAGE_B;         // 81920 B (ff2)
    const int ATTN_SMEM = (96 * ATS + 1024) * 4;
    cudaFuncSetAttribute(gemm_mma_kernel,
                         cudaFuncAttributeMaxDynamicSharedMemorySize, GEMM_SMEM);
    cudaFuncSetAttribute(gemm_ares_kernel,
                         cudaFuncAttributeMaxDynamicSharedMemorySize, ARES_SMEM);
    cudaFuncSetAttribute(attn_kernel,
                         cudaFuncAttributeMaxDynamicSharedMemorySize, ATTN_SMEM);

    // 1. weight splits
    split_w_kernel<<<(W_TOTAL + 255) / 256, 256>>>(qkv_w, out_w, ff1_w, ff2_w, gat_w);
    // 2. LN1 -> b1 split
    ln_kernel<<<MM / 8, 256>>>(x, p_b1hi, p_b1lo, ln1_g, ln1_b);
    // 3. CSR zero
    zero_counts_kernel<<<(K_NODES + 255) / 256, 256>>>();
    // 4. qkv GEMM (A-resident, NT=3)  (ncu slot)
    gemm_ares_kernel<<<MM / 128, 256, ARES_SMEM>>>(
        p_b1hi, p_b1lo, p_whi + WOFF_QKV, p_wlo + WOFF_QKV, 128,
        qkv_b, p_qkv, nullptr, nullptr, 384, nullptr, 0, 3);
    // 5-6. CSR detect/count
    detect_dtype_kernel<<<(N_EDGES + 255) / 256, 256>>>(ei32);
    count_edges_kernel<<<(N_TOT_EDGES + 255) / 256, 256>>>(ei32);
    // 7. attention -> b1 split
    attn_kernel<<<K_NODES, 256, ATTN_SMEM>>>();
    // 8. out-proj + residual -> x2 (fp32)
    gemm_ares_kernel<<<MM / 128, 256, ARES_SMEM>>>(
        p_b1hi, p_b1lo, p_whi + WOFF_OUT, p_wlo + WOFF_OUT, 128,
        out_b, p_x2, nullptr, nullptr, 128, x, 2, 1);
    // 9. CSR scan
    scan_kernel<<<1, 1024>>>();
    // 10. LN2 -> b1 split
    ln_kernel<<<MM / 8, 256>>>(p_x2, p_b1hi, p_b1lo, ln2_g, ln2_b);
    // 11. ff1 + gelu -> b2 split (NT=4)
    gemm_ares_kernel<<<MM / 128, 256, ARES_SMEM>>>(
        p_b1hi, p_b1lo, p_whi + WOFF_FF1, p_wlo + WOFF_FF1, 128,
        ff1_b, nullptr, p_b2hi, p_b2lo, 512, nullptr, 1, 4);
    // 12. ff2 + residual -> xt (b1 split), K=512 streaming kernel
    gemm_mma_kernel<<<dim3(MM / 128, 1), 256, GEMM_SMEM>>>(
        p_b2hi, p_b2lo, 512, 512, p_whi + WOFF_FF2, p_wlo + WOFF_FF2,
        ff2_b, nullptr, p_b1hi, p_b1lo, 128, p_x2, 4);
    // 13. GAT transform -> h (fp32)
    gemm_ares_kernel<<<MM / 128, 256, ARES_SMEM>>>(
        p_b1hi, p_b1lo, p_whi + WOFF_GAT, p_wlo + WOFF_GAT, 128,
        nullptr, p_h, nullptr, nullptr, 128, nullptr, 3, 1);
    // 14. CSR fill
    fill_edges_kernel<<<(N_TOT_EDGES + 255) / 256, 256>>>(ei32);
    // 15. attention coefficients
    asad_kernel<<<K_NODES, 256>>>(att_s, att_d);
    // 16. aggregate
    gat_aggregate_kernel<<<K_NODES, 256>>>(gat_b, out);
}

// round 13
// speedup vs baseline: 3.7810x; 1.0137x over previous
#include <cuda_runtime.h>
#include <cuda_bf16.h>
#include <cstdint>
#include <math.h>

#define K_NODES 4096
#define SEQ_L   32
#define D_MODEL 128
#define D_FF    512
#define N_EDGES 65536
#define N_TOT_EDGES (N_EDGES + K_NODES)
#define MM (K_NODES * SEQ_L)           // 131072 rows

// streaming GEMM (ff2) params
#define KCH  32
#define SLD  40
#define STAGE_B (4 * 128 * SLD * 2)     // 40960 B

// A-resident GEMM params
#define SLDA 136                        // A row stride (128 + 8), conflict-free
#define KCHB 16                         // B chunk k
#define SLDB 24                         // B row stride (16 + 8), conflict-free
#define A_BYTES (2 * 128 * SLDA * 2)    // 69632
#define BSTG_B  (2 * 128 * SLDB * 2)    // 12288 per stage
#define ARES_SMEM (A_BYTES + 3 * BSTG_B)  // 106496 (3-stage)

// attn smem stride
#define ATS 132

// weight segment offsets in the packed split buffer
#define WOFF_QKV 0
#define WOFF_OUT 49152
#define WOFF_FF1 65536
#define WOFF_FF2 131072
#define WOFF_GAT 196608
#define W_TOTAL  212992

// ---------------- scratch (static; no runtime alloc) -------------------------
__device__ __nv_bfloat16 g_b1hi[MM * 128], g_b1lo[MM * 128];
__device__ __nv_bfloat16 g_b2hi[MM * 512], g_b2lo[MM * 512];
__device__ __nv_bfloat16 g_whi[W_TOTAL],  g_wlo[W_TOTAL];
__device__ float g_qkv[MM * 384];
__device__ float g_x2 [MM * 128];
__device__ float g_h  [MM * 128];
__device__ float g_as[K_NODES * SEQ_L];
__device__ float g_ad[K_NODES * SEQ_L];
__device__ int   g_cnt[K_NODES];
__device__ int   g_cur[K_NODES];
__device__ int   g_off[K_NODES + 1];
__device__ int   g_csr_src[N_TOT_EDGES];
__device__ int   g_is32;

__device__ __forceinline__ float gelu_exact(float v) {
    return 0.5f * v * (1.0f + erff(v * 0.70710678118654752f));
}

__device__ __forceinline__ uint32_t smem_u32(const void* p) {
    uint32_t a;
    asm("{ .reg .u64 t; cvta.to.shared.u64 t, %1; cvt.u32.u64 %0, t; }"
        : "=r"(a) : "l"(p));
    return a;
}

__device__ __forceinline__ void cp16(uint32_t dst, const void* src) {
    asm volatile("cp.async.cg.shared.global [%0], [%1], 16;"
                 :: "r"(dst), "l"(src));
}
#define CP_COMMIT() asm volatile("cp.async.commit_group;" ::: "memory")
#define CP_WAIT(n)  asm volatile("cp.async.wait_group %0;" :: "n"(n) : "memory")

__device__ __forceinline__ void mma16816(float* d,
                                         const uint32_t* a, const uint32_t* b) {
    asm volatile(
        "mma.sync.aligned.m16n8k16.row.col.f32.bf16.bf16.f32 "
        "{%0,%1,%2,%3}, {%4,%5,%6,%7}, {%8,%9}, {%0,%1,%2,%3};"
        : "+f"(d[0]), "+f"(d[1]), "+f"(d[2]), "+f"(d[3])
        : "r"(a[0]), "r"(a[1]), "r"(a[2]), "r"(a[3]), "r"(b[0]), "r"(b[1]));
}

__device__ __forceinline__ void ldsm4(uint32_t* r, uint32_t addr) {
    asm volatile("ldmatrix.sync.aligned.m8n8.x4.shared.b16 {%0,%1,%2,%3}, [%4];"
        : "=r"(r[0]), "=r"(r[1]), "=r"(r[2]), "=r"(r[3]) : "r"(addr));
}

__device__ __forceinline__ void split1(float v, __nv_bfloat16& h, __nv_bfloat16& l) {
    h = __float2bfloat16(v);
    l = __float2bfloat16(v - __bfloat162float(h));
}

// generic epilogue (epi 0..4)
__device__ __forceinline__ void epilogue_tile(
    float acc[2][8][4], int M0, int col0, int m_base, int n_base, int g, int c,
    const float* bias, float* C, __nv_bfloat16* Chi, __nv_bfloat16* Clo,
    int ldc, const float* res, int epi) {
    #pragma unroll
    for (int mt = 0; mt < 2; mt++) {
        int row0 = M0 + m_base + mt * 16 + g;
        #pragma unroll
        for (int nt = 0; nt < 8; nt++) {
            int col = col0 + n_base + nt * 8 + 2 * c;
            float b0 = 0.f, b1 = 0.f;
            if (epi != 3) { b0 = bias[col]; b1 = bias[col + 1]; }
            float v00 = acc[mt][nt][0] + b0, v01 = acc[mt][nt][1] + b1;
            float v10 = acc[mt][nt][2] + b0, v11 = acc[mt][nt][3] + b1;
            if (epi == 1) {
                v00 = gelu_exact(v00); v01 = gelu_exact(v01);
                v10 = gelu_exact(v10); v11 = gelu_exact(v11);
            } else if (epi == 2 || epi == 4) {
                float2 ra = *(const float2*)(res + (size_t)row0 * 128 + col);
                float2 rb = *(const float2*)(res + (size_t)(row0 + 8) * 128 + col);
                v00 += ra.x; v01 += ra.y; v10 += rb.x; v11 += rb.y;
            }
            if (epi == 1 || epi == 4) {
                __nv_bfloat162 h0, l0, h1, l1;
                split1(v00, h0.x, l0.x); split1(v01, h0.y, l0.y);
                split1(v10, h1.x, l1.x); split1(v11, h1.y, l1.y);
                *(__nv_bfloat162*)(Chi + (size_t)row0 * ldc + col)       = h0;
                *(__nv_bfloat162*)(Clo + (size_t)row0 * ldc + col)       = l0;
                *(__nv_bfloat162*)(Chi + (size_t)(row0 + 8) * ldc + col) = h1;
                *(__nv_bfloat162*)(Clo + (size_t)(row0 + 8) * ldc + col) = l1;
            } else {
                float2 o0 = {v00, v01}, o1 = {v10, v11};
                *(float2*)(C + (size_t)row0 * ldc + col)       = o0;
                *(float2*)(C + (size_t)(row0 + 8) * ldc + col) = o1;
            }
        }
    }
}

// ---------------- weight split ------------------------------------------------
__global__ void split_w_kernel(const float* __restrict__ w0, const float* __restrict__ w1,
                               const float* __restrict__ w2, const float* __restrict__ w3,
                               const float* __restrict__ w4) {
    int i = blockIdx.x * 256 + threadIdx.x;
    if (i >= W_TOTAL) return;
    const float* src; int off;
    if      (i < WOFF_OUT) { src = w0; off = WOFF_QKV; }
    else if (i < WOFF_FF1) { src = w1; off = WOFF_OUT; }
    else if (i < WOFF_FF2) { src = w2; off = WOFF_FF1; }
    else if (i < WOFF_GAT) { src = w3; off = WOFF_FF2; }
    else                   { src = w4; off = WOFF_GAT; }
    float v = src[i - off];
    __nv_bfloat16 h, l;
    split1(v, h, l);
    g_whi[i] = h; g_wlo[i] = l;
}

// ---------------- A-resident tensor-core GEMM (K = 128) ----------------------
// A (hi+lo) cached fully in smem; NT N-tiles, B in a 3-stage cp.async ring,
// ONE __syncthreads per chunk. Warp grid 4(M)x2(N). 3-term bf16 split.
// epi: 0=+bias fp32; 1=+bias,gelu->split; 2=+bias,+res fp32; 3=none fp32;
//      4=+bias,+res->split; 5=+bias,+res fp32 C AND LN->split (Chi/Clo);
//      6=none fp32 C AND row-dots with av_s/av_d -> as_out/ad_out.
__global__ void __launch_bounds__(256, 2)
gemm_ares_kernel(const __nv_bfloat16* __restrict__ Ahi,
                 const __nv_bfloat16* __restrict__ Alo,
                 const __nv_bfloat16* __restrict__ Whi,
                 const __nv_bfloat16* __restrict__ Wlo, int Kw,
                 const float* __restrict__ bias,
                 float* __restrict__ C,
                 __nv_bfloat16* __restrict__ Chi, __nv_bfloat16* __restrict__ Clo,
                 int ldc, const float* __restrict__ res, int epi, int NT,
                 const float* __restrict__ lng, const float* __restrict__ lnb,
                 const float* __restrict__ av_s, const float* __restrict__ av_d,
                 float* __restrict__ as_out, float* __restrict__ ad_out) {
    extern __shared__ __nv_bfloat16 sm[];
    __shared__ float sred[4][128];
    uint32_t uA = smem_u32(sm);
    uint32_t uB = uA + A_BYTES;

    int t    = threadIdx.x;
    int wid  = t >> 5, lane = t & 31;
    int g    = lane >> 2;
    int c    = lane & 3;
    int M0   = blockIdx.x * 128;
    int wm   = wid >> 1, wn = wid & 1;
    int m_base = wm * 32, n_base = wn * 64;

    int la = lane & 15;
    int ka = (lane >> 4) * 8;
    int lb = (lane & 7) + ((lane >> 4) * 8);
    int kb = ((lane >> 3) & 1) * 8;

    // ---- load A (hi+lo, full 128x128): 4096 16B segments
    #pragma unroll
    for (int it = 0; it < 16; it++) {
        int idx  = it * 256 + t;
        int arr  = idx >> 11;
        int row  = (idx >> 4) & 127;
        int s8   = (idx & 15) * 8;
        const __nv_bfloat16* src =
            (arr ? Alo : Ahi) + (size_t)(M0 + row) * 128 + s8;
        cp16(uA + arr * 128 * SLDA * 2 + (row * SLDA + s8) * 2, src);
    }
    CP_COMMIT();

    auto copyB = [&](int ci, int stg) {
        int col0 = (ci >> 3) * 128;
        int kc   = (ci & 7) * KCHB;
        uint32_t base = uB + stg * BSTG_B;
        #pragma unroll
        for (int it = 0; it < 2; it++) {
            int idx = it * 256 + t;
            int arr = idx >> 8;
            int row = (idx >> 1) & 127;
            int s8  = (idx & 1) * 8;
            const __nv_bfloat16* src =
                (arr ? Wlo : Whi) + (size_t)(col0 + row) * Kw + kc + s8;
            cp16(base + arr * 128 * SLDB * 2 + (row * SLDB + s8) * 2, src);
        }
        CP_COMMIT();
    };

    int total = NT * 8;
    copyB(0, 0);
    if (total > 1) copyB(1, 1);
    else           CP_COMMIT();           // empty group keeps wait(1) exact
    CP_WAIT(1);                            // A + chunk0 ready
    __syncthreads();

    float acc[2][8][4];
    for (int ci = 0; ci < total; ci++) {
        int stg = ci % 3;
        if (ci > 0) { CP_WAIT(1); __syncthreads(); }
        if (ci + 2 < total) copyB(ci + 2, (ci + 2) % 3);
        else                CP_COMMIT();  // empty group per iteration

        if ((ci & 7) == 0) {
            #pragma unroll
            for (int mt = 0; mt < 2; mt++)
                #pragma unroll
                for (int n2 = 0; n2 < 8; n2++)
                    #pragma unroll
                    for (int q = 0; q < 4; q++) acc[mt][n2][q] = 0.f;
        }

        int kk = (ci & 7) * KCHB;
        uint32_t ah0[4], ah1[4], al0[4], al1[4];
        uint32_t aoff0 = ((m_base + la) * SLDA + ka + kk) * 2;
        uint32_t aoff1 = ((m_base + 16 + la) * SLDA + ka + kk) * 2;
        ldsm4(ah0, uA + aoff0);
        ldsm4(ah1, uA + aoff1);
        ldsm4(al0, uA + 128 * SLDA * 2 + aoff0);
        ldsm4(al1, uA + 128 * SLDA * 2 + aoff1);
        uint32_t bbase = uB + stg * BSTG_B;
        #pragma unroll
        for (int np = 0; np < 4; np++) {
            uint32_t bh[4], bl[4];
            uint32_t boff = ((n_base + np * 16 + lb) * SLDB + kb) * 2;
            ldsm4(bh, bbase + boff);
            ldsm4(bl, bbase + 128 * SLDB * 2 + boff);
            int n0 = 2 * np, n1 = 2 * np + 1;
            mma16816(acc[0][n0], ah0, bh);
            mma16816(acc[0][n0], ah0, bl);
            mma16816(acc[0][n0], al0, bh);
            mma16816(acc[0][n1], ah0, bh + 2);
            mma16816(acc[0][n1], ah0, bl + 2);
            mma16816(acc[0][n1], al0, bh + 2);
            mma16816(acc[1][n0], ah1, bh);
            mma16816(acc[1][n0], ah1, bl);
            mma16816(acc[1][n0], al1, bh);
            mma16816(acc[1][n1], ah1, bh + 2);
            mma16816(acc[1][n1], ah1, bl + 2);
            mma16816(acc[1][n1], al1, bh + 2);
        }

        if ((ci & 7) == 7) {
            int col0 = (ci >> 3) * 128;
            if (epi == 5 || epi == 6) {
                // fused epilogue: store fp32 C; row reductions
                float s0[2][2] = {{0.f,0.f},{0.f,0.f}};
                float s1[2][2] = {{0.f,0.f},{0.f,0.f}};
                #pragma unroll
                for (int mt = 0; mt < 2; mt++) {
                    int row0 = M0 + m_base + mt * 16 + g;
                    #pragma unroll
                    for (int n2 = 0; n2 < 8; n2++) {
                        int col = col0 + n_base + n2 * 8 + 2 * c;
                        float b0 = 0.f, b1 = 0.f;
                        if (epi == 5) { b0 = bias[col]; b1 = bias[col + 1]; }
                        float v00 = acc[mt][n2][0] + b0, v01 = acc[mt][n2][1] + b1;
                        float v10 = acc[mt][n2][2] + b0, v11 = acc[mt][n2][3] + b1;
                        if (epi == 5) {
                            float2 ra = *(const float2*)(res + (size_t)row0 * 128 + col);
                            float2 rb = *(const float2*)(res + (size_t)(row0 + 8) * 128 + col);
                            v00 += ra.x; v01 += ra.y; v10 += rb.x; v11 += rb.y;
                        }
                        acc[mt][n2][0] = v00; acc[mt][n2][1] = v01;
                        acc[mt][n2][2] = v10; acc[mt][n2][3] = v11;
                        float2 o0 = {v00, v01}, o1 = {v10, v11};
                        *(float2*)(C + (size_t)row0 * ldc + col)       = o0;
                        *(float2*)(C + (size_t)(row0 + 8) * ldc + col) = o1;
                        if (epi == 5) {
                            s0[mt][0] += v00 + v01; s1[mt][0] += v00 * v00 + v01 * v01;
                            s0[mt][1] += v10 + v11; s1[mt][1] += v10 * v10 + v11 * v11;
                        } else {
                            float as0 = av_s[col], as1 = av_s[col + 1];
                            float ad0 = av_d[col], ad1 = av_d[col + 1];
                            s0[mt][0] += v00 * as0 + v01 * as1;
                            s1[mt][0] += v00 * ad0 + v01 * ad1;
                            s0[mt][1] += v10 * as0 + v11 * as1;
                            s1[mt][1] += v10 * ad0 + v11 * ad1;
                        }
                    }
                }
                #pragma unroll
                for (int off = 1; off <= 2; off <<= 1) {
                    #pragma unroll
                    for (int mt = 0; mt < 2; mt++)
                        #pragma unroll
                        for (int h2 = 0; h2 < 2; h2++) {
                            s0[mt][h2] += __shfl_xor_sync(0xffffffffu, s0[mt][h2], off);
                            s1[mt][h2] += __shfl_xor_sync(0xffffffffu, s1[mt][h2], off);
                        }
                }
                if (c == 0) {
                    #pragma unroll
                    for (int mt = 0; mt < 2; mt++)
                        #pragma unroll
                        for (int h2 = 0; h2 < 2; h2++) {
                            int r = m_base + mt * 16 + g + 8 * h2;
                            sred[wn * 2][r]     = s0[mt][h2];
                            sred[wn * 2 + 1][r] = s1[mt][h2];
                        }
                }
                __syncthreads();
                if (epi == 5) {
                    float mean_[2][2], rs_[2][2];
                    #pragma unroll
                    for (int mt = 0; mt < 2; mt++)
                        #pragma unroll
                        for (int h2 = 0; h2 < 2; h2++) {
                            int r = m_base + mt * 16 + g + 8 * h2;
                            float S = sred[0][r] + sred[2][r];
                            float Q = sred[1][r] + sred[3][r];
                            float m = S * (1.0f / 128.0f);
                            float var = Q * (1.0f / 128.0f) - m * m;
                            mean_[mt][h2] = m;
                            rs_[mt][h2]   = rsqrtf(var + 1e-5f);
                        }
                    #pragma unroll
                    for (int mt = 0; mt < 2; mt++) {
                        int row0 = M0 + m_base + mt * 16 + g;
                        #pragma unroll
                        for (int n2 = 0; n2 < 8; n2++) {
                            int col = col0 + n_base + n2 * 8 + 2 * c;
                            float g0 = lng[col], g1 = lng[col + 1];
                            float be0 = lnb[col], be1 = lnb[col + 1];
                            float l00 = (acc[mt][n2][0] - mean_[mt][0]) * rs_[mt][0] * g0 + be0;
                            float l01 = (acc[mt][n2][1] - mean_[mt][0]) * rs_[mt][0] * g1 + be1;
                            float l10 = (acc[mt][n2][2] - mean_[mt][1]) * rs_[mt][1] * g0 + be0;
                            float l11 = (acc[mt][n2][3] - mean_[mt][1]) * rs_[mt][1] * g1 + be1;
                            __nv_bfloat162 h0, lo0, h1, lo1;
                            split1(l00, h0.x, lo0.x); split1(l01, h0.y, lo0.y);
                            split1(l10, h1.x, lo1.x); split1(l11, h1.y, lo1.y);
                            *(__nv_bfloat162*)(Chi + (size_t)row0 * 128 + col)       = h0;
                            *(__nv_bfloat162*)(Clo + (size_t)row0 * 128 + col)       = lo0;
                            *(__nv_bfloat162*)(Chi + (size_t)(row0 + 8) * 128 + col) = h1;
                            *(__nv_bfloat162*)(Clo + (size_t)(row0 + 8) * 128 + col) = lo1;
                        }
                    }
                } else {
                    if (wn == 0 && c == 0) {
                        #pragma unroll
                        for (int mt = 0; mt < 2; mt++)
                            #pragma unroll
                            for (int h2 = 0; h2 < 2; h2++) {
                                int r = m_base + mt * 16 + g + 8 * h2;
                                as_out[M0 + r] = sred[0][r] + sred[2][r];
                                ad_out[M0 + r] = sred[1][r] + sred[3][r];
                            }
                    }
                }
                __syncthreads();
            } else {
                epilogue_tile(acc, M0, col0, m_base, n_base, g, c,
                              bias, C, Chi, Clo, ldc, res, epi);
            }
        }
    }
}

// ---------------- streaming tensor-core GEMM (ff2, K = 512) -------------------
__global__ void __launch_bounds__(256, 2)
gemm_mma_kernel(const __nv_bfloat16* __restrict__ Ahi,
                const __nv_bfloat16* __restrict__ Alo, int lda, int K,
                const __nv_bfloat16* __restrict__ Whi,
                const __nv_bfloat16* __restrict__ Wlo,
                const float* __restrict__ bias,
                float* __restrict__ C,
                __nv_bfloat16* __restrict__ Chi, __nv_bfloat16* __restrict__ Clo,
                int ldc, const float* __restrict__ res, int epi) {
    extern __shared__ __nv_bfloat16 sm[];
    uint32_t u0 = smem_u32(sm);

    int t    = threadIdx.x;
    int wid  = t >> 5, lane = t & 31;
    int g    = lane >> 2;
    int c    = lane & 3;
    int M0   = blockIdx.x * 128;
    int col0 = blockIdx.y * 128;
    int wm   = wid >> 1, wn = wid & 1;
    int m_base = wm * 32, n_base = wn * 64;

    int la = lane & 15;
    int ka = (lane >> 4) * 8;
    int lb = (lane & 7) + ((lane >> 4) * 8);
    int kb = ((lane >> 3) & 1) * 8;

    float acc[2][8][4];
    #pragma unroll
    for (int mt = 0; mt < 2; mt++)
        #pragma unroll
        for (int nt = 0; nt < 8; nt++)
            #pragma unroll
            for (int q = 0; q < 4; q++) acc[mt][nt][q] = 0.f;

    int nch = K / KCH;
    auto copy_chunk = [&](int kc, int stg) {
        uint32_t sbase = u0 + stg * STAGE_B;
        #pragma unroll
        for (int it = 0; it < 8; it++) {
            int idx  = it * 256 + t;
            int arr  = idx >> 9;
            int row  = (idx >> 2) & 127;
            int seg8 = (idx & 3) * 8;
            const __nv_bfloat16* src;
            if      (arr == 0) src = Ahi + (size_t)(M0 + row) * lda + kc + seg8;
            else if (arr == 1) src = Alo + (size_t)(M0 + row) * lda + kc + seg8;
            else if (arr == 2) src = Whi + (size_t)(col0 + row) * K + kc + seg8;
            else               src = Wlo + (size_t)(col0 + row) * K + kc + seg8;
            cp16(sbase + ((arr * 128 + row) * SLD + seg8) * 2, src);
        }
        CP_COMMIT();
    };

    copy_chunk(0, 0);
    for (int ch = 0; ch < nch; ch++) {
        int cur = ch & 1;
        if (ch + 1 < nch) { copy_chunk((ch + 1) * KCH, cur ^ 1); CP_WAIT(1); }
        else              { CP_WAIT(0); }
        __syncthreads();

        uint32_t base = u0 + cur * STAGE_B;
        #pragma unroll
        for (int kk = 0; kk < KCH; kk += 16) {
            uint32_t ah0[4], ah1[4], al0[4], al1[4];
            uint32_t aoff0 = ((m_base + la) * SLD + ka + kk) * 2;
            uint32_t aoff1 = ((m_base + 16 + la) * SLD + ka + kk) * 2;
            ldsm4(ah0, base + aoff0);
            ldsm4(ah1, base + aoff1);
            ldsm4(al0, base + 128 * SLD * 2 + aoff0);
            ldsm4(al1, base + 128 * SLD * 2 + aoff1);
            #pragma unroll
            for (int np = 0; np < 4; np++) {
                uint32_t bh[4], bl[4];
                uint32_t boff = ((n_base + np * 16 + lb) * SLD + kb + kk) * 2;
                ldsm4(bh, base + 2 * 128 * SLD * 2 + boff);
                ldsm4(bl, base + 3 * 128 * SLD * 2 + boff);
                int n0 = 2 * np, n1 = 2 * np + 1;
                mma16816(acc[0][n0], ah0, bh);
                mma16816(acc[0][n0], ah0, bl);
                mma16816(acc[0][n0], al0, bh);
                mma16816(acc[0][n1], ah0, bh + 2);
                mma16816(acc[0][n1], ah0, bl + 2);
                mma16816(acc[0][n1], al0, bh + 2);
                mma16816(acc[1][n0], ah1, bh);
                mma16816(acc[1][n0], ah1, bl);
                mma16816(acc[1][n0], al1, bh);
                mma16816(acc[1][n1], ah1, bh + 2);
                mma16816(acc[1][n1], ah1, bl + 2);
                mma16816(acc[1][n1], al1, bh + 2);
            }
        }
        __syncthreads();
    }
    epilogue_tile(acc, M0, col0, m_base, n_base, g, c,
                  bias, C, Chi, Clo, ldc, res, epi);
}

// ---------------- LayerNorm: fp32 in -> bf16 split out (LN1 only) ------------
__global__ void __launch_bounds__(256)
ln_kernel(const float* __restrict__ in,
          __nv_bfloat16* __restrict__ ohi, __nv_bfloat16* __restrict__ olo,
          const float* __restrict__ g, const float* __restrict__ b) {
    int warp = threadIdx.x >> 5, lane = threadIdx.x & 31;
    size_t row = (size_t)blockIdx.x * 8 + warp;
    float4 v = *(const float4*)(in + row * 128 + lane * 4);
    float s  = v.x + v.y + v.z + v.w;
    float ss = v.x * v.x + v.y * v.y + v.z * v.z + v.w * v.w;
    #pragma unroll
    for (int o = 16; o; o >>= 1) {
        s  += __shfl_xor_sync(0xffffffffu, s, o);
        ss += __shfl_xor_sync(0xffffffffu, ss, o);
    }
    float m   = s * (1.0f / 128.0f);
    float var = ss * (1.0f / 128.0f) - m * m;
    float rs  = rsqrtf(var + 1e-5f);
    float4 gg = *(const float4*)(g + lane * 4);
    float4 bb = *(const float4*)(b + lane * 4);
    float o0 = (v.x - m) * rs * gg.x + bb.x;
    float o1 = (v.y - m) * rs * gg.y + bb.y;
    float o2 = (v.z - m) * rs * gg.z + bb.z;
    float o3 = (v.w - m) * rs * gg.w + bb.w;
    __nv_bfloat162 h01, l01, h23, l23;
    split1(o0, h01.x, l01.x); split1(o1, h01.y, l01.y);
    split1(o2, h23.x, l23.x); split1(o3, h23.y, l23.y);
    *(__nv_bfloat162*)(ohi + row * 128 + lane * 4)     = h01;
    *(__nv_bfloat162*)(ohi + row * 128 + lane * 4 + 2) = h23;
    *(__nv_bfloat162*)(olo + row * 128 + lane * 4)     = l01;
    *(__nv_bfloat162*)(olo + row * 128 + lane * 4 + 2) = l23;
}

// ---------------- attention (per node, fp32 in, bf16 split out) -------------
__global__ void __launch_bounds__(256)
attn_kernel() {
    extern __shared__ float s[];
    float* sq  = s;
    float* sk  = s + 32 * ATS;
    float* sv  = s + 64 * ATS;
    float* ssc = s + 96 * ATS;
    int node = blockIdx.x, t = threadIdx.x;
    const float* qg = g_qkv + (size_t)node * 32 * 384;

    for (int i = t; i < 1024; i += 256) {
        int l = i >> 5, c4 = (i & 31) * 4;
        *(float4*)(sq + l * ATS + c4) = *(const float4*)(qg + l * 384 + c4);
        *(float4*)(sk + l * ATS + c4) = *(const float4*)(qg + l * 384 + 128 + c4);
        *(float4*)(sv + l * ATS + c4) = *(const float4*)(qg + l * 384 + 256 + c4);
    }
    __syncthreads();

    {   // scores
        int i = t >> 3, j0 = (t & 7) * 4;
        float acc[4] = {0.f, 0.f, 0.f, 0.f};
        #pragma unroll 4
        for (int d = 0; d < 128; d += 4) {
            float4 q = *(const float4*)(sq + i * ATS + d);
            #pragma unroll
            for (int jj = 0; jj < 4; jj++) {
                float4 k4 = *(const float4*)(sk + (j0 + jj) * ATS + d);
                acc[jj] += q.x * k4.x + q.y * k4.y + q.z * k4.z + q.w * k4.w;
            }
        }
        const float scale = 0.08838834764831845f;
        #pragma unroll
        for (int jj = 0; jj < 4; jj++) ssc[i * 32 + j0 + jj] = acc[jj] * scale;
    }
    __syncthreads();
    {   // softmax
        int warp = t >> 5, lane = t & 31;
        for (int r = warp; r < 32; r += 8) {
            float v = ssc[r * 32 + lane];
            float mx = v;
            #pragma unroll
            for (int o = 16; o; o >>= 1) mx = fmaxf(mx, __shfl_xor_sync(0xffffffffu, mx, o));
            float e = expf(v - mx);
            float sm2 = e;
            #pragma unroll
            for (int o = 16; o; o >>= 1) sm2 += __shfl_xor_sync(0xffffffffu, sm2, o);
            ssc[r * 32 + lane] = e / sm2;
        }
    }
    __syncthreads();
    {   // attn = a @ v -> split bf16
        int i = t >> 3, d0 = (t & 7) * 4;
        float acc[4][4];
        #pragma unroll
        for (int q = 0; q < 4; q++)
            #pragma unroll
            for (int e = 0; e < 4; e++) acc[q][e] = 0.f;
        for (int j = 0; j < 32; j++) {
            float a = ssc[i * 32 + j];
            const float* vr = sv + j * ATS + d0;
            #pragma unroll
            for (int q = 0; q < 4; q++) {
                float4 v4 = *(const float4*)(vr + q * 32);
                acc[q][0] += a * v4.x; acc[q][1] += a * v4.y;
                acc[q][2] += a * v4.z; acc[q][3] += a * v4.w;
            }
        }
        size_t base = ((size_t)node * 32 + i) * 128 + d0;
        #pragma unroll
        for (int q = 0; q < 4; q++) {
            __nv_bfloat162 h0, l0, h1, l1;
            split1(acc[q][0], h0.x, l0.x); split1(acc[q][1], h0.y, l0.y);
            split1(acc[q][2], h1.x, l1.x); split1(acc[q][3], h1.y, l1.y);
            *(__nv_bfloat162*)(g_b1hi + base + q * 32)     = h0;
            *(__nv_bfloat162*)(g_b1hi + base + q * 32 + 2) = h1;
            *(__nv_bfloat162*)(g_b1lo + base + q * 32)     = l0;
            *(__nv_bfloat162*)(g_b1lo + base + q * 32 + 2) = l1;
        }
    }
}

// ---------------- edge dtype detection + CSR build ---------------------------
__global__ void zero_counts_kernel() {
    int i = blockIdx.x * blockDim.x + threadIdx.x;
    if (i < K_NODES) { g_cnt[i] = 0; g_cur[i] = 0; }
    if (i == 0) g_is32 = 0;
}
__global__ void detect_dtype_kernel(const int* __restrict__ ei32) {
    int i = blockIdx.x * blockDim.x + threadIdx.x;
    if (i < N_EDGES && ei32[2 * i + 1] != 0) atomicExch(&g_is32, 1);
}
__device__ __forceinline__ int load_idx(const int* __restrict__ ei32, int elem) {
    return g_is32 ? ei32[elem] : ei32[2 * elem];
}
__global__ void count_edges_kernel(const int* __restrict__ ei32) {
    int e = blockIdx.x * blockDim.x + threadIdx.x;
    if (e >= N_TOT_EDGES) return;
    int dst = (e < N_EDGES) ? load_idx(ei32, N_EDGES + e) : (e - N_EDGES);
    if ((unsigned)dst >= K_NODES) return;
    atomicAdd(&g_cnt[dst], 1);
}
__global__ void scan_kernel() {
    __shared__ int ts[1024];
    int t = threadIdx.x;
    int c[4], s = 0;
    #pragma unroll
    for (int i = 0; i < 4; i++) { c[i] = s; s += g_cnt[t * 4 + i]; }
    ts[t] = s;
    __syncthreads();
    for (int o = 1; o < 1024; o <<= 1) {
        int v = (t >= o) ? ts[t - o] : 0;
        __syncthreads();
        ts[t] += v;
        __syncthreads();
    }
    int base = (t == 0) ? 0 : ts[t - 1];
    #pragma unroll
    for (int i = 0; i < 4; i++) g_off[t * 4 + i] = base + c[i];
    if (t == 1023) g_off[4096] = ts[1023];
}
__global__ void fill_edges_kernel(const int* __restrict__ ei32) {
    int e = blockIdx.x * blockDim.x + threadIdx.x;
    if (e >= N_TOT_EDGES) return;
    int src, dst;
    if (e < N_EDGES) {
        src = load_idx(ei32, e);
        dst = load_idx(ei32, N_EDGES + e);
    } else {
        src = dst = e - N_EDGES;
    }
    if ((unsigned)dst >= K_NODES || (unsigned)src >= K_NODES) return;
    int pos = atomicAdd(&g_cur[dst], 1);
    g_csr_src[g_off[dst] + pos] = src;
}

// ---------------- GAT aggregation: one block per dst node --------------------
__global__ void __launch_bounds__(256)
gat_aggregate_kernel(const float* __restrict__ gat_b, float* __restrict__ out) {
    __shared__ float sm_m[32], sm_d[32];
    __shared__ float part[8][32];
    __shared__ float s_alpha[64][33];
    __shared__ int   s_src[64];
    int dst = blockIdx.x, t = threadIdx.x;
    int off0 = g_off[dst], ne = g_cur[dst];

    {   // phase A: per-l max
        int l = t & 31, grp = t >> 5;
        float adl = g_ad[dst * 32 + l];
        float lm = -3.4e38f;
        for (int e = grp; e < ne; e += 8) {
            int src = g_csr_src[off0 + e];
            float v = g_as[src * 32 + l] + adl;
            v = v > 0.f ? v : 0.2f * v;
            lm = fmaxf(lm, v);
        }
        part[grp][l] = lm;
        __syncthreads();
        if (t < 32) {
            float m = part[0][t];
            #pragma unroll
            for (int g2 = 1; g2 < 8; g2++) m = fmaxf(m, part[g2][t]);
            sm_m[t] = m;
        }
        __syncthreads();
    }
    {   // phase B: denom
        int l = t & 31, grp = t >> 5;
        float adl = g_ad[dst * 32 + l];
        float m = sm_m[l], sden = 0.f;
        for (int e = grp; e < ne; e += 8) {
            int src = g_csr_src[off0 + e];
            float v = g_as[src * 32 + l] + adl;
            v = v > 0.f ? v : 0.2f * v;
            sden += expf(v - m);
        }
        __syncthreads();
        part[grp][l] = sden;
        __syncthreads();
        if (t < 32) {
            float s2 = 0.f;
            #pragma unroll
            for (int g2 = 0; g2 < 8; g2++) s2 += part[g2][t];
            sm_d[t] = s2;
        }
        __syncthreads();
    }
    {   // phase C: chunked alpha staging + weighted aggregation
        int l = t >> 3, d0 = (t & 7) * 16;
        float acc[16];
        #pragma unroll
        for (int i = 0; i < 16; i++) acc[i] = 0.f;

        for (int e0 = 0; e0 < ne; e0 += 64) {
            int ecnt = min(64, ne - e0);
            __syncthreads();
            if (t < ecnt) s_src[t] = g_csr_src[off0 + e0 + t];
            __syncthreads();
            for (int idx = t; idx < ecnt * 32; idx += 256) {
                int e = idx >> 5, ll = idx & 31;
                float v = g_as[s_src[e] * 32 + ll] + g_ad[dst * 32 + ll];
                v = v > 0.f ? v : 0.2f * v;
                s_alpha[e][ll] = expf(v - sm_m[ll]);
            }
            __syncthreads();
            for (int e = 0; e < ecnt; e++) {
                float ex = s_alpha[e][l];
                const float4* hp =
                    (const float4*)(g_h + ((size_t)s_src[e] * 32 + l) * 128 + d0);
                #pragma unroll
                for (int q = 0; q < 4; q++) {
                    float4 h4 = hp[q];
                    acc[q * 4 + 0] += ex * h4.x;
                    acc[q * 4 + 1] += ex * h4.y;
                    acc[q * 4 + 2] += ex * h4.z;
                    acc[q * 4 + 3] += ex * h4.w;
                }
            }
        }

        float inv = 1.f / (sm_d[l] + 1e-16f);
        float* op = out + ((size_t)dst * 32 + l) * 128 + d0;
        #pragma unroll
        for (int q = 0; q < 4; q++) {
            float4 o4;
            o4.x = acc[q * 4 + 0] * inv + gat_b[d0 + q * 4 + 0];
            o4.y = acc[q * 4 + 1] * inv + gat_b[d0 + q * 4 + 1];
            o4.z = acc[q * 4 + 2] * inv + gat_b[d0 + q * 4 + 2];
            o4.w = acc[q * 4 + 3] * inv + gat_b[d0 + q * 4 + 3];
            ((float4*)op)[q] = o4;
        }
    }
}

// ---------------- launch ------------------------------------------------------
extern "C" void kernel_launch(void* const* d_in, const int* in_sizes, int n_in,
                              void* d_out, int out_size) {
    const float* x     = (const float*)d_in[0];
    const int*   ei32  = (const int*)d_in[1];
    const float* ln1_g = (const float*)d_in[2];
    const float* ln1_b = (const float*)d_in[3];
    const float* qkv_w = (const float*)d_in[4];
    const float* qkv_b = (const float*)d_in[5];
    const float* out_w = (const float*)d_in[6];
    const float* out_b = (const float*)d_in[7];
    const float* ln2_g = (const float*)d_in[8];
    const float* ln2_b = (const float*)d_in[9];
    const float* ff1_w = (const float*)d_in[10];
    const float* ff1_b = (const float*)d_in[11];
    const float* ff2_w = (const float*)d_in[12];
    const float* ff2_b = (const float*)d_in[13];
    const float* gat_w = (const float*)d_in[14];
    const float* att_s = (const float*)d_in[15];
    const float* att_d = (const float*)d_in[16];
    const float* gat_b = (const float*)d_in[17];
    float* out = (float*)d_out;

    float *p_qkv, *p_x2, *p_h, *p_as, *p_ad;
    __nv_bfloat16 *p_b1hi, *p_b1lo, *p_b2hi, *p_b2lo, *p_whi, *p_wlo;
    cudaGetSymbolAddress((void**)&p_qkv,  g_qkv);
    cudaGetSymbolAddress((void**)&p_x2,   g_x2);
    cudaGetSymbolAddress((void**)&p_h,    g_h);
    cudaGetSymbolAddress((void**)&p_as,   g_as);
    cudaGetSymbolAddress((void**)&p_ad,   g_ad);
    cudaGetSymbolAddress((void**)&p_b1hi, g_b1hi);
    cudaGetSymbolAddress((void**)&p_b1lo, g_b1lo);
    cudaGetSymbolAddress((void**)&p_b2hi, g_b2hi);
    cudaGetSymbolAddress((void**)&p_b2lo, g_b2lo);
    cudaGetSymbolAddress((void**)&p_whi,  g_whi);
    cudaGetSymbolAddress((void**)&p_wlo,  g_wlo);

    const int GEMM_SMEM = 2 * STAGE_B;
    const int ATTN_SMEM = (96 * ATS + 1024) * 4;
    cudaFuncSetAttribute(gemm_mma_kernel,
                         cudaFuncAttributeMaxDynamicSharedMemorySize, GEMM_SMEM);
    cudaFuncSetAttribute(gemm_ares_kernel,
                         cudaFuncAttributeMaxDynamicSharedMemorySize, ARES_SMEM);
    cudaFuncSetAttribute(attn_kernel,
                         cudaFuncAttributeMaxDynamicSharedMemorySize, ATTN_SMEM);

    // 1. weight splits
    split_w_kernel<<<(W_TOTAL + 255) / 256, 256>>>(qkv_w, out_w, ff1_w, ff2_w, gat_w);
    // 2. LN1 -> b1 split
    ln_kernel<<<MM / 8, 256>>>(x, p_b1hi, p_b1lo, ln1_g, ln1_b);
    // 3. CSR zero
    zero_counts_kernel<<<(K_NODES + 255) / 256, 256>>>();
    // 4. qkv GEMM (A-resident, NT=3)  (ncu slot)
    gemm_ares_kernel<<<MM / 128, 256, ARES_SMEM>>>(
        p_b1hi, p_b1lo, p_whi + WOFF_QKV, p_wlo + WOFF_QKV, 128,
        qkv_b, p_qkv, nullptr, nullptr, 384, nullptr, 0, 3,
        nullptr, nullptr, nullptr, nullptr, nullptr, nullptr);
    // 5-6. CSR detect/count
    detect_dtype_kernel<<<(N_EDGES + 255) / 256, 256>>>(ei32);
    count_edges_kernel<<<(N_TOT_EDGES + 255) / 256, 256>>>(ei32);
    // 7. attention -> b1 split
    attn_kernel<<<K_NODES, 256, ATTN_SMEM>>>();
    // 8. out-proj + residual -> x2 fp32 AND fused LN2 -> b1 split (epi 5)
    gemm_ares_kernel<<<MM / 128, 256, ARES_SMEM>>>(
        p_b1hi, p_b1lo, p_whi + WOFF_OUT, p_wlo + WOFF_OUT, 128,
        out_b, p_x2, p_b1hi, p_b1lo, 128, x, 5, 1,
        ln2_g, ln2_b, nullptr, nullptr, nullptr, nullptr);
    // 9. CSR scan
    scan_kernel<<<1, 1024>>>();
    // 10. ff1 + gelu -> b2 split (NT=4)
    gemm_ares_kernel<<<MM / 128, 256, ARES_SMEM>>>(
        p_b1hi, p_b1lo, p_whi + WOFF_FF1, p_wlo + WOFF_FF1, 128,
        ff1_b, nullptr, p_b2hi, p_b2lo, 512, nullptr, 1, 4,
        nullptr, nullptr, nullptr, nullptr, nullptr, nullptr);
    // 11. ff2 + residual -> xt (b1 split), K=512 streaming kernel
    gemm_mma_kernel<<<dim3(MM / 128, 1), 256, GEMM_SMEM>>>(
        p_b2hi, p_b2lo, 512, 512, p_whi + WOFF_FF2, p_wlo + WOFF_FF2,
        ff2_b, nullptr, p_b1hi, p_b1lo, 128, p_x2, 4);
    // 12. GAT transform -> h fp32 AND fused a_src/a_dst (epi 6)
    gemm_ares_kernel<<<MM / 128, 256, ARES_SMEM>>>(
        p_b1hi, p_b1lo, p_whi + WOFF_GAT, p_wlo + WOFF_GAT, 128,
        nullptr, p_h, nullptr, nullptr, 128, nullptr, 6, 1,
        nullptr, nullptr, att_s, att_d, p_as, p_ad);
    // 13. CSR fill
    fill_edges_kernel<<<(N_TOT_EDGES + 255) / 256, 256>>>(ei32);
    // 14. aggregate
    gat_aggregate_kernel<<<K_NODES, 256>>>(gat_b, out);
}

// round 15
// speedup vs baseline: 3.8965x; 1.0306x over previous
#include <cuda_runtime.h>
#include <cuda_bf16.h>
#include <cstdint>
#include <math.h>

#define K_NODES 4096
#define SEQ_L   32
#define D_MODEL 128
#define D_FF    512
#define N_EDGES 65536
#define N_TOT_EDGES (N_EDGES + K_NODES)
#define MM (K_NODES * SEQ_L)           // 131072 rows

// streaming GEMM (ff2) params
#define KCH  32
#define SLD  40
#define STAGE_B (4 * 128 * SLD * 2)     // 40960 B

// A-resident GEMM params
#define SLDA 136                        // A row stride (128 + 8), conflict-free
#define KCHB 32                         // B chunk k
#define SLDB 40                         // B row stride (32 + 8), conflict-free
#define A_BYTES (2 * 128 * SLDA * 2)    // 69632
#define BSTG_B  (2 * 128 * SLDB * 2)    // 20480 per stage
#define ARES_SMEM (A_BYTES + 2 * BSTG_B)  // 110592 (2-stage)

// attn smem stride
#define ATS 132

// weight segment offsets in the packed split buffer
#define WOFF_QKV 0
#define WOFF_OUT 49152
#define WOFF_FF1 65536
#define WOFF_FF2 131072
#define WOFF_GAT 196608
#define W_TOTAL  212992

// ---------------- scratch (static; no runtime alloc) -------------------------
__device__ __nv_bfloat16 g_b1hi[MM * 128], g_b1lo[MM * 128];
__device__ __nv_bfloat16 g_b2hi[MM * 512], g_b2lo[MM * 512];
__device__ __nv_bfloat16 g_whi[W_TOTAL],  g_wlo[W_TOTAL];
__device__ float g_qkv[MM * 384];
__device__ float g_x2 [MM * 128];
__device__ float g_h  [MM * 128];
__device__ float g_as[K_NODES * SEQ_L];
__device__ float g_ad[K_NODES * SEQ_L];
__device__ int   g_cnt[K_NODES];
__device__ int   g_cur[K_NODES];
__device__ int   g_off[K_NODES + 1];
__device__ int   g_csr_src[N_TOT_EDGES];
__device__ int   g_is32;

__device__ __forceinline__ float gelu_exact(float v) {
    return 0.5f * v * (1.0f + erff(v * 0.70710678118654752f));
}

__device__ __forceinline__ uint32_t smem_u32(const void* p) {
    uint32_t a;
    asm("{ .reg .u64 t; cvta.to.shared.u64 t, %1; cvt.u32.u64 %0, t; }"
        : "=r"(a) : "l"(p));
    return a;
}

__device__ __forceinline__ void cp16(uint32_t dst, const void* src) {
    asm volatile("cp.async.cg.shared.global [%0], [%1], 16;"
                 :: "r"(dst), "l"(src));
}
#define CP_COMMIT() asm volatile("cp.async.commit_group;" ::: "memory")
#define CP_WAIT(n)  asm volatile("cp.async.wait_group %0;" :: "n"(n) : "memory")

__device__ __forceinline__ void mma16816(float* d,
                                         const uint32_t* a, const uint32_t* b) {
    asm volatile(
        "mma.sync.aligned.m16n8k16.row.col.f32.bf16.bf16.f32 "
        "{%0,%1,%2,%3}, {%4,%5,%6,%7}, {%8,%9}, {%0,%1,%2,%3};"
        : "+f"(d[0]), "+f"(d[1]), "+f"(d[2]), "+f"(d[3])
        : "r"(a[0]), "r"(a[1]), "r"(a[2]), "r"(a[3]), "r"(b[0]), "r"(b[1]));
}

__device__ __forceinline__ void ldsm4(uint32_t* r, uint32_t addr) {
    asm volatile("ldmatrix.sync.aligned.m8n8.x4.shared.b16 {%0,%1,%2,%3}, [%4];"
        : "=r"(r[0]), "=r"(r[1]), "=r"(r[2]), "=r"(r[3]) : "r"(addr));
}

__device__ __forceinline__ void split1(float v, __nv_bfloat16& h, __nv_bfloat16& l) {
    h = __float2bfloat16(v);
    l = __float2bfloat16(v - __bfloat162float(h));
}

// generic epilogue (epi 0..4)
__device__ __forceinline__ void epilogue_tile(
    float acc[2][8][4], int M0, int col0, int m_base, int n_base, int g, int c,
    const float* bias, float* C, __nv_bfloat16* Chi, __nv_bfloat16* Clo,
    int ldc, const float* res, int epi) {
    #pragma unroll
    for (int mt = 0; mt < 2; mt++) {
        int row0 = M0 + m_base + mt * 16 + g;
        #pragma unroll
        for (int nt = 0; nt < 8; nt++) {
            int col = col0 + n_base + nt * 8 + 2 * c;
            float b0 = 0.f, b1 = 0.f;
            if (epi != 3) { b0 = bias[col]; b1 = bias[col + 1]; }
            float v00 = acc[mt][nt][0] + b0, v01 = acc[mt][nt][1] + b1;
            float v10 = acc[mt][nt][2] + b0, v11 = acc[mt][nt][3] + b1;
            if (epi == 1) {
                v00 = gelu_exact(v00); v01 = gelu_exact(v01);
                v10 = gelu_exact(v10); v11 = gelu_exact(v11);
            } else if (epi == 2 || epi == 4) {
                float2 ra = *(const float2*)(res + (size_t)row0 * 128 + col);
                float2 rb = *(const float2*)(res + (size_t)(row0 + 8) * 128 + col);
                v00 += ra.x; v01 += ra.y; v10 += rb.x; v11 += rb.y;
            }
            if (epi == 1 || epi == 4) {
                __nv_bfloat162 h0, l0, h1, l1;
                split1(v00, h0.x, l0.x); split1(v01, h0.y, l0.y);
                split1(v10, h1.x, l1.x); split1(v11, h1.y, l1.y);
                *(__nv_bfloat162*)(Chi + (size_t)row0 * ldc + col)       = h0;
                *(__nv_bfloat162*)(Clo + (size_t)row0 * ldc + col)       = l0;
                *(__nv_bfloat162*)(Chi + (size_t)(row0 + 8) * ldc + col) = h1;
                *(__nv_bfloat162*)(Clo + (size_t)(row0 + 8) * ldc + col) = l1;
            } else {
                float2 o0 = {v00, v01}, o1 = {v10, v11};
                *(float2*)(C + (size_t)row0 * ldc + col)       = o0;
                *(float2*)(C + (size_t)(row0 + 8) * ldc + col) = o1;
            }
        }
    }
}

// ---------------- weight split ------------------------------------------------
__global__ void split_w_kernel(const float* __restrict__ w0, const float* __restrict__ w1,
                               const float* __restrict__ w2, const float* __restrict__ w3,
                               const float* __restrict__ w4) {
    int i = blockIdx.x * 256 + threadIdx.x;
    if (i >= W_TOTAL) return;
    const float* src; int off;
    if      (i < WOFF_OUT) { src = w0; off = WOFF_QKV; }
    else if (i < WOFF_FF1) { src = w1; off = WOFF_OUT; }
    else if (i < WOFF_FF2) { src = w2; off = WOFF_FF1; }
    else if (i < WOFF_GAT) { src = w3; off = WOFF_FF2; }
    else                   { src = w4; off = WOFF_GAT; }
    float v = src[i - off];
    __nv_bfloat16 h, l;
    split1(v, h, l);
    g_whi[i] = h; g_wlo[i] = l;
}

// ---------------- A-resident tensor-core GEMM (K = 128) ----------------------
// A (hi+lo) cached fully in smem; NT N-tiles, B in a 2-stage 32-k ring.
// Pipeline per chunk: sync(WAR) -> issue next copy -> CP_WAIT(own) ->
// sync(visibility) -> MMAs.  Warp grid 4(M)x2(N), 3-term bf16 split.
// epi: 0=+bias fp32; 1=+bias,gelu->split; 2=+bias,+res fp32; 3=none fp32;
//      4=+bias,+res->split; 5=+bias,+res fp32 C AND LN->split (Chi/Clo);
//      6=none fp32 C AND row-dots with av_s/av_d -> as_out/ad_out.
__global__ void __launch_bounds__(256, 2)
gemm_ares_kernel(const __nv_bfloat16* __restrict__ Ahi,
                 const __nv_bfloat16* __restrict__ Alo,
                 const __nv_bfloat16* __restrict__ Whi,
                 const __nv_bfloat16* __restrict__ Wlo, int Kw,
                 const float* __restrict__ bias,
                 float* __restrict__ C,
                 __nv_bfloat16* __restrict__ Chi, __nv_bfloat16* __restrict__ Clo,
                 int ldc, const float* __restrict__ res, int epi, int NT,
                 const float* __restrict__ lng, const float* __restrict__ lnb,
                 const float* __restrict__ av_s, const float* __restrict__ av_d,
                 float* __restrict__ as_out, float* __restrict__ ad_out) {
    extern __shared__ __nv_bfloat16 sm[];
    __shared__ float sred[4][128];
    uint32_t uA = smem_u32(sm);
    uint32_t uB = uA + A_BYTES;

    int t    = threadIdx.x;
    int wid  = t >> 5, lane = t & 31;
    int g    = lane >> 2;
    int c    = lane & 3;
    int M0   = blockIdx.x * 128;
    int wm   = wid >> 1, wn = wid & 1;
    int m_base = wm * 32, n_base = wn * 64;

    int la = lane & 15;
    int ka = (lane >> 4) * 8;
    int lb = (lane & 7) + ((lane >> 4) * 8);
    int kb = ((lane >> 3) & 1) * 8;

    // ---- load A (hi+lo, full 128x128): 4096 16B segments
    #pragma unroll
    for (int it = 0; it < 16; it++) {
        int idx  = it * 256 + t;
        int arr  = idx >> 11;
        int row  = (idx >> 4) & 127;
        int s8   = (idx & 15) * 8;
        const __nv_bfloat16* src =
            (arr ? Alo : Ahi) + (size_t)(M0 + row) * 128 + s8;
        cp16(uA + arr * 128 * SLDA * 2 + (row * SLDA + s8) * 2, src);
    }
    CP_COMMIT();

    // B chunk copy: 1024 16B segs (4 per thread), 32-k chunk
    auto copyB = [&](int ci, int stg) {
        int col0 = (ci >> 2) * 128;
        int kc   = (ci & 3) * KCHB;
        uint32_t base = uB + stg * BSTG_B;
        #pragma unroll
        for (int it = 0; it < 4; it++) {
            int idx = it * 256 + t;
            int arr = idx >> 9;
            int row = (idx >> 2) & 127;
            int s8  = (idx & 3) * 8;
            const __nv_bfloat16* src =
                (arr ? Wlo : Whi) + (size_t)(col0 + row) * Kw + kc + s8;
            cp16(base + arr * 128 * SLDB * 2 + (row * SLDB + s8) * 2, src);
        }
        CP_COMMIT();
    };

    int total = NT * 4;
    copyB(0, 0);

    float acc[2][8][4];
    for (int ci = 0; ci < total; ci++) {
        int stg = ci & 1;
        __syncthreads();                    // WAR: all reads of stage stg^1 done
        if (ci + 1 < total) copyB(ci + 1, stg ^ 1);
        else                CP_COMMIT();    // keep group accounting exact
        CP_WAIT(1);                          // this thread's chunk-ci copies done
        __syncthreads();                    // visibility of ALL threads' copies

        if ((ci & 3) == 0) {
            #pragma unroll
            for (int mt = 0; mt < 2; mt++)
                #pragma unroll
                for (int n2 = 0; n2 < 8; n2++)
                    #pragma unroll
                    for (int q = 0; q < 4; q++) acc[mt][n2][q] = 0.f;
        }

        uint32_t bbase = uB + stg * BSTG_B;
        #pragma unroll
        for (int kk2 = 0; kk2 < KCHB; kk2 += 16) {
            int kk = (ci & 3) * KCHB + kk2;
            uint32_t ah0[4], ah1[4], al0[4], al1[4];
            uint32_t aoff0 = ((m_base + la) * SLDA + ka + kk) * 2;
            uint32_t aoff1 = ((m_base + 16 + la) * SLDA + ka + kk) * 2;
            ldsm4(ah0, uA + aoff0);
            ldsm4(ah1, uA + aoff1);
            ldsm4(al0, uA + 128 * SLDA * 2 + aoff0);
            ldsm4(al1, uA + 128 * SLDA * 2 + aoff1);
            #pragma unroll
            for (int np = 0; np < 4; np++) {
                uint32_t bh[4], bl[4];
                uint32_t boff = ((n_base + np * 16 + lb) * SLDB + kb + kk2) * 2;
                ldsm4(bh, bbase + boff);
                ldsm4(bl, bbase + 128 * SLDB * 2 + boff);
                int n0 = 2 * np, n1 = 2 * np + 1;
                mma16816(acc[0][n0], ah0, bh);
                mma16816(acc[0][n0], ah0, bl);
                mma16816(acc[0][n0], al0, bh);
                mma16816(acc[0][n1], ah0, bh + 2);
                mma16816(acc[0][n1], ah0, bl + 2);
                mma16816(acc[0][n1], al0, bh + 2);
                mma16816(acc[1][n0], ah1, bh);
                mma16816(acc[1][n0], ah1, bl);
                mma16816(acc[1][n0], al1, bh);
                mma16816(acc[1][n1], ah1, bh + 2);
                mma16816(acc[1][n1], ah1, bl + 2);
                mma16816(acc[1][n1], al1, bh + 2);
            }
        }

        if ((ci & 3) == 3) {
            int col0 = (ci >> 2) * 128;
            if (epi == 5 || epi == 6) {
                float s0[2][2] = {{0.f,0.f},{0.f,0.f}};
                float s1[2][2] = {{0.f,0.f},{0.f,0.f}};
                #pragma unroll
                for (int mt = 0; mt < 2; mt++) {
                    int row0 = M0 + m_base + mt * 16 + g;
                    #pragma unroll
                    for (int n2 = 0; n2 < 8; n2++) {
                        int col = col0 + n_base + n2 * 8 + 2 * c;
                        float b0 = 0.f, b1 = 0.f;
                        if (epi == 5) { b0 = bias[col]; b1 = bias[col + 1]; }
                        float v00 = acc[mt][n2][0] + b0, v01 = acc[mt][n2][1] + b1;
                        float v10 = acc[mt][n2][2] + b0, v11 = acc[mt][n2][3] + b1;
                        if (epi == 5) {
                            float2 ra = *(const float2*)(res + (size_t)row0 * 128 + col);
                            float2 rb = *(const float2*)(res + (size_t)(row0 + 8) * 128 + col);
                            v00 += ra.x; v01 += ra.y; v10 += rb.x; v11 += rb.y;
                        }
                        acc[mt][n2][0] = v00; acc[mt][n2][1] = v01;
                        acc[mt][n2][2] = v10; acc[mt][n2][3] = v11;
                        float2 o0 = {v00, v01}, o1 = {v10, v11};
                        *(float2*)(C + (size_t)row0 * ldc + col)       = o0;
                        *(float2*)(C + (size_t)(row0 + 8) * ldc + col) = o1;
                        if (epi == 5) {
                            s0[mt][0] += v00 + v01; s1[mt][0] += v00 * v00 + v01 * v01;
                            s0[mt][1] += v10 + v11; s1[mt][1] += v10 * v10 + v11 * v11;
                        } else {
                            float as0 = av_s[col], as1 = av_s[col + 1];
                            float ad0 = av_d[col], ad1 = av_d[col + 1];
                            s0[mt][0] += v00 * as0 + v01 * as1;
                            s1[mt][0] += v00 * ad0 + v01 * ad1;
                            s0[mt][1] += v10 * as0 + v11 * as1;
                            s1[mt][1] += v10 * ad0 + v11 * ad1;
                        }
                    }
                }
                #pragma unroll
                for (int off = 1; off <= 2; off <<= 1) {
                    #pragma unroll
                    for (int mt = 0; mt < 2; mt++)
                        #pragma unroll
                        for (int h2 = 0; h2 < 2; h2++) {
                            s0[mt][h2] += __shfl_xor_sync(0xffffffffu, s0[mt][h2], off);
                            s1[mt][h2] += __shfl_xor_sync(0xffffffffu, s1[mt][h2], off);
                        }
                }
                if (c == 0) {
                    #pragma unroll
                    for (int mt = 0; mt < 2; mt++)
                        #pragma unroll
                        for (int h2 = 0; h2 < 2; h2++) {
                            int r = m_base + mt * 16 + g + 8 * h2;
                            sred[wn * 2][r]     = s0[mt][h2];
                            sred[wn * 2 + 1][r] = s1[mt][h2];
                        }
                }
                __syncthreads();
                if (epi == 5) {
                    float mean_[2][2], rs_[2][2];
                    #pragma unroll
                    for (int mt = 0; mt < 2; mt++)
                        #pragma unroll
                        for (int h2 = 0; h2 < 2; h2++) {
                            int r = m_base + mt * 16 + g + 8 * h2;
                            float S = sred[0][r] + sred[2][r];
                            float Q = sred[1][r] + sred[3][r];
                            float m = S * (1.0f / 128.0f);
                            float var = Q * (1.0f / 128.0f) - m * m;
                            mean_[mt][h2] = m;
                            rs_[mt][h2]   = rsqrtf(var + 1e-5f);
                        }
                    #pragma unroll
                    for (int mt = 0; mt < 2; mt++) {
                        int row0 = M0 + m_base + mt * 16 + g;
                        #pragma unroll
                        for (int n2 = 0; n2 < 8; n2++) {
                            int col = col0 + n_base + n2 * 8 + 2 * c;
                            float g0 = lng[col], g1 = lng[col + 1];
                            float be0 = lnb[col], be1 = lnb[col + 1];
                            float l00 = (acc[mt][n2][0] - mean_[mt][0]) * rs_[mt][0] * g0 + be0;
                            float l01 = (acc[mt][n2][1] - mean_[mt][0]) * rs_[mt][0] * g1 + be1;
                            float l10 = (acc[mt][n2][2] - mean_[mt][1]) * rs_[mt][1] * g0 + be0;
                            float l11 = (acc[mt][n2][3] - mean_[mt][1]) * rs_[mt][1] * g1 + be1;
                            __nv_bfloat162 h0, lo0, h1, lo1;
                            split1(l00, h0.x, lo0.x); split1(l01, h0.y, lo0.y);
                            split1(l10, h1.x, lo1.x); split1(l11, h1.y, lo1.y);
                            *(__nv_bfloat162*)(Chi + (size_t)row0 * 128 + col)       = h0;
                            *(__nv_bfloat162*)(Clo + (size_t)row0 * 128 + col)       = lo0;
                            *(__nv_bfloat162*)(Chi + (size_t)(row0 + 8) * 128 + col) = h1;
                            *(__nv_bfloat162*)(Clo + (size_t)(row0 + 8) * 128 + col) = lo1;
                        }
                    }
                } else {
                    if (wn == 0 && c == 0) {
                        #pragma unroll
                        for (int mt = 0; mt < 2; mt++)
                            #pragma unroll
                            for (int h2 = 0; h2 < 2; h2++) {
                                int r = m_base + mt * 16 + g + 8 * h2;
                                as_out[M0 + r] = sred[0][r] + sred[2][r];
                                ad_out[M0 + r] = sred[1][r] + sred[3][r];
                            }
                    }
                }
            } else {
                epilogue_tile(acc, M0, col0, m_base, n_base, g, c,
                              bias, C, Chi, Clo, ldc, res, epi);
            }
        }
    }
}

// ---------------- streaming tensor-core GEMM (ff2, K = 512) -------------------
__global__ void __launch_bounds__(256, 2)
gemm_mma_kernel(const __nv_bfloat16* __restrict__ Ahi,
                const __nv_bfloat16* __restrict__ Alo, int lda, int K,
                const __nv_bfloat16* __restrict__ Whi,
                const __nv_bfloat16* __restrict__ Wlo,
                const float* __restrict__ bias,
                float* __restrict__ C,
                __nv_bfloat16* __restrict__ Chi, __nv_bfloat16* __restrict__ Clo,
                int ldc, const float* __restrict__ res, int epi) {
    extern __shared__ __nv_bfloat16 sm[];
    uint32_t u0 = smem_u32(sm);

    int t    = threadIdx.x;
    int wid  = t >> 5, lane = t & 31;
    int g    = lane >> 2;
    int c    = lane & 3;
    int M0   = blockIdx.x * 128;
    int col0 = blockIdx.y * 128;
    int wm   = wid >> 1, wn = wid & 1;
    int m_base = wm * 32, n_base = wn * 64;

    int la = lane & 15;
    int ka = (lane >> 4) * 8;
    int lb = (lane & 7) + ((lane >> 4) * 8);
    int kb = ((lane >> 3) & 1) * 8;

    float acc[2][8][4];
    #pragma unroll
    for (int mt = 0; mt < 2; mt++)
        #pragma unroll
        for (int nt = 0; nt < 8; nt++)
            #pragma unroll
            for (int q = 0; q < 4; q++) acc[mt][nt][q] = 0.f;

    int nch = K / KCH;
    auto copy_chunk = [&](int kc, int stg) {
        uint32_t sbase = u0 + stg * STAGE_B;
        #pragma unroll
        for (int it = 0; it < 8; it++) {
            int idx  = it * 256 + t;
            int arr  = idx >> 9;
            int row  = (idx >> 2) & 127;
            int seg8 = (idx & 3) * 8;
            const __nv_bfloat16* src;
            if      (arr == 0) src = Ahi + (size_t)(M0 + row) * lda + kc + seg8;
            else if (arr == 1) src = Alo + (size_t)(M0 + row) * lda + kc + seg8;
            else if (arr == 2) src = Whi + (size_t)(col0 + row) * K + kc + seg8;
            else               src = Wlo + (size_t)(col0 + row) * K + kc + seg8;
            cp16(sbase + ((arr * 128 + row) * SLD + seg8) * 2, src);
        }
        CP_COMMIT();
    };

    copy_chunk(0, 0);
    for (int ch = 0; ch < nch; ch++) {
        int cur = ch & 1;
        if (ch + 1 < nch) { copy_chunk((ch + 1) * KCH, cur ^ 1); CP_WAIT(1); }
        else              { CP_WAIT(0); }
        __syncthreads();

        uint32_t base = u0 + cur * STAGE_B;
        #pragma unroll
        for (int kk = 0; kk < KCH; kk += 16) {
            uint32_t ah0[4], ah1[4], al0[4], al1[4];
            uint32_t aoff0 = ((m_base + la) * SLD + ka + kk) * 2;
            uint32_t aoff1 = ((m_base + 16 + la) * SLD + ka + kk) * 2;
            ldsm4(ah0, base + aoff0);
            ldsm4(ah1, base + aoff1);
            ldsm4(al0, base + 128 * SLD * 2 + aoff0);
            ldsm4(al1, base + 128 * SLD * 2 + aoff1);
            #pragma unroll
            for (int np = 0; np < 4; np++) {
                uint32_t bh[4], bl[4];
                uint32_t boff = ((n_base + np * 16 + lb) * SLD + kb + kk) * 2;
                ldsm4(bh, base + 2 * 128 * SLD * 2 + boff);
                ldsm4(bl, base + 3 * 128 * SLD * 2 + boff);
                int n0 = 2 * np, n1 = 2 * np + 1;
                mma16816(acc[0][n0], ah0, bh);
                mma16816(acc[0][n0], ah0, bl);
                mma16816(acc[0][n0], al0, bh);
                mma16816(acc[0][n1], ah0, bh + 2);
                mma16816(acc[0][n1], ah0, bl + 2);
                mma16816(acc[0][n1], al0, bh + 2);
                mma16816(acc[1][n0], ah1, bh);
                mma16816(acc[1][n0], ah1, bl);
                mma16816(acc[1][n0], al1, bh);
                mma16816(acc[1][n1], ah1, bh + 2);
                mma16816(acc[1][n1], ah1, bl + 2);
                mma16816(acc[1][n1], al1, bh + 2);
            }
        }
        __syncthreads();
    }
    epilogue_tile(acc, M0, col0, m_base, n_base, g, c,
                  bias, C, Chi, Clo, ldc, res, epi);
}

// ---------------- LayerNorm: fp32 in -> bf16 split out (LN1 only) ------------
__global__ void __launch_bounds__(256)
ln_kernel(const float* __restrict__ in,
          __nv_bfloat16* __restrict__ ohi, __nv_bfloat16* __restrict__ olo,
          const float* __restrict__ g, const float* __restrict__ b) {
    int warp = threadIdx.x >> 5, lane = threadIdx.x & 31;
    size_t row = (size_t)blockIdx.x * 8 + warp;
    float4 v = *(const float4*)(in + row * 128 + lane * 4);
    float s  = v.x + v.y + v.z + v.w;
    float ss = v.x * v.x + v.y * v.y + v.z * v.z + v.w * v.w;
    #pragma unroll
    for (int o = 16; o; o >>= 1) {
        s  += __shfl_xor_sync(0xffffffffu, s, o);
        ss += __shfl_xor_sync(0xffffffffu, ss, o);
    }
    float m   = s * (1.0f / 128.0f);
    float var = ss * (1.0f / 128.0f) - m * m;
    float rs  = rsqrtf(var + 1e-5f);
    float4 gg = *(const float4*)(g + lane * 4);
    float4 bb = *(const float4*)(b + lane * 4);
    float o0 = (v.x - m) * rs * gg.x + bb.x;
    float o1 = (v.y - m) * rs * gg.y + bb.y;
    float o2 = (v.z - m) * rs * gg.z + bb.z;
    float o3 = (v.w - m) * rs * gg.w + bb.w;
    __nv_bfloat162 h01, l01, h23, l23;
    split1(o0, h01.x, l01.x); split1(o1, h01.y, l01.y);
    split1(o2, h23.x, l23.x); split1(o3, h23.y, l23.y);
    *(__nv_bfloat162*)(ohi + row * 128 + lane * 4)     = h01;
    *(__nv_bfloat162*)(ohi + row * 128 + lane * 4 + 2) = h23;
    *(__nv_bfloat162*)(olo + row * 128 + lane * 4)     = l01;
    *(__nv_bfloat162*)(olo + row * 128 + lane * 4 + 2) = l23;
}

// ---------------- attention (per node, fp32 in, bf16 split out) -------------
__global__ void __launch_bounds__(256)
attn_kernel() {
    extern __shared__ float s[];
    float* sq  = s;
    float* sk  = s + 32 * ATS;
    float* sv  = s + 64 * ATS;
    float* ssc = s + 96 * ATS;
    int node = blockIdx.x, t = threadIdx.x;
    const float* qg = g_qkv + (size_t)node * 32 * 384;

    for (int i = t; i < 1024; i += 256) {
        int l = i >> 5, c4 = (i & 31) * 4;
        *(float4*)(sq + l * ATS + c4) = *(const float4*)(qg + l * 384 + c4);
        *(float4*)(sk + l * ATS + c4) = *(const float4*)(qg + l * 384 + 128 + c4);
        *(float4*)(sv + l * ATS + c4) = *(const float4*)(qg + l * 384 + 256 + c4);
    }
    __syncthreads();

    {   // scores
        int i = t >> 3, j0 = (t & 7) * 4;
        float acc[4] = {0.f, 0.f, 0.f, 0.f};
        #pragma unroll 4
        for (int d = 0; d < 128; d += 4) {
            float4 q = *(const float4*)(sq + i * ATS + d);
            #pragma unroll
            for (int jj = 0; jj < 4; jj++) {
                float4 k4 = *(const float4*)(sk + (j0 + jj) * ATS + d);
                acc[jj] += q.x * k4.x + q.y * k4.y + q.z * k4.z + q.w * k4.w;
            }
        }
        const float scale = 0.08838834764831845f;
        #pragma unroll
        for (int jj = 0; jj < 4; jj++) ssc[i * 32 + j0 + jj] = acc[jj] * scale;
    }
    __syncthreads();
    {   // softmax
        int warp = t >> 5, lane = t & 31;
        for (int r = warp; r < 32; r += 8) {
            float v = ssc[r * 32 + lane];
            float mx = v;
            #pragma unroll
            for (int o = 16; o; o >>= 1) mx = fmaxf(mx, __shfl_xor_sync(0xffffffffu, mx, o));
            float e = expf(v - mx);
            float sm2 = e;
            #pragma unroll
            for (int o = 16; o; o >>= 1) sm2 += __shfl_xor_sync(0xffffffffu, sm2, o);
            ssc[r * 32 + lane] = e / sm2;
        }
    }
    __syncthreads();
    {   // attn = a @ v -> split bf16
        int i = t >> 3, d0 = (t & 7) * 4;
        float acc[4][4];
        #pragma unroll
        for (int q = 0; q < 4; q++)
            #pragma unroll
            for (int e = 0; e < 4; e++) acc[q][e] = 0.f;
        for (int j = 0; j < 32; j++) {
            float a = ssc[i * 32 + j];
            const float* vr = sv + j * ATS + d0;
            #pragma unroll
            for (int q = 0; q < 4; q++) {
                float4 v4 = *(const float4*)(vr + q * 32);
                acc[q][0] += a * v4.x; acc[q][1] += a * v4.y;
                acc[q][2] += a * v4.z; acc[q][3] += a * v4.w;
            }
        }
        size_t base = ((size_t)node * 32 + i) * 128 + d0;
        #pragma unroll
        for (int q = 0; q < 4; q++) {
            __nv_bfloat162 h0, l0, h1, l1;
            split1(acc[q][0], h0.x, l0.x); split1(acc[q][1], h0.y, l0.y);
            split1(acc[q][2], h1.x, l1.x); split1(acc[q][3], h1.y, l1.y);
            *(__nv_bfloat162*)(g_b1hi + base + q * 32)     = h0;
            *(__nv_bfloat162*)(g_b1hi + base + q * 32 + 2) = h1;
            *(__nv_bfloat162*)(g_b1lo + base + q * 32)     = l0;
            *(__nv_bfloat162*)(g_b1lo + base + q * 32 + 2) = l1;
        }
    }
}

// ---------------- edge dtype detection + CSR build ---------------------------
__global__ void zero_counts_kernel() {
    int i = blockIdx.x * blockDim.x + threadIdx.x;
    if (i < K_NODES) { g_cnt[i] = 0; g_cur[i] = 0; }
    if (i == 0) g_is32 = 0;
}
__global__ void detect_dtype_kernel(const int* __restrict__ ei32) {
    int i = blockIdx.x * blockDim.x + threadIdx.x;
    if (i < N_EDGES && ei32[2 * i + 1] != 0) atomicExch(&g_is32, 1);
}
__device__ __forceinline__ int load_idx(const int* __restrict__ ei32, int elem) {
    return g_is32 ? ei32[elem] : ei32[2 * elem];
}
__global__ void count_edges_kernel(const int* __restrict__ ei32) {
    int e = blockIdx.x * blockDim.x + threadIdx.x;
    if (e >= N_TOT_EDGES) return;
    int dst = (e < N_EDGES) ? load_idx(ei32, N_EDGES + e) : (e - N_EDGES);
    if ((unsigned)dst >= K_NODES) return;
    atomicAdd(&g_cnt[dst], 1);
}
__global__ void scan_kernel() {
    __shared__ int ts[1024];
    int t = threadIdx.x;
    int c[4], s = 0;
    #pragma unroll
    for (int i = 0; i < 4; i++) { c[i] = s; s += g_cnt[t * 4 + i]; }
    ts[t] = s;
    __syncthreads();
    for (int o = 1; o < 1024; o <<= 1) {
        int v = (t >= o) ? ts[t - o] : 0;
        __syncthreads();
        ts[t] += v;
        __syncthreads();
    }
    int base = (t == 0) ? 0 : ts[t - 1];
    #pragma unroll
    for (int i = 0; i < 4; i++) g_off[t * 4 + i] = base + c[i];
    if (t == 1023) g_off[4096] = ts[1023];
}
__global__ void fill_edges_kernel(const int* __restrict__ ei32) {
    int e = blockIdx.x * blockDim.x + threadIdx.x;
    if (e >= N_TOT_EDGES) return;
    int src, dst;
    if (e < N_EDGES) {
        src = load_idx(ei32, e);
        dst = load_idx(ei32, N_EDGES + e);
    } else {
        src = dst = e - N_EDGES;
    }
    if ((unsigned)dst >= K_NODES || (unsigned)src >= K_NODES) return;
    int pos = atomicAdd(&g_cur[dst], 1);
    g_csr_src[g_off[dst] + pos] = src;
}

// ---------------- GAT aggregation: one block per dst node --------------------
__global__ void __launch_bounds__(256)
gat_aggregate_kernel(const float* __restrict__ gat_b, float* __restrict__ out) {
    __shared__ float sm_m[32], sm_d[32];
    __shared__ float part[8][32];
    __shared__ float s_alpha[64][33];
    __shared__ int   s_src[64];
    int dst = blockIdx.x, t = threadIdx.x;
    int off0 = g_off[dst], ne = g_cur[dst];

    {   // phase A: per-l max
        int l = t & 31, grp = t >> 5;
        float adl = g_ad[dst * 32 + l];
        float lm = -3.4e38f;
        for (int e = grp; e < ne; e += 8) {
            int src = g_csr_src[off0 + e];
            float v = g_as[src * 32 + l] + adl;
            v = v > 0.f ? v : 0.2f * v;
            lm = fmaxf(lm, v);
        }
        part[grp][l] = lm;
        __syncthreads();
        if (t < 32) {
            float m = part[0][t];
            #pragma unroll
            for (int g2 = 1; g2 < 8; g2++) m = fmaxf(m, part[g2][t]);
            sm_m[t] = m;
        }
        __syncthreads();
    }
    {   // phase B: denom
        int l = t & 31, grp = t >> 5;
        float adl = g_ad[dst * 32 + l];
        float m = sm_m[l], sden = 0.f;
        for (int e = grp; e < ne; e += 8) {
            int src = g_csr_src[off0 + e];
            float v = g_as[src * 32 + l] + adl;
            v = v > 0.f ? v : 0.2f * v;
            sden += expf(v - m);
        }
        __syncthreads();
        part[grp][l] = sden;
        __syncthreads();
        if (t < 32) {
            float s2 = 0.f;
            #pragma unroll
            for (int g2 = 0; g2 < 8; g2++) s2 += part[g2][t];
            sm_d[t] = s2;
        }
        __syncthreads();
    }
    {   // phase C: chunked alpha staging + weighted aggregation
        int l = t >> 3, d0 = (t & 7) * 16;
        float acc[16];
        #pragma unroll
        for (int i = 0; i < 16; i++) acc[i] = 0.f;

        for (int e0 = 0; e0 < ne; e0 += 64) {
            int ecnt = min(64, ne - e0);
            __syncthreads();
            if (t < ecnt) s_src[t] = g_csr_src[off0 + e0 + t];
            __syncthreads();
            for (int idx = t; idx < ecnt * 32; idx += 256) {
                int e = idx >> 5, ll = idx & 31;
                float v = g_as[s_src[e] * 32 + ll] + g_ad[dst * 32 + ll];
                v = v > 0.f ? v : 0.2f * v;
                s_alpha[e][ll] = expf(v - sm_m[ll]);
            }
            __syncthreads();
            for (int e = 0; e < ecnt; e++) {
                float ex = s_alpha[e][l];
                const float4* hp =
                    (const float4*)(g_h + ((size_t)s_src[e] * 32 + l) * 128 + d0);
                #pragma unroll
                for (int q = 0; q < 4; q++) {
                    float4 h4 = hp[q];
                    acc[q * 4 + 0] += ex * h4.x;
                    acc[q * 4 + 1] += ex * h4.y;
                    acc[q * 4 + 2] += ex * h4.z;
                    acc[q * 4 + 3] += ex * h4.w;
                }
            }
        }

        float inv = 1.f / (sm_d[l] + 1e-16f);
        float* op = out + ((size_t)dst * 32 + l) * 128 + d0;
        #pragma unroll
        for (int q = 0; q < 4; q++) {
            float4 o4;
            o4.x = acc[q * 4 + 0] * inv + gat_b[d0 + q * 4 + 0];
            o4.y = acc[q * 4 + 1] * inv + gat_b[d0 + q * 4 + 1];
            o4.z = acc[q * 4 + 2] * inv + gat_b[d0 + q * 4 + 2];
            o4.w = acc[q * 4 + 3] * inv + gat_b[d0 + q * 4 + 3];
            ((float4*)op)[q] = o4;
        }
    }
}

// ---------------- launch ------------------------------------------------------
extern "C" void kernel_launch(void* const* d_in, const int* in_sizes, int n_in,
                              void* d_out, int out_size) {
    const float* x     = (const float*)d_in[0];
    const int*   ei32  = (const int*)d_in[1];
    const float* ln1_g = (const float*)d_in[2];
    const float* ln1_b = (const float*)d_in[3];
    const float* qkv_w = (const float*)d_in[4];
    const float* qkv_b = (const float*)d_in[5];
    const float* out_w = (const float*)d_in[6];
    const float* out_b = (const float*)d_in[7];
    const float* ln2_g = (const float*)d_in[8];
    const float* ln2_b = (const float*)d_in[9];
    const float* ff1_w = (const float*)d_in[10];
    const float* ff1_b = (const float*)d_in[11];
    const float* ff2_w = (const float*)d_in[12];
    const float* ff2_b = (const float*)d_in[13];
    const float* gat_w = (const float*)d_in[14];
    const float* att_s = (const float*)d_in[15];
    const float* att_d = (const float*)d_in[16];
    const float* gat_b = (const float*)d_in[17];
    float* out = (float*)d_out;

    float *p_qkv, *p_x2, *p_h, *p_as, *p_ad;
    __nv_bfloat16 *p_b1hi, *p_b1lo, *p_b2hi, *p_b2lo, *p_whi, *p_wlo;
    cudaGetSymbolAddress((void**)&p_qkv,  g_qkv);
    cudaGetSymbolAddress((void**)&p_x2,   g_x2);
    cudaGetSymbolAddress((void**)&p_h,    g_h);
    cudaGetSymbolAddress((void**)&p_as,   g_as);
    cudaGetSymbolAddress((void**)&p_ad,   g_ad);
    cudaGetSymbolAddress((void**)&p_b1hi, g_b1hi);
    cudaGetSymbolAddress((void**)&p_b1lo, g_b1lo);
    cudaGetSymbolAddress((void**)&p_b2hi, g_b2hi);
    cudaGetSymbolAddress((void**)&p_b2lo, g_b2lo);
    cudaGetSymbolAddress((void**)&p_whi,  g_whi);
    cudaGetSymbolAddress((void**)&p_wlo,  g_wlo);

    const int GEMM_SMEM = 2 * STAGE_B;
    const int ATTN_SMEM = (96 * ATS + 1024) * 4;
    cudaFuncSetAttribute(gemm_mma_kernel,
                         cudaFuncAttributeMaxDynamicSharedMemorySize, GEMM_SMEM);
    cudaFuncSetAttribute(gemm_ares_kernel,
                         cudaFuncAttributeMaxDynamicSharedMemorySize, ARES_SMEM);
    cudaFuncSetAttribute(attn_kernel,
                         cudaFuncAttributeMaxDynamicSharedMemorySize, ATTN_SMEM);

    // 1. weight splits
    split_w_kernel<<<(W_TOTAL + 255) / 256, 256>>>(qkv_w, out_w, ff1_w, ff2_w, gat_w);
    // 2. LN1 -> b1 split
    ln_kernel<<<MM / 8, 256>>>(x, p_b1hi, p_b1lo, ln1_g, ln1_b);
    // 3. CSR zero
    zero_counts_kernel<<<(K_NODES + 255) / 256, 256>>>();
    // 4. qkv GEMM (A-resident, NT=3)  (ncu slot)
    gemm_ares_kernel<<<MM / 128, 256, ARES_SMEM>>>(
        p_b1hi, p_b1lo, p_whi + WOFF_QKV, p_wlo + WOFF_QKV, 128,
        qkv_b, p_qkv, nullptr, nullptr, 384, nullptr, 0, 3,
        nullptr, nullptr, nullptr, nullptr, nullptr, nullptr);
    // 5-6. CSR detect/count
    detect_dtype_kernel<<<(N_EDGES + 255) / 256, 256>>>(ei32);
    count_edges_kernel<<<(N_TOT_EDGES + 255) / 256, 256>>>(ei32);
    // 7. attention -> b1 split
    attn_kernel<<<K_NODES, 256, ATTN_SMEM>>>();
    // 8. out-proj + residual -> x2 fp32 AND fused LN2 -> b1 split (epi 5)
    gemm_ares_kernel<<<MM / 128, 256, ARES_SMEM>>>(
        p_b1hi, p_b1lo, p_whi + WOFF_OUT, p_wlo + WOFF_OUT, 128,
        out_b, p_x2, p_b1hi, p_b1lo, 128, x, 5, 1,
        ln2_g, ln2_b, nullptr, nullptr, nullptr, nullptr);
    // 9. CSR scan
    scan_kernel<<<1, 1024>>>();
    // 10. ff1 + gelu -> b2 split (NT=4)
    gemm_ares_kernel<<<MM / 128, 256, ARES_SMEM>>>(
        p_b1hi, p_b1lo, p_whi + WOFF_FF1, p_wlo + WOFF_FF1, 128,
        ff1_b, nullptr, p_b2hi, p_b2lo, 512, nullptr, 1, 4,
        nullptr, nullptr, nullptr, nullptr, nullptr, nullptr);
    // 11. ff2 + residual -> xt (b1 split), K=512 streaming kernel
    gemm_mma_kernel<<<dim3(MM / 128, 1), 256, GEMM_SMEM>>>(
        p_b2hi, p_b2lo, 512, 512, p_whi + WOFF_FF2, p_wlo + WOFF_FF2,
        ff2_b, nullptr, p_b1hi, p_b1lo, 128, p_x2, 4);
    // 12. GAT transform -> h fp32 AND fused a_src/a_dst (epi 6)
    gemm_ares_kernel<<<MM / 128, 256, ARES_SMEM>>>(
        p_b1hi, p_b1lo, p_whi + WOFF_GAT, p_wlo + WOFF_GAT, 128,
        nullptr, p_h, nullptr, nullptr, 128, nullptr, 6, 1,
        nullptr, nullptr, att_s, att_d, p_as, p_ad);
    // 13. CSR fill
    fill_edges_kernel<<<(N_TOT_EDGES + 255) / 256, 256>>>(ei32);
    // 14. aggregate
    gat_aggregate_kernel<<<K_NODES, 256>>>(gat_b, out);
}

// round 16
// speedup vs baseline: 4.1522x; 1.0656x over previous
#include <cuda_runtime.h>
#include <cuda_bf16.h>
#include <cstdint>
#include <math.h>

#define K_NODES 4096
#define SEQ_L   32
#define D_MODEL 128
#define D_FF    512
#define N_EDGES 65536
#define N_TOT_EDGES (N_EDGES + K_NODES)
#define MM (K_NODES * SEQ_L)           // 131072 rows

// ff2 single-A streaming GEMM params
#define KCH  32
#define SLD  40
#define FF2_STAGE_B (3 * 128 * SLD * 2) // 30720 B per stage (A, Whi, Wlo)

// A-resident GEMM params
#define SLDA 136
#define KCHB 32
#define SLDB 40
#define A_BYTES (2 * 128 * SLDA * 2)    // 69632
#define BSTG_B  (2 * 128 * SLDB * 2)    // 20480 per stage
#define ARES_SMEM (A_BYTES + 2 * BSTG_B)  // 110592

// attn smem stride
#define ATS 132

// weight segment offsets in the packed split buffer
#define WOFF_QKV 0
#define WOFF_OUT 49152
#define WOFF_FF1 65536
#define WOFF_FF2 131072
#define WOFF_GAT 196608
#define W_TOTAL  212992

// ---------------- scratch (static; no runtime alloc) -------------------------
__device__ __nv_bfloat16 g_b1hi[MM * 128], g_b1lo[MM * 128];
__device__ __nv_bfloat16 g_b2hi[MM * 512];                  // gelu(ff1), single bf16
__device__ __nv_bfloat16 g_whi[W_TOTAL],  g_wlo[W_TOTAL];
__device__ float g_qkv[MM * 384];
__device__ float g_x2 [MM * 128];
__device__ float g_h  [MM * 128];
__device__ float g_as[K_NODES * SEQ_L];
__device__ float g_ad[K_NODES * SEQ_L];
__device__ int   g_cnt[K_NODES];
__device__ int   g_cur[K_NODES];
__device__ int   g_off[K_NODES + 1];
__device__ int   g_csr_src[N_TOT_EDGES];
__device__ int   g_is32;

__device__ __forceinline__ float gelu_exact(float v) {
    return 0.5f * v * (1.0f + erff(v * 0.70710678118654752f));
}

__device__ __forceinline__ uint32_t smem_u32(const void* p) {
    uint32_t a;
    asm("{ .reg .u64 t; cvta.to.shared.u64 t, %1; cvt.u32.u64 %0, t; }"
        : "=r"(a) : "l"(p));
    return a;
}

__device__ __forceinline__ void cp16(uint32_t dst, const void* src) {
    asm volatile("cp.async.cg.shared.global [%0], [%1], 16;"
                 :: "r"(dst), "l"(src));
}
#define CP_COMMIT() asm volatile("cp.async.commit_group;" ::: "memory")
#define CP_WAIT(n)  asm volatile("cp.async.wait_group %0;" :: "n"(n) : "memory")

__device__ __forceinline__ void mma16816(float* d,
                                         const uint32_t* a, const uint32_t* b) {
    asm volatile(
        "mma.sync.aligned.m16n8k16.row.col.f32.bf16.bf16.f32 "
        "{%0,%1,%2,%3}, {%4,%5,%6,%7}, {%8,%9}, {%0,%1,%2,%3};"
        : "+f"(d[0]), "+f"(d[1]), "+f"(d[2]), "+f"(d[3])
        : "r"(a[0]), "r"(a[1]), "r"(a[2]), "r"(a[3]), "r"(b[0]), "r"(b[1]));
}

__device__ __forceinline__ void ldsm4(uint32_t* r, uint32_t addr) {
    asm volatile("ldmatrix.sync.aligned.m8n8.x4.shared.b16 {%0,%1,%2,%3}, [%4];"
        : "=r"(r[0]), "=r"(r[1]), "=r"(r[2]), "=r"(r[3]) : "r"(addr));
}

__device__ __forceinline__ void split1(float v, __nv_bfloat16& h, __nv_bfloat16& l) {
    h = __float2bfloat16(v);
    l = __float2bfloat16(v - __bfloat162float(h));
}

// generic epilogue (epi 0..4). epi 1 with Clo==nullptr writes single bf16.
__device__ __forceinline__ void epilogue_tile(
    float acc[2][8][4], int M0, int col0, int m_base, int n_base, int g, int c,
    const float* bias, float* C, __nv_bfloat16* Chi, __nv_bfloat16* Clo,
    int ldc, const float* res, int epi) {
    #pragma unroll
    for (int mt = 0; mt < 2; mt++) {
        int row0 = M0 + m_base + mt * 16 + g;
        #pragma unroll
        for (int nt = 0; nt < 8; nt++) {
            int col = col0 + n_base + nt * 8 + 2 * c;
            float b0 = 0.f, b1 = 0.f;
            if (epi != 3) { b0 = bias[col]; b1 = bias[col + 1]; }
            float v00 = acc[mt][nt][0] + b0, v01 = acc[mt][nt][1] + b1;
            float v10 = acc[mt][nt][2] + b0, v11 = acc[mt][nt][3] + b1;
            if (epi == 1) {
                v00 = gelu_exact(v00); v01 = gelu_exact(v01);
                v10 = gelu_exact(v10); v11 = gelu_exact(v11);
            } else if (epi == 2 || epi == 4) {
                float2 ra = *(const float2*)(res + (size_t)row0 * 128 + col);
                float2 rb = *(const float2*)(res + (size_t)(row0 + 8) * 128 + col);
                v00 += ra.x; v01 += ra.y; v10 += rb.x; v11 += rb.y;
            }
            if (epi == 1 && Clo == nullptr) {
                __nv_bfloat162 h0, h1;
                h0.x = __float2bfloat16(v00); h0.y = __float2bfloat16(v01);
                h1.x = __float2bfloat16(v10); h1.y = __float2bfloat16(v11);
                *(__nv_bfloat162*)(Chi + (size_t)row0 * ldc + col)       = h0;
                *(__nv_bfloat162*)(Chi + (size_t)(row0 + 8) * ldc + col) = h1;
            } else if (epi == 1 || epi == 4) {
                __nv_bfloat162 h0, l0, h1, l1;
                split1(v00, h0.x, l0.x); split1(v01, h0.y, l0.y);
                split1(v10, h1.x, l1.x); split1(v11, h1.y, l1.y);
                *(__nv_bfloat162*)(Chi + (size_t)row0 * ldc + col)       = h0;
                *(__nv_bfloat162*)(Clo + (size_t)row0 * ldc + col)       = l0;
                *(__nv_bfloat162*)(Chi + (size_t)(row0 + 8) * ldc + col) = h1;
                *(__nv_bfloat162*)(Clo + (size_t)(row0 + 8) * ldc + col) = l1;
            } else {
                float2 o0 = {v00, v01}, o1 = {v10, v11};
                *(float2*)(C + (size_t)row0 * ldc + col)       = o0;
                *(float2*)(C + (size_t)(row0 + 8) * ldc + col) = o1;
            }
        }
    }
}

// ---------------- weight split ------------------------------------------------
__global__ void split_w_kernel(const float* __restrict__ w0, const float* __restrict__ w1,
                               const float* __restrict__ w2, const float* __restrict__ w3,
                               const float* __restrict__ w4) {
    int i = blockIdx.x * 256 + threadIdx.x;
    if (i >= W_TOTAL) return;
    const float* src; int off;
    if      (i < WOFF_OUT) { src = w0; off = WOFF_QKV; }
    else if (i < WOFF_FF1) { src = w1; off = WOFF_OUT; }
    else if (i < WOFF_FF2) { src = w2; off = WOFF_FF1; }
    else if (i < WOFF_GAT) { src = w3; off = WOFF_FF2; }
    else                   { src = w4; off = WOFF_GAT; }
    float v = src[i - off];
    __nv_bfloat16 h, l;
    split1(v, h, l);
    g_whi[i] = h; g_wlo[i] = l;
}

// ---------------- A-resident tensor-core GEMM (K = 128) ----------------------
// (identical to R15 passing version)
__global__ void __launch_bounds__(256, 2)
gemm_ares_kernel(const __nv_bfloat16* __restrict__ Ahi,
                 const __nv_bfloat16* __restrict__ Alo,
                 const __nv_bfloat16* __restrict__ Whi,
                 const __nv_bfloat16* __restrict__ Wlo, int Kw,
                 const float* __restrict__ bias,
                 float* __restrict__ C,
                 __nv_bfloat16* __restrict__ Chi, __nv_bfloat16* __restrict__ Clo,
                 int ldc, const float* __restrict__ res, int epi, int NT,
                 const float* __restrict__ lng, const float* __restrict__ lnb,
                 const float* __restrict__ av_s, const float* __restrict__ av_d,
                 float* __restrict__ as_out, float* __restrict__ ad_out) {
    extern __shared__ __nv_bfloat16 sm[];
    __shared__ float sred[4][128];
    uint32_t uA = smem_u32(sm);
    uint32_t uB = uA + A_BYTES;

    int t    = threadIdx.x;
    int wid  = t >> 5, lane = t & 31;
    int g    = lane >> 2;
    int c    = lane & 3;
    int M0   = blockIdx.x * 128;
    int wm   = wid >> 1, wn = wid & 1;
    int m_base = wm * 32, n_base = wn * 64;

    int la = lane & 15;
    int ka = (lane >> 4) * 8;
    int lb = (lane & 7) + ((lane >> 4) * 8);
    int kb = ((lane >> 3) & 1) * 8;

    #pragma unroll
    for (int it = 0; it < 16; it++) {
        int idx  = it * 256 + t;
        int arr  = idx >> 11;
        int row  = (idx >> 4) & 127;
        int s8   = (idx & 15) * 8;
        const __nv_bfloat16* src =
            (arr ? Alo : Ahi) + (size_t)(M0 + row) * 128 + s8;
        cp16(uA + arr * 128 * SLDA * 2 + (row * SLDA + s8) * 2, src);
    }
    CP_COMMIT();

    auto copyB = [&](int ci, int stg) {
        int col0 = (ci >> 2) * 128;
        int kc   = (ci & 3) * KCHB;
        uint32_t base = uB + stg * BSTG_B;
        #pragma unroll
        for (int it = 0; it < 4; it++) {
            int idx = it * 256 + t;
            int arr = idx >> 9;
            int row = (idx >> 2) & 127;
            int s8  = (idx & 3) * 8;
            const __nv_bfloat16* src =
                (arr ? Wlo : Whi) + (size_t)(col0 + row) * Kw + kc + s8;
            cp16(base + arr * 128 * SLDB * 2 + (row * SLDB + s8) * 2, src);
        }
        CP_COMMIT();
    };

    int total = NT * 4;
    copyB(0, 0);

    float acc[2][8][4];
    for (int ci = 0; ci < total; ci++) {
        int stg = ci & 1;
        __syncthreads();
        if (ci + 1 < total) copyB(ci + 1, stg ^ 1);
        else                CP_COMMIT();
        CP_WAIT(1);
        __syncthreads();

        if ((ci & 3) == 0) {
            #pragma unroll
            for (int mt = 0; mt < 2; mt++)
                #pragma unroll
                for (int n2 = 0; n2 < 8; n2++)
                    #pragma unroll
                    for (int q = 0; q < 4; q++) acc[mt][n2][q] = 0.f;
        }

        uint32_t bbase = uB + stg * BSTG_B;
        #pragma unroll
        for (int kk2 = 0; kk2 < KCHB; kk2 += 16) {
            int kk = (ci & 3) * KCHB + kk2;
            uint32_t ah0[4], ah1[4], al0[4], al1[4];
            uint32_t aoff0 = ((m_base + la) * SLDA + ka + kk) * 2;
            uint32_t aoff1 = ((m_base + 16 + la) * SLDA + ka + kk) * 2;
            ldsm4(ah0, uA + aoff0);
            ldsm4(ah1, uA + aoff1);
            ldsm4(al0, uA + 128 * SLDA * 2 + aoff0);
            ldsm4(al1, uA + 128 * SLDA * 2 + aoff1);
            #pragma unroll
            for (int np = 0; np < 4; np++) {
                uint32_t bh[4], bl[4];
                uint32_t boff = ((n_base + np * 16 + lb) * SLDB + kb + kk2) * 2;
                ldsm4(bh, bbase + boff);
                ldsm4(bl, bbase + 128 * SLDB * 2 + boff);
                int n0 = 2 * np, n1 = 2 * np + 1;
                mma16816(acc[0][n0], ah0, bh);
                mma16816(acc[0][n0], ah0, bl);
                mma16816(acc[0][n0], al0, bh);
                mma16816(acc[0][n1], ah0, bh + 2);
                mma16816(acc[0][n1], ah0, bl + 2);
                mma16816(acc[0][n1], al0, bh + 2);
                mma16816(acc[1][n0], ah1, bh);
                mma16816(acc[1][n0], ah1, bl);
                mma16816(acc[1][n0], al1, bh);
                mma16816(acc[1][n1], ah1, bh + 2);
                mma16816(acc[1][n1], ah1, bl + 2);
                mma16816(acc[1][n1], al1, bh + 2);
            }
        }

        if ((ci & 3) == 3) {
            int col0 = (ci >> 2) * 128;
            if (epi == 5 || epi == 6) {
                float s0[2][2] = {{0.f,0.f},{0.f,0.f}};
                float s1[2][2] = {{0.f,0.f},{0.f,0.f}};
                #pragma unroll
                for (int mt = 0; mt < 2; mt++) {
                    int row0 = M0 + m_base + mt * 16 + g;
                    #pragma unroll
                    for (int n2 = 0; n2 < 8; n2++) {
                        int col = col0 + n_base + n2 * 8 + 2 * c;
                        float b0 = 0.f, b1 = 0.f;
                        if (epi == 5) { b0 = bias[col]; b1 = bias[col + 1]; }
                        float v00 = acc[mt][n2][0] + b0, v01 = acc[mt][n2][1] + b1;
                        float v10 = acc[mt][n2][2] + b0, v11 = acc[mt][n2][3] + b1;
                        if (epi == 5) {
                            float2 ra = *(const float2*)(res + (size_t)row0 * 128 + col);
                            float2 rb = *(const float2*)(res + (size_t)(row0 + 8) * 128 + col);
                            v00 += ra.x; v01 += ra.y; v10 += rb.x; v11 += rb.y;
                        }
                        acc[mt][n2][0] = v00; acc[mt][n2][1] = v01;
                        acc[mt][n2][2] = v10; acc[mt][n2][3] = v11;
                        float2 o0 = {v00, v01}, o1 = {v10, v11};
                        *(float2*)(C + (size_t)row0 * ldc + col)       = o0;
                        *(float2*)(C + (size_t)(row0 + 8) * ldc + col) = o1;
                        if (epi == 5) {
                            s0[mt][0] += v00 + v01; s1[mt][0] += v00 * v00 + v01 * v01;
                            s0[mt][1] += v10 + v11; s1[mt][1] += v10 * v10 + v11 * v11;
                        } else {
                            float as0 = av_s[col], as1 = av_s[col + 1];
                            float ad0 = av_d[col], ad1 = av_d[col + 1];
                            s0[mt][0] += v00 * as0 + v01 * as1;
                            s1[mt][0] += v00 * ad0 + v01 * ad1;
                            s0[mt][1] += v10 * as0 + v11 * as1;
                            s1[mt][1] += v10 * ad0 + v11 * ad1;
                        }
                    }
                }
                #pragma unroll
                for (int off = 1; off <= 2; off <<= 1) {
                    #pragma unroll
                    for (int mt = 0; mt < 2; mt++)
                        #pragma unroll
                        for (int h2 = 0; h2 < 2; h2++) {
                            s0[mt][h2] += __shfl_xor_sync(0xffffffffu, s0[mt][h2], off);
                            s1[mt][h2] += __shfl_xor_sync(0xffffffffu, s1[mt][h2], off);
                        }
                }
                if (c == 0) {
                    #pragma unroll
                    for (int mt = 0; mt < 2; mt++)
                        #pragma unroll
                        for (int h2 = 0; h2 < 2; h2++) {
                            int r = m_base + mt * 16 + g + 8 * h2;
                            sred[wn * 2][r]     = s0[mt][h2];
                            sred[wn * 2 + 1][r] = s1[mt][h2];
                        }
                }
                __syncthreads();
                if (epi == 5) {
                    float mean_[2][2], rs_[2][2];
                    #pragma unroll
                    for (int mt = 0; mt < 2; mt++)
                        #pragma unroll
                        for (int h2 = 0; h2 < 2; h2++) {
                            int r = m_base + mt * 16 + g + 8 * h2;
                            float S = sred[0][r] + sred[2][r];
                            float Q = sred[1][r] + sred[3][r];
                            float m = S * (1.0f / 128.0f);
                            float var = Q * (1.0f / 128.0f) - m * m;
                            mean_[mt][h2] = m;
                            rs_[mt][h2]   = rsqrtf(var + 1e-5f);
                        }
                    #pragma unroll
                    for (int mt = 0; mt < 2; mt++) {
                        int row0 = M0 + m_base + mt * 16 + g;
                        #pragma unroll
                        for (int n2 = 0; n2 < 8; n2++) {
                            int col = col0 + n_base + n2 * 8 + 2 * c;
                            float g0 = lng[col], g1 = lng[col + 1];
                            float be0 = lnb[col], be1 = lnb[col + 1];
                            float l00 = (acc[mt][n2][0] - mean_[mt][0]) * rs_[mt][0] * g0 + be0;
                            float l01 = (acc[mt][n2][1] - mean_[mt][0]) * rs_[mt][0] * g1 + be1;
                            float l10 = (acc[mt][n2][2] - mean_[mt][1]) * rs_[mt][1] * g0 + be0;
                            float l11 = (acc[mt][n2][3] - mean_[mt][1]) * rs_[mt][1] * g1 + be1;
                            __nv_bfloat162 h0, lo0, h1, lo1;
                            split1(l00, h0.x, lo0.x); split1(l01, h0.y, lo0.y);
                            split1(l10, h1.x, lo1.x); split1(l11, h1.y, lo1.y);
                            *(__nv_bfloat162*)(Chi + (size_t)row0 * 128 + col)       = h0;
                            *(__nv_bfloat162*)(Clo + (size_t)row0 * 128 + col)       = lo0;
                            *(__nv_bfloat162*)(Chi + (size_t)(row0 + 8) * 128 + col) = h1;
                            *(__nv_bfloat162*)(Clo + (size_t)(row0 + 8) * 128 + col) = lo1;
                        }
                    }
                } else {
                    if (wn == 0 && c == 0) {
                        #pragma unroll
                        for (int mt = 0; mt < 2; mt++)
                            #pragma unroll
                            for (int h2 = 0; h2 < 2; h2++) {
                                int r = m_base + mt * 16 + g + 8 * h2;
                                as_out[M0 + r] = sred[0][r] + sred[2][r];
                                ad_out[M0 + r] = sred[1][r] + sred[3][r];
                            }
                    }
                }
            } else {
                epilogue_tile(acc, M0, col0, m_base, n_base, g, c,
                              bias, C, Chi, Clo, ldc, res, epi);
            }
        }
    }
}

// ---------------- ff2 GEMM: single-bf16 A (K=512), split W, 2-term ------------
__global__ void __launch_bounds__(256, 2)
gemm_ff2_kernel(const __nv_bfloat16* __restrict__ A, int K,
                const __nv_bfloat16* __restrict__ Whi,
                const __nv_bfloat16* __restrict__ Wlo,
                const float* __restrict__ bias,
                __nv_bfloat16* __restrict__ Chi, __nv_bfloat16* __restrict__ Clo,
                const float* __restrict__ res) {
    extern __shared__ __nv_bfloat16 sm[];
    uint32_t u0 = smem_u32(sm);

    int t    = threadIdx.x;
    int wid  = t >> 5, lane = t & 31;
    int g    = lane >> 2;
    int c    = lane & 3;
    int M0   = blockIdx.x * 128;
    int wm   = wid >> 1, wn = wid & 1;
    int m_base = wm * 32, n_base = wn * 64;

    int la = lane & 15;
    int ka = (lane >> 4) * 8;
    int lb = (lane & 7) + ((lane >> 4) * 8);
    int kb = ((lane >> 3) & 1) * 8;

    float acc[2][8][4];
    #pragma unroll
    for (int mt = 0; mt < 2; mt++)
        #pragma unroll
        for (int nt = 0; nt < 8; nt++)
            #pragma unroll
            for (int q = 0; q < 4; q++) acc[mt][nt][q] = 0.f;

    int nch = K / KCH;
    // 3 arrays x 512 segs = 1536 segments (6 per thread)
    auto copy_chunk = [&](int kc, int stg) {
        uint32_t sbase = u0 + stg * FF2_STAGE_B;
        #pragma unroll
        for (int it = 0; it < 6; it++) {
            int idx  = it * 256 + t;
            int arr  = idx >> 9;              // 0=A, 1=Whi, 2=Wlo
            int row  = (idx >> 2) & 127;
            int seg8 = (idx & 3) * 8;
            const __nv_bfloat16* src;
            if      (arr == 0) src = A   + (size_t)(M0 + row) * K + kc + seg8;
            else if (arr == 1) src = Whi + (size_t)row * K + kc + seg8;
            else               src = Wlo + (size_t)row * K + kc + seg8;
            cp16(sbase + ((arr * 128 + row) * SLD + seg8) * 2, src);
        }
        CP_COMMIT();
    };

    copy_chunk(0, 0);
    for (int ch = 0; ch < nch; ch++) {
        int cur = ch & 1;
        if (ch + 1 < nch) { copy_chunk((ch + 1) * KCH, cur ^ 1); CP_WAIT(1); }
        else              { CP_WAIT(0); }
        __syncthreads();

        uint32_t base = u0 + cur * FF2_STAGE_B;
        #pragma unroll
        for (int kk = 0; kk < KCH; kk += 16) {
            uint32_t ah0[4], ah1[4];
            uint32_t aoff0 = ((m_base + la) * SLD + ka + kk) * 2;
            uint32_t aoff1 = ((m_base + 16 + la) * SLD + ka + kk) * 2;
            ldsm4(ah0, base + aoff0);
            ldsm4(ah1, base + aoff1);
            #pragma unroll
            for (int np = 0; np < 4; np++) {
                uint32_t bh[4], bl[4];
                uint32_t boff = ((n_base + np * 16 + lb) * SLD + kb + kk) * 2;
                ldsm4(bh, base + 1 * 128 * SLD * 2 + boff);
                ldsm4(bl, base + 2 * 128 * SLD * 2 + boff);
                int n0 = 2 * np, n1 = 2 * np + 1;
                mma16816(acc[0][n0], ah0, bh);
                mma16816(acc[0][n0], ah0, bl);
                mma16816(acc[0][n1], ah0, bh + 2);
                mma16816(acc[0][n1], ah0, bl + 2);
                mma16816(acc[1][n0], ah1, bh);
                mma16816(acc[1][n0], ah1, bl);
                mma16816(acc[1][n1], ah1, bh + 2);
                mma16816(acc[1][n1], ah1, bl + 2);
            }
        }
        __syncthreads();
    }
    // epi 4: +bias, +res, split write
    epilogue_tile(acc, M0, 0, m_base, n_base, g, c,
                  bias, nullptr, Chi, Clo, 128, res, 4);
}

// ---------------- LayerNorm: fp32 in -> bf16 split out (LN1 only) ------------
__global__ void __launch_bounds__(256)
ln_kernel(const float* __restrict__ in,
          __nv_bfloat16* __restrict__ ohi, __nv_bfloat16* __restrict__ olo,
          const float* __restrict__ g, const float* __restrict__ b) {
    int warp = threadIdx.x >> 5, lane = threadIdx.x & 31;
    size_t row = (size_t)blockIdx.x * 8 + warp;
    float4 v = *(const float4*)(in + row * 128 + lane * 4);
    float s  = v.x + v.y + v.z + v.w;
    float ss = v.x * v.x + v.y * v.y + v.z * v.z + v.w * v.w;
    #pragma unroll
    for (int o = 16; o; o >>= 1) {
        s  += __shfl_xor_sync(0xffffffffu, s, o);
        ss += __shfl_xor_sync(0xffffffffu, ss, o);
    }
    float m   = s * (1.0f / 128.0f);
    float var = ss * (1.0f / 128.0f) - m * m;
    float rs  = rsqrtf(var + 1e-5f);
    float4 gg = *(const float4*)(g + lane * 4);
    float4 bb = *(const float4*)(b + lane * 4);
    float o0 = (v.x - m) * rs * gg.x + bb.x;
    float o1 = (v.y - m) * rs * gg.y + bb.y;
    float o2 = (v.z - m) * rs * gg.z + bb.z;
    float o3 = (v.w - m) * rs * gg.w + bb.w;
    __nv_bfloat162 h01, l01, h23, l23;
    split1(o0, h01.x, l01.x); split1(o1, h01.y, l01.y);
    split1(o2, h23.x, l23.x); split1(o3, h23.y, l23.y);
    *(__nv_bfloat162*)(ohi + row * 128 + lane * 4)     = h01;
    *(__nv_bfloat162*)(ohi + row * 128 + lane * 4 + 2) = h23;
    *(__nv_bfloat162*)(olo + row * 128 + lane * 4)     = l01;
    *(__nv_bfloat162*)(olo + row * 128 + lane * 4 + 2) = l23;
}

// ---------------- attention (per node, fp32 in, bf16 split out) -------------
__global__ void __launch_bounds__(256)
attn_kernel() {
    extern __shared__ float s[];
    float* sq  = s;
    float* sk  = s + 32 * ATS;
    float* sv  = s + 64 * ATS;
    float* ssc = s + 96 * ATS;
    int node = blockIdx.x, t = threadIdx.x;
    const float* qg = g_qkv + (size_t)node * 32 * 384;

    for (int i = t; i < 1024; i += 256) {
        int l = i >> 5, c4 = (i & 31) * 4;
        *(float4*)(sq + l * ATS + c4) = *(const float4*)(qg + l * 384 + c4);
        *(float4*)(sk + l * ATS + c4) = *(const float4*)(qg + l * 384 + 128 + c4);
        *(float4*)(sv + l * ATS + c4) = *(const float4*)(qg + l * 384 + 256 + c4);
    }
    __syncthreads();

    {   // scores
        int i = t >> 3, j0 = (t & 7) * 4;
        float acc[4] = {0.f, 0.f, 0.f, 0.f};
        #pragma unroll 4
        for (int d = 0; d < 128; d += 4) {
            float4 q = *(const float4*)(sq + i * ATS + d);
            #pragma unroll
            for (int jj = 0; jj < 4; jj++) {
                float4 k4 = *(const float4*)(sk + (j0 + jj) * ATS + d);
                acc[jj] += q.x * k4.x + q.y * k4.y + q.z * k4.z + q.w * k4.w;
            }
        }
        const float scale = 0.08838834764831845f;
        #pragma unroll
        for (int jj = 0; jj < 4; jj++) ssc[i * 32 + j0 + jj] = acc[jj] * scale;
    }
    __syncthreads();
    {   // softmax
        int warp = t >> 5, lane = t & 31;
        for (int r = warp; r < 32; r += 8) {
            float v = ssc[r * 32 + lane];
            float mx = v;
            #pragma unroll
            for (int o = 16; o; o >>= 1) mx = fmaxf(mx, __shfl_xor_sync(0xffffffffu, mx, o));
            float e = expf(v - mx);
            float sm2 = e;
            #pragma unroll
            for (int o = 16; o; o >>= 1) sm2 += __shfl_xor_sync(0xffffffffu, sm2, o);
            ssc[r * 32 + lane] = e / sm2;
        }
    }
    __syncthreads();
    {   // attn = a @ v -> split bf16
        int i = t >> 3, d0 = (t & 7) * 4;
        float acc[4][4];
        #pragma unroll
        for (int q = 0; q < 4; q++)
            #pragma unroll
            for (int e = 0; e < 4; e++) acc[q][e] = 0.f;
        for (int j = 0; j < 32; j++) {
            float a = ssc[i * 32 + j];
            const float* vr = sv + j * ATS + d0;
            #pragma unroll
            for (int q = 0; q < 4; q++) {
                float4 v4 = *(const float4*)(vr + q * 32);
                acc[q][0] += a * v4.x; acc[q][1] += a * v4.y;
                acc[q][2] += a * v4.z; acc[q][3] += a * v4.w;
            }
        }
        size_t base = ((size_t)node * 32 + i) * 128 + d0;
        #pragma unroll
        for (int q = 0; q < 4; q++) {
            __nv_bfloat162 h0, l0, h1, l1;
            split1(acc[q][0], h0.x, l0.x); split1(acc[q][1], h0.y, l0.y);
            split1(acc[q][2], h1.x, l1.x); split1(acc[q][3], h1.y, l1.y);
            *(__nv_bfloat162*)(g_b1hi + base + q * 32)     = h0;
            *(__nv_bfloat162*)(g_b1hi + base + q * 32 + 2) = h1;
            *(__nv_bfloat162*)(g_b1lo + base + q * 32)     = l0;
            *(__nv_bfloat162*)(g_b1lo + base + q * 32 + 2) = l1;
        }
    }
}

// ---------------- edge dtype detection + CSR build ---------------------------
__global__ void zero_counts_kernel() {
    int i = blockIdx.x * blockDim.x + threadIdx.x;
    if (i < K_NODES) { g_cnt[i] = 0; g_cur[i] = 0; }
    if (i == 0) g_is32 = 0;
}
__global__ void detect_dtype_kernel(const int* __restrict__ ei32) {
    int i = blockIdx.x * blockDim.x + threadIdx.x;
    if (i < N_EDGES && ei32[2 * i + 1] != 0) atomicExch(&g_is32, 1);
}
__device__ __forceinline__ int load_idx(const int* __restrict__ ei32, int elem) {
    return g_is32 ? ei32[elem] : ei32[2 * elem];
}
__global__ void count_edges_kernel(const int* __restrict__ ei32) {
    int e = blockIdx.x * blockDim.x + threadIdx.x;
    if (e >= N_TOT_EDGES) return;
    int dst = (e < N_EDGES) ? load_idx(ei32, N_EDGES + e) : (e - N_EDGES);
    if ((unsigned)dst >= K_NODES) return;
    atomicAdd(&g_cnt[dst], 1);
}
__global__ void scan_kernel() {
    __shared__ int ts[1024];
    int t = threadIdx.x;
    int c[4], s = 0;
    #pragma unroll
    for (int i = 0; i < 4; i++) { c[i] = s; s += g_cnt[t * 4 + i]; }
    ts[t] = s;
    __syncthreads();
    for (int o = 1; o < 1024; o <<= 1) {
        int v = (t >= o) ? ts[t - o] : 0;
        __syncthreads();
        ts[t] += v;
        __syncthreads();
    }
    int base = (t == 0) ? 0 : ts[t - 1];
    #pragma unroll
    for (int i = 0; i < 4; i++) g_off[t * 4 + i] = base + c[i];
    if (t == 1023) g_off[4096] = ts[1023];
}
__global__ void fill_edges_kernel(const int* __restrict__ ei32) {
    int e = blockIdx.x * blockDim.x + threadIdx.x;
    if (e >= N_TOT_EDGES) return;
    int src, dst;
    if (e < N_EDGES) {
        src = load_idx(ei32, e);
        dst = load_idx(ei32, N_EDGES + e);
    } else {
        src = dst = e - N_EDGES;
    }
    if ((unsigned)dst >= K_NODES || (unsigned)src >= K_NODES) return;
    int pos = atomicAdd(&g_cur[dst], 1);
    g_csr_src[g_off[dst] + pos] = src;
}

// ---------------- GAT aggregation: one block per dst node --------------------
__global__ void __launch_bounds__(256)
gat_aggregate_kernel(const float* __restrict__ gat_b, float* __restrict__ out) {
    __shared__ float sm_m[32], sm_d[32];
    __shared__ float part[8][32];
    __shared__ float s_alpha[64][33];
    __shared__ int   s_src[64];
    int dst = blockIdx.x, t = threadIdx.x;
    int off0 = g_off[dst], ne = g_cur[dst];

    {   // phase A: per-l max
        int l = t & 31, grp = t >> 5;
        float adl = g_ad[dst * 32 + l];
        float lm = -3.4e38f;
        for (int e = grp; e < ne; e += 8) {
            int src = g_csr_src[off0 + e];
            float v = g_as[src * 32 + l] + adl;
            v = v > 0.f ? v : 0.2f * v;
            lm = fmaxf(lm, v);
        }
        part[grp][l] = lm;
        __syncthreads();
        if (t < 32) {
            float m = part[0][t];
            #pragma unroll
            for (int g2 = 1; g2 < 8; g2++) m = fmaxf(m, part[g2][t]);
            sm_m[t] = m;
        }
        __syncthreads();
    }
    {   // phase B: denom
        int l = t & 31, grp = t >> 5;
        float adl = g_ad[dst * 32 + l];
        float m = sm_m[l], sden = 0.f;
        for (int e = grp; e < ne; e += 8) {
            int src = g_csr_src[off0 + e];
            float v = g_as[src * 32 + l] + adl;
            v = v > 0.f ? v : 0.2f * v;
            sden += expf(v - m);
        }
        __syncthreads();
        part[grp][l] = sden;
        __syncthreads();
        if (t < 32) {
            float s2 = 0.f;
            #pragma unroll
            for (int g2 = 0; g2 < 8; g2++) s2 += part[g2][t];
            sm_d[t] = s2;
        }
        __syncthreads();
    }
    {   // phase C: chunked alpha staging + weighted aggregation
        int l = t >> 3, d0 = (t & 7) * 16;
        float acc[16];
        #pragma unroll
        for (int i = 0; i < 16; i++) acc[i] = 0.f;

        for (int e0 = 0; e0 < ne; e0 += 64) {
            int ecnt = min(64, ne - e0);
            __syncthreads();
            if (t < ecnt) s_src[t] = g_csr_src[off0 + e0 + t];
            __syncthreads();
            for (int idx = t; idx < ecnt * 32; idx += 256) {
                int e = idx >> 5, ll = idx & 31;
                float v = g_as[s_src[e] * 32 + ll] + g_ad[dst * 32 + ll];
                v = v > 0.f ? v : 0.2f * v;
                s_alpha[e][ll] = expf(v - sm_m[ll]);
            }
            __syncthreads();
            for (int e = 0; e < ecnt; e++) {
                float ex = s_alpha[e][l];
                const float4* hp =
                    (const float4*)(g_h + ((size_t)s_src[e] * 32 + l) * 128 + d0);
                #pragma unroll
                for (int q = 0; q < 4; q++) {
                    float4 h4 = hp[q];
                    acc[q * 4 + 0] += ex * h4.x;
                    acc[q * 4 + 1] += ex * h4.y;
                    acc[q * 4 + 2] += ex * h4.z;
                    acc[q * 4 + 3] += ex * h4.w;
                }
            }
        }

        float inv = 1.f / (sm_d[l] + 1e-16f);
        float* op = out + ((size_t)dst * 32 + l) * 128 + d0;
        #pragma unroll
        for (int q = 0; q < 4; q++) {
            float4 o4;
            o4.x = acc[q * 4 + 0] * inv + gat_b[d0 + q * 4 + 0];
            o4.y = acc[q * 4 + 1] * inv + gat_b[d0 + q * 4 + 1];
            o4.z = acc[q * 4 + 2] * inv + gat_b[d0 + q * 4 + 2];
            o4.w = acc[q * 4 + 3] * inv + gat_b[d0 + q * 4 + 3];
            ((float4*)op)[q] = o4;
        }
    }
}

// ---------------- launch ------------------------------------------------------
extern "C" void kernel_launch(void* const* d_in, const int* in_sizes, int n_in,
                              void* d_out, int out_size) {
    const float* x     = (const float*)d_in[0];
    const int*   ei32  = (const int*)d_in[1];
    const float* ln1_g = (const float*)d_in[2];
    const float* ln1_b = (const float*)d_in[3];
    const float* qkv_w = (const float*)d_in[4];
    const float* qkv_b = (const float*)d_in[5];
    const float* out_w = (const float*)d_in[6];
    const float* out_b = (const float*)d_in[7];
    const float* ln2_g = (const float*)d_in[8];
    const float* ln2_b = (const float*)d_in[9];
    const float* ff1_w = (const float*)d_in[10];
    const float* ff1_b = (const float*)d_in[11];
    const float* ff2_w = (const float*)d_in[12];
    const float* ff2_b = (const float*)d_in[13];
    const float* gat_w = (const float*)d_in[14];
    const float* att_s = (const float*)d_in[15];
    const float* att_d = (const float*)d_in[16];
    const float* gat_b = (const float*)d_in[17];
    float* out = (float*)d_out;

    float *p_qkv, *p_x2, *p_h, *p_as, *p_ad;
    __nv_bfloat16 *p_b1hi, *p_b1lo, *p_b2hi, *p_whi, *p_wlo;
    cudaGetSymbolAddress((void**)&p_qkv,  g_qkv);
    cudaGetSymbolAddress((void**)&p_x2,   g_x2);
    cudaGetSymbolAddress((void**)&p_h,    g_h);
    cudaGetSymbolAddress((void**)&p_as,   g_as);
    cudaGetSymbolAddress((void**)&p_ad,   g_ad);
    cudaGetSymbolAddress((void**)&p_b1hi, g_b1hi);
    cudaGetSymbolAddress((void**)&p_b1lo, g_b1lo);
    cudaGetSymbolAddress((void**)&p_b2hi, g_b2hi);
    cudaGetSymbolAddress((void**)&p_whi,  g_whi);
    cudaGetSymbolAddress((void**)&p_wlo,  g_wlo);

    const int FF2_SMEM = 2 * FF2_STAGE_B;   // 61440 B
    const int ATTN_SMEM = (96 * ATS + 1024) * 4;
    cudaFuncSetAttribute(gemm_ff2_kernel,
                         cudaFuncAttributeMaxDynamicSharedMemorySize, FF2_SMEM);
    cudaFuncSetAttribute(gemm_ares_kernel,
                         cudaFuncAttributeMaxDynamicSharedMemorySize, ARES_SMEM);
    cudaFuncSetAttribute(attn_kernel,
                         cudaFuncAttributeMaxDynamicSharedMemorySize, ATTN_SMEM);

    // 1. weight splits
    split_w_kernel<<<(W_TOTAL + 255) / 256, 256>>>(qkv_w, out_w, ff1_w, ff2_w, gat_w);
    // 2. LN1 -> b1 split
    ln_kernel<<<MM / 8, 256>>>(x, p_b1hi, p_b1lo, ln1_g, ln1_b);
    // 3. CSR zero
    zero_counts_kernel<<<(K_NODES + 255) / 256, 256>>>();
    // 4. qkv GEMM (A-resident, NT=3)  (ncu slot)
    gemm_ares_kernel<<<MM / 128, 256, ARES_SMEM>>>(
        p_b1hi, p_b1lo, p_whi + WOFF_QKV, p_wlo + WOFF_QKV, 128,
        qkv_b, p_qkv, nullptr, nullptr, 384, nullptr, 0, 3,
        nullptr, nullptr, nullptr, nullptr, nullptr, nullptr);
    // 5-6. CSR detect/count
    detect_dtype_kernel<<<(N_EDGES + 255) / 256, 256>>>(ei32);
    count_edges_kernel<<<(N_TOT_EDGES + 255) / 256, 256>>>(ei32);
    // 7. attention -> b1 split
    attn_kernel<<<K_NODES, 256, ATTN_SMEM>>>();
    // 8. out-proj + residual -> x2 fp32 AND fused LN2 -> b1 split (epi 5)
    gemm_ares_kernel<<<MM / 128, 256, ARES_SMEM>>>(
        p_b1hi, p_b1lo, p_whi + WOFF_OUT, p_wlo + WOFF_OUT, 128,
        out_b, p_x2, p_b1hi, p_b1lo, 128, x, 5, 1,
        ln2_g, ln2_b, nullptr, nullptr, nullptr, nullptr);
    // 9. CSR scan
    scan_kernel<<<1, 1024>>>();
    // 10. ff1 + gelu -> b2 single bf16 (NT=4, epi 1 with Clo=nullptr)
    gemm_ares_kernel<<<MM / 128, 256, ARES_SMEM>>>(
        p_b1hi, p_b1lo, p_whi + WOFF_FF1, p_wlo + WOFF_FF1, 128,
        ff1_b, nullptr, p_b2hi, nullptr, 512, nullptr, 1, 4,
        nullptr, nullptr, nullptr, nullptr, nullptr, nullptr);
    // 11. ff2 + residual -> xt (b1 split), single-A 2-term kernel
    gemm_ff2_kernel<<<MM / 128, 256, FF2_SMEM>>>(
        p_b2hi, 512, p_whi + WOFF_FF2, p_wlo + WOFF_FF2,
        ff2_b, p_b1hi, p_b1lo, p_x2);
    // 12. GAT transform -> h fp32 AND fused a_src/a_dst (epi 6)
    gemm_ares_kernel<<<MM / 128, 256, ARES_SMEM>>>(
        p_b1hi, p_b1lo, p_whi + WOFF_GAT, p_wlo + WOFF_GAT, 128,
        nullptr, p_h, nullptr, nullptr, 128, nullptr, 6, 1,
        nullptr, nullptr, att_s, att_d, p_as, p_ad);
    // 13. CSR fill
    fill_edges_kernel<<<(N_TOT_EDGES + 255) / 256, 256>>>(ei32);
    // 14. aggregate
    gat_aggregate_kernel<<<K_NODES, 256>>>(gat_b, out);
}

// round 17
// speedup vs baseline: 4.3762x; 1.0539x over previous
#include <cuda_runtime.h>
#include <cuda_bf16.h>
#include <cstdint>
#include <math.h>

#define K_NODES 4096
#define SEQ_L   32
#define D_MODEL 128
#define D_FF    512
#define N_EDGES 65536
#define N_TOT_EDGES (N_EDGES + K_NODES)
#define MM (K_NODES * SEQ_L)           // 131072 rows

// ff2 single-A streaming GEMM params
#define KCH  32
#define SLD  40
#define FF2_STAGE_B (3 * 128 * SLD * 2) // 30720 B per stage

// A-resident GEMM params
#define SLDA 136
#define KCHB 32
#define SLDB 40
#define BSTG_B  (2 * 128 * SLDB * 2)    // 20480 per stage
#define ABYTES_1 (128 * SLDA * 2)       // 34816 (single A)
#define ABYTES_2 (2 * 128 * SLDA * 2)   // 69632 (split A)
#define ARES_SMEM_1 (ABYTES_1 + 2 * BSTG_B)  // 75776
#define ARES_SMEM_2 (ABYTES_2 + 2 * BSTG_B)  // 110592

// attn smem stride
#define ATS 132

// weight segment offsets
#define WOFF_QKV 0
#define WOFF_OUT 49152
#define WOFF_FF1 65536
#define WOFF_FF2 131072
#define WOFF_GAT 196608
#define W_TOTAL  212992

// ---------------- scratch -----------------------------------------------------
__device__ __nv_bfloat16 g_b1hi[MM * 128], g_b1lo[MM * 128];
__device__ __nv_bfloat16 g_b2hi[MM * 512];
__device__ __nv_bfloat16 g_whi[W_TOTAL],  g_wlo[W_TOTAL];
__device__ float g_qkv[MM * 384];
__device__ float g_x2 [MM * 128];
__device__ float g_h  [MM * 128];
__device__ float g_as[K_NODES * SEQ_L];
__device__ float g_ad[K_NODES * SEQ_L];
__device__ int   g_cnt[K_NODES];
__device__ int   g_cur[K_NODES];
__device__ int   g_off[K_NODES + 1];
__device__ int   g_csr_src[N_TOT_EDGES];
__device__ int   g_is32;

__device__ __forceinline__ float gelu_exact(float v) {
    return 0.5f * v * (1.0f + erff(v * 0.70710678118654752f));
}

__device__ __forceinline__ uint32_t smem_u32(const void* p) {
    uint32_t a;
    asm("{ .reg .u64 t; cvta.to.shared.u64 t, %1; cvt.u32.u64 %0, t; }"
        : "=r"(a) : "l"(p));
    return a;
}

__device__ __forceinline__ void cp16(uint32_t dst, const void* src) {
    asm volatile("cp.async.cg.shared.global [%0], [%1], 16;"
                 :: "r"(dst), "l"(src));
}
#define CP_COMMIT() asm volatile("cp.async.commit_group;" ::: "memory")
#define CP_WAIT(n)  asm volatile("cp.async.wait_group %0;" :: "n"(n) : "memory")

__device__ __forceinline__ void mma16816(float* d,
                                         const uint32_t* a, const uint32_t* b) {
    asm volatile(
        "mma.sync.aligned.m16n8k16.row.col.f32.bf16.bf16.f32 "
        "{%0,%1,%2,%3}, {%4,%5,%6,%7}, {%8,%9}, {%0,%1,%2,%3};"
        : "+f"(d[0]), "+f"(d[1]), "+f"(d[2]), "+f"(d[3])
        : "r"(a[0]), "r"(a[1]), "r"(a[2]), "r"(a[3]), "r"(b[0]), "r"(b[1]));
}

__device__ __forceinline__ void ldsm4(uint32_t* r, uint32_t addr) {
    asm volatile("ldmatrix.sync.aligned.m8n8.x4.shared.b16 {%0,%1,%2,%3}, [%4];"
        : "=r"(r[0]), "=r"(r[1]), "=r"(r[2]), "=r"(r[3]) : "r"(addr));
}

__device__ __forceinline__ void split1(float v, __nv_bfloat16& h, __nv_bfloat16& l) {
    h = __float2bfloat16(v);
    l = __float2bfloat16(v - __bfloat162float(h));
}

// generic epilogue (epi 0..4). epi 1/4 with Clo==nullptr writes single bf16.
__device__ __forceinline__ void epilogue_tile(
    float acc[2][8][4], int M0, int col0, int m_base, int n_base, int g, int c,
    const float* bias, float* C, __nv_bfloat16* Chi, __nv_bfloat16* Clo,
    int ldc, const float* res, int epi) {
    #pragma unroll
    for (int mt = 0; mt < 2; mt++) {
        int row0 = M0 + m_base + mt * 16 + g;
        #pragma unroll
        for (int nt = 0; nt < 8; nt++) {
            int col = col0 + n_base + nt * 8 + 2 * c;
            float b0 = 0.f, b1 = 0.f;
            if (epi != 3) { b0 = bias[col]; b1 = bias[col + 1]; }
            float v00 = acc[mt][nt][0] + b0, v01 = acc[mt][nt][1] + b1;
            float v10 = acc[mt][nt][2] + b0, v11 = acc[mt][nt][3] + b1;
            if (epi == 1) {
                v00 = gelu_exact(v00); v01 = gelu_exact(v01);
                v10 = gelu_exact(v10); v11 = gelu_exact(v11);
            } else if (epi == 2 || epi == 4) {
                float2 ra = *(const float2*)(res + (size_t)row0 * 128 + col);
                float2 rb = *(const float2*)(res + (size_t)(row0 + 8) * 128 + col);
                v00 += ra.x; v01 += ra.y; v10 += rb.x; v11 += rb.y;
            }
            if ((epi == 1 || epi == 4) && Clo == nullptr) {
                __nv_bfloat162 h0, h1;
                h0.x = __float2bfloat16(v00); h0.y = __float2bfloat16(v01);
                h1.x = __float2bfloat16(v10); h1.y = __float2bfloat16(v11);
                *(__nv_bfloat162*)(Chi + (size_t)row0 * ldc + col)       = h0;
                *(__nv_bfloat162*)(Chi + (size_t)(row0 + 8) * ldc + col) = h1;
            } else if (epi == 1 || epi == 4) {
                __nv_bfloat162 h0, l0, h1, l1;
                split1(v00, h0.x, l0.x); split1(v01, h0.y, l0.y);
                split1(v10, h1.x, l1.x); split1(v11, h1.y, l1.y);
                *(__nv_bfloat162*)(Chi + (size_t)row0 * ldc + col)       = h0;
                *(__nv_bfloat162*)(Clo + (size_t)row0 * ldc + col)       = l0;
                *(__nv_bfloat162*)(Chi + (size_t)(row0 + 8) * ldc + col) = h1;
                *(__nv_bfloat162*)(Clo + (size_t)(row0 + 8) * ldc + col) = l1;
            } else {
                float2 o0 = {v00, v01}, o1 = {v10, v11};
                *(float2*)(C + (size_t)row0 * ldc + col)       = o0;
                *(float2*)(C + (size_t)(row0 + 8) * ldc + col) = o1;
            }
        }
    }
}

// ---------------- weight split ------------------------------------------------
__global__ void split_w_kernel(const float* __restrict__ w0, const float* __restrict__ w1,
                               const float* __restrict__ w2, const float* __restrict__ w3,
                               const float* __restrict__ w4) {
    int i = blockIdx.x * 256 + threadIdx.x;
    if (i >= W_TOTAL) return;
    const float* src; int off;
    if      (i < WOFF_OUT) { src = w0; off = WOFF_QKV; }
    else if (i < WOFF_FF1) { src = w1; off = WOFF_OUT; }
    else if (i < WOFF_FF2) { src = w2; off = WOFF_FF1; }
    else if (i < WOFF_GAT) { src = w3; off = WOFF_FF2; }
    else                   { src = w4; off = WOFF_GAT; }
    float v = src[i - off];
    __nv_bfloat16 h, l;
    split1(v, h, l);
    g_whi[i] = h; g_wlo[i] = l;
}

// ---------------- A-resident tensor-core GEMM (K = 128) ----------------------
// SPLITA=1: A hi+lo (3-term). SPLITA=0: A single (2-term).
// epi: 0=+bias fp32; 1=+bias,gelu->bf16(single if Clo null); 2=+bias,+res fp32;
//      3=none fp32; 4=+bias,+res->bf16; 5=+bias,+res fp32 C AND LN->bf16;
//      6=none fp32 C AND row-dots -> as_out/ad_out.
template <int SPLITA>
__global__ void __launch_bounds__(256, 2)
gemm_ares_kernel(const __nv_bfloat16* __restrict__ Ahi,
                 const __nv_bfloat16* __restrict__ Alo,
                 const __nv_bfloat16* __restrict__ Whi,
                 const __nv_bfloat16* __restrict__ Wlo, int Kw,
                 const float* __restrict__ bias,
                 float* __restrict__ C,
                 __nv_bfloat16* __restrict__ Chi, __nv_bfloat16* __restrict__ Clo,
                 int ldc, const float* __restrict__ res, int epi, int NT,
                 const float* __restrict__ lng, const float* __restrict__ lnb,
                 const float* __restrict__ av_s, const float* __restrict__ av_d,
                 float* __restrict__ as_out, float* __restrict__ ad_out) {
    extern __shared__ __nv_bfloat16 sm[];
    __shared__ float sred[4][128];
    const int ABYTES = SPLITA ? ABYTES_2 : ABYTES_1;
    uint32_t uA = smem_u32(sm);
    uint32_t uB = uA + ABYTES;

    int t    = threadIdx.x;
    int wid  = t >> 5, lane = t & 31;
    int g    = lane >> 2;
    int c    = lane & 3;
    int M0   = blockIdx.x * 128;
    int wm   = wid >> 1, wn = wid & 1;
    int m_base = wm * 32, n_base = wn * 64;

    int la = lane & 15;
    int ka = (lane >> 4) * 8;
    int lb = (lane & 7) + ((lane >> 4) * 8);
    int kb = ((lane >> 3) & 1) * 8;

    // ---- load A: 2048 segs (hi) + 2048 (lo if split)
    #pragma unroll
    for (int it = 0; it < (SPLITA ? 16 : 8); it++) {
        int idx  = it * 256 + t;
        int arr  = idx >> 11;
        int row  = (idx >> 4) & 127;
        int s8   = (idx & 15) * 8;
        const __nv_bfloat16* src =
            (arr ? Alo : Ahi) + (size_t)(M0 + row) * 128 + s8;
        cp16(uA + arr * 128 * SLDA * 2 + (row * SLDA + s8) * 2, src);
    }
    CP_COMMIT();

    auto copyB = [&](int ci, int stg) {
        int col0 = (ci >> 2) * 128;
        int kc   = (ci & 3) * KCHB;
        uint32_t base = uB + stg * BSTG_B;
        #pragma unroll
        for (int it = 0; it < 4; it++) {
            int idx = it * 256 + t;
            int arr = idx >> 9;
            int row = (idx >> 2) & 127;
            int s8  = (idx & 3) * 8;
            const __nv_bfloat16* src =
                (arr ? Wlo : Whi) + (size_t)(col0 + row) * Kw + kc + s8;
            cp16(base + arr * 128 * SLDB * 2 + (row * SLDB + s8) * 2, src);
        }
        CP_COMMIT();
    };

    int total = NT * 4;
    copyB(0, 0);

    float acc[2][8][4];
    for (int ci = 0; ci < total; ci++) {
        int stg = ci & 1;
        __syncthreads();
        if (ci + 1 < total) copyB(ci + 1, stg ^ 1);
        else                CP_COMMIT();
        CP_WAIT(1);
        __syncthreads();

        if ((ci & 3) == 0) {
            #pragma unroll
            for (int mt = 0; mt < 2; mt++)
                #pragma unroll
                for (int n2 = 0; n2 < 8; n2++)
                    #pragma unroll
                    for (int q = 0; q < 4; q++) acc[mt][n2][q] = 0.f;
        }

        uint32_t bbase = uB + stg * BSTG_B;
        #pragma unroll
        for (int kk2 = 0; kk2 < KCHB; kk2 += 16) {
            int kk = (ci & 3) * KCHB + kk2;
            uint32_t ah0[4], ah1[4], al0[4], al1[4];
            uint32_t aoff0 = ((m_base + la) * SLDA + ka + kk) * 2;
            uint32_t aoff1 = ((m_base + 16 + la) * SLDA + ka + kk) * 2;
            ldsm4(ah0, uA + aoff0);
            ldsm4(ah1, uA + aoff1);
            if (SPLITA) {
                ldsm4(al0, uA + 128 * SLDA * 2 + aoff0);
                ldsm4(al1, uA + 128 * SLDA * 2 + aoff1);
            }
            #pragma unroll
            for (int np = 0; np < 4; np++) {
                uint32_t bh[4], bl[4];
                uint32_t boff = ((n_base + np * 16 + lb) * SLDB + kb + kk2) * 2;
                ldsm4(bh, bbase + boff);
                ldsm4(bl, bbase + 128 * SLDB * 2 + boff);
                int n0 = 2 * np, n1 = 2 * np + 1;
                mma16816(acc[0][n0], ah0, bh);
                mma16816(acc[0][n0], ah0, bl);
                mma16816(acc[0][n1], ah0, bh + 2);
                mma16816(acc[0][n1], ah0, bl + 2);
                mma16816(acc[1][n0], ah1, bh);
                mma16816(acc[1][n0], ah1, bl);
                mma16816(acc[1][n1], ah1, bh + 2);
                mma16816(acc[1][n1], ah1, bl + 2);
                if (SPLITA) {
                    mma16816(acc[0][n0], al0, bh);
                    mma16816(acc[0][n1], al0, bh + 2);
                    mma16816(acc[1][n0], al1, bh);
                    mma16816(acc[1][n1], al1, bh + 2);
                }
            }
        }

        if ((ci & 3) == 3) {
            int col0 = (ci >> 2) * 128;
            if (epi == 5 || epi == 6) {
                float s0[2][2] = {{0.f,0.f},{0.f,0.f}};
                float s1[2][2] = {{0.f,0.f},{0.f,0.f}};
                #pragma unroll
                for (int mt = 0; mt < 2; mt++) {
                    int row0 = M0 + m_base + mt * 16 + g;
                    #pragma unroll
                    for (int n2 = 0; n2 < 8; n2++) {
                        int col = col0 + n_base + n2 * 8 + 2 * c;
                        float b0 = 0.f, b1 = 0.f;
                        if (epi == 5) { b0 = bias[col]; b1 = bias[col + 1]; }
                        float v00 = acc[mt][n2][0] + b0, v01 = acc[mt][n2][1] + b1;
                        float v10 = acc[mt][n2][2] + b0, v11 = acc[mt][n2][3] + b1;
                        if (epi == 5) {
                            float2 ra = *(const float2*)(res + (size_t)row0 * 128 + col);
                            float2 rb = *(const float2*)(res + (size_t)(row0 + 8) * 128 + col);
                            v00 += ra.x; v01 += ra.y; v10 += rb.x; v11 += rb.y;
                        }
                        acc[mt][n2][0] = v00; acc[mt][n2][1] = v01;
                        acc[mt][n2][2] = v10; acc[mt][n2][3] = v11;
                        float2 o0 = {v00, v01}, o1 = {v10, v11};
                        *(float2*)(C + (size_t)row0 * ldc + col)       = o0;
                        *(float2*)(C + (size_t)(row0 + 8) * ldc + col) = o1;
                        if (epi == 5) {
                            s0[mt][0] += v00 + v01; s1[mt][0] += v00 * v00 + v01 * v01;
                            s0[mt][1] += v10 + v11; s1[mt][1] += v10 * v10 + v11 * v11;
                        } else {
                            float as0 = av_s[col], as1 = av_s[col + 1];
                            float ad0 = av_d[col], ad1 = av_d[col + 1];
                            s0[mt][0] += v00 * as0 + v01 * as1;
                            s1[mt][0] += v00 * ad0 + v01 * ad1;
                            s0[mt][1] += v10 * as0 + v11 * as1;
                            s1[mt][1] += v10 * ad0 + v11 * ad1;
                        }
                    }
                }
                #pragma unroll
                for (int off = 1; off <= 2; off <<= 1) {
                    #pragma unroll
                    for (int mt = 0; mt < 2; mt++)
                        #pragma unroll
                        for (int h2 = 0; h2 < 2; h2++) {
                            s0[mt][h2] += __shfl_xor_sync(0xffffffffu, s0[mt][h2], off);
                            s1[mt][h2] += __shfl_xor_sync(0xffffffffu, s1[mt][h2], off);
                        }
                }
                if (c == 0) {
                    #pragma unroll
                    for (int mt = 0; mt < 2; mt++)
                        #pragma unroll
                        for (int h2 = 0; h2 < 2; h2++) {
                            int r = m_base + mt * 16 + g + 8 * h2;
                            sred[wn * 2][r]     = s0[mt][h2];
                            sred[wn * 2 + 1][r] = s1[mt][h2];
                        }
                }
                __syncthreads();
                if (epi == 5) {
                    float mean_[2][2], rs_[2][2];
                    #pragma unroll
                    for (int mt = 0; mt < 2; mt++)
                        #pragma unroll
                        for (int h2 = 0; h2 < 2; h2++) {
                            int r = m_base + mt * 16 + g + 8 * h2;
                            float S = sred[0][r] + sred[2][r];
                            float Q = sred[1][r] + sred[3][r];
                            float m = S * (1.0f / 128.0f);
                            float var = Q * (1.0f / 128.0f) - m * m;
                            mean_[mt][h2] = m;
                            rs_[mt][h2]   = rsqrtf(var + 1e-5f);
                        }
                    #pragma unroll
                    for (int mt = 0; mt < 2; mt++) {
                        int row0 = M0 + m_base + mt * 16 + g;
                        #pragma unroll
                        for (int n2 = 0; n2 < 8; n2++) {
                            int col = col0 + n_base + n2 * 8 + 2 * c;
                            float g0 = lng[col], g1 = lng[col + 1];
                            float be0 = lnb[col], be1 = lnb[col + 1];
                            float l00 = (acc[mt][n2][0] - mean_[mt][0]) * rs_[mt][0] * g0 + be0;
                            float l01 = (acc[mt][n2][1] - mean_[mt][0]) * rs_[mt][0] * g1 + be1;
                            float l10 = (acc[mt][n2][2] - mean_[mt][1]) * rs_[mt][1] * g0 + be0;
                            float l11 = (acc[mt][n2][3] - mean_[mt][1]) * rs_[mt][1] * g1 + be1;
                            __nv_bfloat162 h0, h1;
                            h0.x = __float2bfloat16(l00); h0.y = __float2bfloat16(l01);
                            h1.x = __float2bfloat16(l10); h1.y = __float2bfloat16(l11);
                            *(__nv_bfloat162*)(Chi + (size_t)row0 * 128 + col)       = h0;
                            *(__nv_bfloat162*)(Chi + (size_t)(row0 + 8) * 128 + col) = h1;
                        }
                    }
                } else {
                    if (wn == 0 && c == 0) {
                        #pragma unroll
                        for (int mt = 0; mt < 2; mt++)
                            #pragma unroll
                            for (int h2 = 0; h2 < 2; h2++) {
                                int r = m_base + mt * 16 + g + 8 * h2;
                                as_out[M0 + r] = sred[0][r] + sred[2][r];
                                ad_out[M0 + r] = sred[1][r] + sred[3][r];
                            }
                    }
                }
            } else {
                epilogue_tile(acc, M0, col0, m_base, n_base, g, c,
                              bias, C, Chi, Clo, ldc, res, epi);
            }
        }
    }
}

// ---------------- ff2 GEMM: single-bf16 A (K=512), split W, 2-term ------------
__global__ void __launch_bounds__(256, 2)
gemm_ff2_kernel(const __nv_bfloat16* __restrict__ A, int K,
                const __nv_bfloat16* __restrict__ Whi,
                const __nv_bfloat16* __restrict__ Wlo,
                const float* __restrict__ bias,
                __nv_bfloat16* __restrict__ Chi, __nv_bfloat16* __restrict__ Clo,
                const float* __restrict__ res) {
    extern __shared__ __nv_bfloat16 sm[];
    uint32_t u0 = smem_u32(sm);

    int t    = threadIdx.x;
    int wid  = t >> 5, lane = t & 31;
    int g    = lane >> 2;
    int c    = lane & 3;
    int M0   = blockIdx.x * 128;
    int wm   = wid >> 1, wn = wid & 1;
    int m_base = wm * 32, n_base = wn * 64;

    int la = lane & 15;
    int ka = (lane >> 4) * 8;
    int lb = (lane & 7) + ((lane >> 4) * 8);
    int kb = ((lane >> 3) & 1) * 8;

    float acc[2][8][4];
    #pragma unroll
    for (int mt = 0; mt < 2; mt++)
        #pragma unroll
        for (int nt = 0; nt < 8; nt++)
            #pragma unroll
            for (int q = 0; q < 4; q++) acc[mt][nt][q] = 0.f;

    int nch = K / KCH;
    auto copy_chunk = [&](int kc, int stg) {
        uint32_t sbase = u0 + stg * FF2_STAGE_B;
        #pragma unroll
        for (int it = 0; it < 6; it++) {
            int idx  = it * 256 + t;
            int arr  = idx >> 9;
            int row  = (idx >> 2) & 127;
            int seg8 = (idx & 3) * 8;
            const __nv_bfloat16* src;
            if      (arr == 0) src = A   + (size_t)(M0 + row) * K + kc + seg8;
            else if (arr == 1) src = Whi + (size_t)row * K + kc + seg8;
            else               src = Wlo + (size_t)row * K + kc + seg8;
            cp16(sbase + ((arr * 128 + row) * SLD + seg8) * 2, src);
        }
        CP_COMMIT();
    };

    copy_chunk(0, 0);
    for (int ch = 0; ch < nch; ch++) {
        int cur = ch & 1;
        if (ch + 1 < nch) { copy_chunk((ch + 1) * KCH, cur ^ 1); CP_WAIT(1); }
        else              { CP_WAIT(0); }
        __syncthreads();

        uint32_t base = u0 + cur * FF2_STAGE_B;
        #pragma unroll
        for (int kk = 0; kk < KCH; kk += 16) {
            uint32_t ah0[4], ah1[4];
            uint32_t aoff0 = ((m_base + la) * SLD + ka + kk) * 2;
            uint32_t aoff1 = ((m_base + 16 + la) * SLD + ka + kk) * 2;
            ldsm4(ah0, base + aoff0);
            ldsm4(ah1, base + aoff1);
            #pragma unroll
            for (int np = 0; np < 4; np++) {
                uint32_t bh[4], bl[4];
                uint32_t boff = ((n_base + np * 16 + lb) * SLD + kb + kk) * 2;
                ldsm4(bh, base + 1 * 128 * SLD * 2 + boff);
                ldsm4(bl, base + 2 * 128 * SLD * 2 + boff);
                int n0 = 2 * np, n1 = 2 * np + 1;
                mma16816(acc[0][n0], ah0, bh);
                mma16816(acc[0][n0], ah0, bl);
                mma16816(acc[0][n1], ah0, bh + 2);
                mma16816(acc[0][n1], ah0, bl + 2);
                mma16816(acc[1][n0], ah1, bh);
                mma16816(acc[1][n0], ah1, bl);
                mma16816(acc[1][n1], ah1, bh + 2);
                mma16816(acc[1][n1], ah1, bl + 2);
            }
        }
        __syncthreads();
    }
    epilogue_tile(acc, M0, 0, m_base, n_base, g, c,
                  bias, nullptr, Chi, Clo, 128, res, 4);
}

// ---------------- LayerNorm: fp32 in -> single bf16 out (LN1) ----------------
__global__ void __launch_bounds__(256)
ln_kernel(const float* __restrict__ in,
          __nv_bfloat16* __restrict__ ohi,
          const float* __restrict__ g, const float* __restrict__ b) {
    int warp = threadIdx.x >> 5, lane = threadIdx.x & 31;
    size_t row = (size_t)blockIdx.x * 8 + warp;
    float4 v = *(const float4*)(in + row * 128 + lane * 4);
    float s  = v.x + v.y + v.z + v.w;
    float ss = v.x * v.x + v.y * v.y + v.z * v.z + v.w * v.w;
    #pragma unroll
    for (int o = 16; o; o >>= 1) {
        s  += __shfl_xor_sync(0xffffffffu, s, o);
        ss += __shfl_xor_sync(0xffffffffu, ss, o);
    }
    float m   = s * (1.0f / 128.0f);
    float var = ss * (1.0f / 128.0f) - m * m;
    float rs  = rsqrtf(var + 1e-5f);
    float4 gg = *(const float4*)(g + lane * 4);
    float4 bb = *(const float4*)(b + lane * 4);
    __nv_bfloat162 h01, h23;
    h01.x = __float2bfloat16((v.x - m) * rs * gg.x + bb.x);
    h01.y = __float2bfloat16((v.y - m) * rs * gg.y + bb.y);
    h23.x = __float2bfloat16((v.z - m) * rs * gg.z + bb.z);
    h23.y = __float2bfloat16((v.w - m) * rs * gg.w + bb.w);
    *(__nv_bfloat162*)(ohi + row * 128 + lane * 4)     = h01;
    *(__nv_bfloat162*)(ohi + row * 128 + lane * 4 + 2) = h23;
}

// ---------------- attention (fp32 in, single bf16 out) -----------------------
__global__ void __launch_bounds__(256)
attn_kernel() {
    extern __shared__ float s[];
    float* sq  = s;
    float* sk  = s + 32 * ATS;
    float* sv  = s + 64 * ATS;
    float* ssc = s + 96 * ATS;
    int node = blockIdx.x, t = threadIdx.x;
    const float* qg = g_qkv + (size_t)node * 32 * 384;

    for (int i = t; i < 1024; i += 256) {
        int l = i >> 5, c4 = (i & 31) * 4;
        *(float4*)(sq + l * ATS + c4) = *(const float4*)(qg + l * 384 + c4);
        *(float4*)(sk + l * ATS + c4) = *(const float4*)(qg + l * 384 + 128 + c4);
        *(float4*)(sv + l * ATS + c4) = *(const float4*)(qg + l * 384 + 256 + c4);
    }
    __syncthreads();

    {   // scores
        int i = t >> 3, j0 = (t & 7) * 4;
        float acc[4] = {0.f, 0.f, 0.f, 0.f};
        #pragma unroll 4
        for (int d = 0; d < 128; d += 4) {
            float4 q = *(const float4*)(sq + i * ATS + d);
            #pragma unroll
            for (int jj = 0; jj < 4; jj++) {
                float4 k4 = *(const float4*)(sk + (j0 + jj) * ATS + d);
                acc[jj] += q.x * k4.x + q.y * k4.y + q.z * k4.z + q.w * k4.w;
            }
        }
        const float scale = 0.08838834764831845f;
        #pragma unroll
        for (int jj = 0; jj < 4; jj++) ssc[i * 32 + j0 + jj] = acc[jj] * scale;
    }
    __syncthreads();
    {   // softmax
        int warp = t >> 5, lane = t & 31;
        for (int r = warp; r < 32; r += 8) {
            float v = ssc[r * 32 + lane];
            float mx = v;
            #pragma unroll
            for (int o = 16; o; o >>= 1) mx = fmaxf(mx, __shfl_xor_sync(0xffffffffu, mx, o));
            float e = expf(v - mx);
            float sm2 = e;
            #pragma unroll
            for (int o = 16; o; o >>= 1) sm2 += __shfl_xor_sync(0xffffffffu, sm2, o);
            ssc[r * 32 + lane] = e / sm2;
        }
    }
    __syncthreads();
    {   // attn = a @ v -> single bf16
        int i = t >> 3, d0 = (t & 7) * 4;
        float acc[4][4];
        #pragma unroll
        for (int q = 0; q < 4; q++)
            #pragma unroll
            for (int e = 0; e < 4; e++) acc[q][e] = 0.f;
        for (int j = 0; j < 32; j++) {
            float a = ssc[i * 32 + j];
            const float* vr = sv + j * ATS + d0;
            #pragma unroll
            for (int q = 0; q < 4; q++) {
                float4 v4 = *(const float4*)(vr + q * 32);
                acc[q][0] += a * v4.x; acc[q][1] += a * v4.y;
                acc[q][2] += a * v4.z; acc[q][3] += a * v4.w;
            }
        }
        size_t base = ((size_t)node * 32 + i) * 128 + d0;
        #pragma unroll
        for (int q = 0; q < 4; q++) {
            __nv_bfloat162 h0, h1;
            h0.x = __float2bfloat16(acc[q][0]); h0.y = __float2bfloat16(acc[q][1]);
            h1.x = __float2bfloat16(acc[q][2]); h1.y = __float2bfloat16(acc[q][3]);
            *(__nv_bfloat162*)(g_b1hi + base + q * 32)     = h0;
            *(__nv_bfloat162*)(g_b1hi + base + q * 32 + 2) = h1;
        }
    }
}

// ---------------- edge dtype detection + CSR build ---------------------------
__global__ void zero_counts_kernel() {
    int i = blockIdx.x * blockDim.x + threadIdx.x;
    if (i < K_NODES) { g_cnt[i] = 0; g_cur[i] = 0; }
    if (i == 0) g_is32 = 0;
}
__global__ void detect_dtype_kernel(const int* __restrict__ ei32) {
    int i = blockIdx.x * blockDim.x + threadIdx.x;
    if (i < N_EDGES && ei32[2 * i + 1] != 0) atomicExch(&g_is32, 1);
}
__device__ __forceinline__ int load_idx(const int* __restrict__ ei32, int elem) {
    return g_is32 ? ei32[elem] : ei32[2 * elem];
}
__global__ void count_edges_kernel(const int* __restrict__ ei32) {
    int e = blockIdx.x * blockDim.x + threadIdx.x;
    if (e >= N_TOT_EDGES) return;
    int dst = (e < N_EDGES) ? load_idx(ei32, N_EDGES + e) : (e - N_EDGES);
    if ((unsigned)dst >= K_NODES) return;
    atomicAdd(&g_cnt[dst], 1);
}
__global__ void scan_kernel() {
    __shared__ int ts[1024];
    int t = threadIdx.x;
    int c[4], s = 0;
    #pragma unroll
    for (int i = 0; i < 4; i++) { c[i] = s; s += g_cnt[t * 4 + i]; }
    ts[t] = s;
    __syncthreads();
    for (int o = 1; o < 1024; o <<= 1) {
        int v = (t >= o) ? ts[t - o] : 0;
        __syncthreads();
        ts[t] += v;
        __syncthreads();
    }
    int base = (t == 0) ? 0 : ts[t - 1];
    #pragma unroll
    for (int i = 0; i < 4; i++) g_off[t * 4 + i] = base + c[i];
    if (t == 1023) g_off[4096] = ts[1023];
}
__global__ void fill_edges_kernel(const int* __restrict__ ei32) {
    int e = blockIdx.x * blockDim.x + threadIdx.x;
    if (e >= N_TOT_EDGES) return;
    int src, dst;
    if (e < N_EDGES) {
        src = load_idx(ei32, e);
        dst = load_idx(ei32, N_EDGES + e);
    } else {
        src = dst = e - N_EDGES;
    }
    if ((unsigned)dst >= K_NODES || (unsigned)src >= K_NODES) return;
    int pos = atomicAdd(&g_cur[dst], 1);
    g_csr_src[g_off[dst] + pos] = src;
}

// ---------------- GAT aggregation: one block per dst node --------------------
__global__ void __launch_bounds__(256)
gat_aggregate_kernel(const float* __restrict__ gat_b, float* __restrict__ out) {
    __shared__ float sm_m[32], sm_d[32];
    __shared__ float part[8][32];
    __shared__ float s_alpha[64][33];
    __shared__ int   s_src[64];
    int dst = blockIdx.x, t = threadIdx.x;
    int off0 = g_off[dst], ne = g_cur[dst];

    {   // phase A: per-l max
        int l = t & 31, grp = t >> 5;
        float adl = g_ad[dst * 32 + l];
        float lm = -3.4e38f;
        for (int e = grp; e < ne; e += 8) {
            int src = g_csr_src[off0 + e];
            float v = g_as[src * 32 + l] + adl;
            v = v > 0.f ? v : 0.2f * v;
            lm = fmaxf(lm, v);
        }
        part[grp][l] = lm;
        __syncthreads();
        if (t < 32) {
            float m = part[0][t];
            #pragma unroll
            for (int g2 = 1; g2 < 8; g2++) m = fmaxf(m, part[g2][t]);
            sm_m[t] = m;
        }
        __syncthreads();
    }
    {   // phase B: denom
        int l = t & 31, grp = t >> 5;
        float adl = g_ad[dst * 32 + l];
        float m = sm_m[l], sden = 0.f;
        for (int e = grp; e < ne; e += 8) {
            int src = g_csr_src[off0 + e];
            float v = g_as[src * 32 + l] + adl;
            v = v > 0.f ? v : 0.2f * v;
            sden += expf(v - m);
        }
        __syncthreads();
        part[grp][l] = sden;
        __syncthreads();
        if (t < 32) {
            float s2 = 0.f;
            #pragma unroll
            for (int g2 = 0; g2 < 8; g2++) s2 += part[g2][t];
            sm_d[t] = s2;
        }
        __syncthreads();
    }
    {   // phase C: chunked alpha staging + weighted aggregation
        int l = t >> 3, d0 = (t & 7) * 16;
        float acc[16];
        #pragma unroll
        for (int i = 0; i < 16; i++) acc[i] = 0.f;

        for (int e0 = 0; e0 < ne; e0 += 64) {
            int ecnt = min(64, ne - e0);
            __syncthreads();
            if (t < ecnt) s_src[t] = g_csr_src[off0 + e0 + t];
            __syncthreads();
            for (int idx = t; idx < ecnt * 32; idx += 256) {
                int e = idx >> 5, ll = idx & 31;
                float v = g_as[s_src[e] * 32 + ll] + g_ad[dst * 32 + ll];
                v = v > 0.f ? v : 0.2f * v;
                s_alpha[e][ll] = expf(v - sm_m[ll]);
            }
            __syncthreads();
            for (int e = 0; e < ecnt; e++) {
                float ex = s_alpha[e][l];
                const float4* hp =
                    (const float4*)(g_h + ((size_t)s_src[e] * 32 + l) * 128 + d0);
                #pragma unroll
                for (int q = 0; q < 4; q++) {
                    float4 h4 = hp[q];
                    acc[q * 4 + 0] += ex * h4.x;
                    acc[q * 4 + 1] += ex * h4.y;
                    acc[q * 4 + 2] += ex * h4.z;
                    acc[q * 4 + 3] += ex * h4.w;
                }
            }
        }

        float inv = 1.f / (sm_d[l] + 1e-16f);
        float* op = out + ((size_t)dst * 32 + l) * 128 + d0;
        #pragma unroll
        for (int q = 0; q < 4; q++) {
            float4 o4;
            o4.x = acc[q * 4 + 0] * inv + gat_b[d0 + q * 4 + 0];
            o4.y = acc[q * 4 + 1] * inv + gat_b[d0 + q * 4 + 1];
            o4.z = acc[q * 4 + 2] * inv + gat_b[d0 + q * 4 + 2];
            o4.w = acc[q * 4 + 3] * inv + gat_b[d0 + q * 4 + 3];
            ((float4*)op)[q] = o4;
        }
    }
}

// ---------------- launch ------------------------------------------------------
extern "C" void kernel_launch(void* const* d_in, const int* in_sizes, int n_in,
                              void* d_out, int out_size) {
    const float* x     = (const float*)d_in[0];
    const int*   ei32  = (const int*)d_in[1];
    const float* ln1_g = (const float*)d_in[2];
    const float* ln1_b = (const float*)d_in[3];
    const float* qkv_w = (const float*)d_in[4];
    const float* qkv_b = (const float*)d_in[5];
    const float* out_w = (const float*)d_in[6];
    const float* out_b = (const float*)d_in[7];
    const float* ln2_g = (const float*)d_in[8];
    const float* ln2_b = (const float*)d_in[9];
    const float* ff1_w = (const float*)d_in[10];
    const float* ff1_b = (const float*)d_in[11];
    const float* ff2_w = (const float*)d_in[12];
    const float* ff2_b = (const float*)d_in[13];
    const float* gat_w = (const float*)d_in[14];
    const float* att_s = (const float*)d_in[15];
    const float* att_d = (const float*)d_in[16];
    const float* gat_b = (const float*)d_in[17];
    float* out = (float*)d_out;

    float *p_qkv, *p_x2, *p_h, *p_as, *p_ad;
    __nv_bfloat16 *p_b1hi, *p_b1lo, *p_b2hi, *p_whi, *p_wlo;
    cudaGetSymbolAddress((void**)&p_qkv,  g_qkv);
    cudaGetSymbolAddress((void**)&p_x2,   g_x2);
    cudaGetSymbolAddress((void**)&p_h,    g_h);
    cudaGetSymbolAddress((void**)&p_as,   g_as);
    cudaGetSymbolAddress((void**)&p_ad,   g_ad);
    cudaGetSymbolAddress((void**)&p_b1hi, g_b1hi);
    cudaGetSymbolAddress((void**)&p_b1lo, g_b1lo);
    cudaGetSymbolAddress((void**)&p_b2hi, g_b2hi);
    cudaGetSymbolAddress((void**)&p_whi,  g_whi);
    cudaGetSymbolAddress((void**)&p_wlo,  g_wlo);

    const int FF2_SMEM = 2 * FF2_STAGE_B;
    const int ATTN_SMEM = (96 * ATS + 1024) * 4;
    cudaFuncSetAttribute(gemm_ff2_kernel,
                         cudaFuncAttributeMaxDynamicSharedMemorySize, FF2_SMEM);
    cudaFuncSetAttribute(gemm_ares_kernel<0>,
                         cudaFuncAttributeMaxDynamicSharedMemorySize, ARES_SMEM_1);
    cudaFuncSetAttribute(gemm_ares_kernel<1>,
                         cudaFuncAttributeMaxDynamicSharedMemorySize, ARES_SMEM_2);
    cudaFuncSetAttribute(attn_kernel,
                         cudaFuncAttributeMaxDynamicSharedMemorySize, ATTN_SMEM);

    // 1. weight splits
    split_w_kernel<<<(W_TOTAL + 255) / 256, 256>>>(qkv_w, out_w, ff1_w, ff2_w, gat_w);
    // 2. LN1 -> b1 single bf16
    ln_kernel<<<MM / 8, 256>>>(x, p_b1hi, ln1_g, ln1_b);
    // 3. CSR zero
    zero_counts_kernel<<<(K_NODES + 255) / 256, 256>>>();
    // 4. qkv GEMM (single-A 2-term, NT=3)  (ncu slot)
    gemm_ares_kernel<0><<<MM / 128, 256, ARES_SMEM_1>>>(
        p_b1hi, nullptr, p_whi + WOFF_QKV, p_wlo + WOFF_QKV, 128,
        qkv_b, p_qkv, nullptr, nullptr, 384, nullptr, 0, 3,
        nullptr, nullptr, nullptr, nullptr, nullptr, nullptr);
    // 5-6. CSR detect/count
    detect_dtype_kernel<<<(N_EDGES + 255) / 256, 256>>>(ei32);
    count_edges_kernel<<<(N_TOT_EDGES + 255) / 256, 256>>>(ei32);
    // 7. attention -> b1 single bf16
    attn_kernel<<<K_NODES, 256, ATTN_SMEM>>>();
    // 8. out-proj + residual -> x2 fp32 AND fused LN2 -> b1 single (epi 5)
    gemm_ares_kernel<0><<<MM / 128, 256, ARES_SMEM_1>>>(
        p_b1hi, nullptr, p_whi + WOFF_OUT, p_wlo + WOFF_OUT, 128,
        out_b, p_x2, p_b1hi, nullptr, 128, x, 5, 1,
        ln2_g, ln2_b, nullptr, nullptr, nullptr, nullptr);
    // 9. CSR scan
    scan_kernel<<<1, 1024>>>();
    // 10. ff1 + gelu -> b2 single bf16 (NT=4)
    gemm_ares_kernel<0><<<MM / 128, 256, ARES_SMEM_1>>>(
        p_b1hi, nullptr, p_whi + WOFF_FF1, p_wlo + WOFF_FF1, 128,
        ff1_b, nullptr, p_b2hi, nullptr, 512, nullptr, 1, 4,
        nullptr, nullptr, nullptr, nullptr, nullptr, nullptr);
    // 11. ff2 + residual -> xt (b1 SPLIT: GAT input needs full precision)
    gemm_ff2_kernel<<<MM / 128, 256, FF2_SMEM>>>(
        p_b2hi, 512, p_whi + WOFF_FF2, p_wlo + WOFF_FF2,
        ff2_b, p_b1hi, p_b1lo, p_x2);
    // 12. GAT transform (split-A 3-term) -> h fp32 AND fused a_src/a_dst (epi 6)
    gemm_ares_kernel<1><<<MM / 128, 256, ARES_SMEM_2>>>(
        p_b1hi, p_b1lo, p_whi + WOFF_GAT, p_wlo + WOFF_GAT, 128,
        nullptr, p_h, nullptr, nullptr, 128, nullptr, 6, 1,
        nullptr, nullptr, att_s, att_d, p_as, p_ad);
    // 13. CSR fill
    fill_edges_kernel<<<(N_TOT_EDGES + 255) / 256, 256>>>(ei32);
    // 14. aggregate
    gat_aggregate_kernel<<<K_NODES, 256>>>(gat_b, out);
}